// round 3
// baseline (speedup 1.0000x reference)
#include <cuda_runtime.h>
#include <math.h>

// ---------------------------------------------------------------------------
// Problem constants
// ---------------------------------------------------------------------------
#define BB   8
#define HH   64
#define WW_  64
#define LL   4096          // H*W
#define CC   128
#define NHEAD 4
#define HD   32
#define WIN  8
#define NTOK 64            // WIN*WIN
#define NWIN 64            // (H/WIN)*(W/WIN)
#define MROWS (BB*LL)      // 32768
#define SCALE_Q 0.17677669529663687f   // HD^-0.5

// ---------------------------------------------------------------------------
// Scratch (device globals — no allocation allowed)
// ---------------------------------------------------------------------------
__device__ float g_buf  [MROWS * CC];       // running state x / g
__device__ float g_xw   [MROWS * CC];       // LN output (window layout or token layout)
__device__ float g_qkv  [MROWS * 3 * CC];   // qkv rows (window layout)
__device__ float g_attn [MROWS * CC];       // attention out (window layout)
__device__ float g_h1   [MROWS * 4 * CC];   // FFN hidden
__device__ float g_off  [BB * 3 * LL];
__device__ float g_msk  [BB * 3 * LL];
__device__ float g_local[MROWS * CC];       // deform output, (B,C,L) memory == (B,L,C) view
__device__ float g_t1   [MROWS * CC];
__device__ float g_t2   [MROWS * CC];

// ---------------------------------------------------------------------------
// Generic fp32 GEMM: C = epilogue(A(MxK) @ W(KxN)), 128x128 tile, 8x8/thread
// ---------------------------------------------------------------------------
struct ALDirect {
    const float* A; int K;
    __device__ __forceinline__ float4 load4(int m, int k) const {
        return *(const float4*)(A + (size_t)m * K + k);
    }
};
struct ALConcat {   // A = concat([xt, hx], -1), K = 256
    const float* x; const float* h;
    __device__ __forceinline__ float4 load4(int m, int k) const {
        const float* p = (k < CC) ? (x + (size_t)m * CC + k)
                                  : (h + (size_t)m * CC + (k - CC));
        return *(const float4*)p;
    }
};

struct EpiBias {
    float* out; const float* bias;
    __device__ __forceinline__ void operator()(int m, int n, int N, float acc) const {
        out[(size_t)m * N + n] = acc + bias[n];
    }
};
struct EpiGelu {
    float* out; const float* bias;
    __device__ __forceinline__ void operator()(int m, int n, int N, float acc) const {
        float v = acc + bias[n];
        out[(size_t)m * N + n] = 0.5f * v * (1.0f + erff(v * 0.7071067811865476f));
    }
};
struct EpiResid {   // out[m,n] = res[m,n] + acc + bias[n]   (in-place safe: A != out)
    float* out; const float* res; const float* bias;
    __device__ __forceinline__ void operator()(int m, int n, int N, float acc) const {
        size_t i = (size_t)m * N + n;
        out[i] = res[i] + acc + bias[n];
    }
};
// proj epilogue: window-reverse + unroll(+shift) + residual into g (in place)
struct EpiProj {
    float* out; const float* bias; int shift;
    __device__ __forceinline__ void operator()(int m, int n, int N, float acc) const {
        int b    = m >> 12;        // /4096 (rows per batch = 64 win * 64 tok)
        int rb   = m & 4095;
        int widx = rb >> 6;
        int tok  = rb & 63;
        int hh = ((widx >> 3) << 3) + (tok >> 3);   // rolled image coords
        int ww = ((widx & 7) << 3) + (tok & 7);
        int h = (hh + shift) & 63;
        int w = (ww + shift) & 63;
        size_t dst = ((size_t)(b << 12) + (h << 6) + w) * CC + n;
        out[dst] = out[dst] + acc + bias[n];
    }
};
struct EpiMulRelu {  // out = relu(t1 * (acc+bias))
    float* out; const float* t1; const float* bias;
    __device__ __forceinline__ void operator()(int m, int n, int N, float acc) const {
        size_t i = (size_t)m * N + n;
        out[i] = fmaxf(0.0f, t1[i] * (acc + bias[n]));
    }
};
struct EpiLSTM {
    float* hy; const float* cx; const float* bias;
    __device__ __forceinline__ void operator()(int m, int n, int N, float acc) const {
        size_t i = (size_t)m * N + n;
        float f    = acc + bias[n];
        float gate = 1.0f / (1.0f + expf(-f));
        float cell = tanhf(f);
        float cy   = gate * (cx[i] + cell);
        hy[i] = gate * tanhf(cy);
    }
};

template <class AL, class EP>
__global__ __launch_bounds__(256, 2)
void gemm128(AL al, const float* __restrict__ W, int K, int N, EP ep) {
    __shared__ float As[16][128];
    __shared__ float Ws[16][128];
    const int tid = threadIdx.x;
    const int tx = tid & 15, ty = tid >> 4;
    const int bm = blockIdx.y * 128, bn = blockIdx.x * 128;

    float acc[8][8];
#pragma unroll
    for (int i = 0; i < 8; i++)
#pragma unroll
        for (int j = 0; j < 8; j++) acc[i][j] = 0.0f;

    for (int kt = 0; kt < K; kt += 16) {
#pragma unroll
        for (int r = 0; r < 2; r++) {
            int e  = tid + 256 * r;
            int m  = e >> 2, ak = (e & 3) << 2;
            float4 av = al.load4(bm + m, kt + ak);
            As[ak + 0][m] = av.x; As[ak + 1][m] = av.y;
            As[ak + 2][m] = av.z; As[ak + 3][m] = av.w;
            int wk = e >> 5, wn = (e & 31) << 2;
            *(float4*)&Ws[wk][wn] =
                *(const float4*)&W[(size_t)(kt + wk) * N + bn + wn];
        }
        __syncthreads();
#pragma unroll
        for (int k = 0; k < 16; k++) {
            float a[8], w[8];
            *(float4*)&a[0] = *(const float4*)&As[k][ty * 8];
            *(float4*)&a[4] = *(const float4*)&As[k][ty * 8 + 4];
            *(float4*)&w[0] = *(const float4*)&Ws[k][tx * 8];
            *(float4*)&w[4] = *(const float4*)&Ws[k][tx * 8 + 4];
#pragma unroll
            for (int i = 0; i < 8; i++)
#pragma unroll
                for (int j = 0; j < 8; j++) acc[i][j] += a[i] * w[j];
        }
        __syncthreads();
    }
#pragma unroll
    for (int i = 0; i < 8; i++) {
        int m = bm + ty * 8 + i;
#pragma unroll
        for (int j = 0; j < 8; j++) ep(m, bn + tx * 8 + j, N, acc[i][j]);
    }
}

// ---------------------------------------------------------------------------
// LayerNorm + (roll by -shift) + window partition : g -> xw (window layout)
// one warp per output token
// ---------------------------------------------------------------------------
__global__ void ln_part_kernel(const float* __restrict__ x,
                               const float* __restrict__ gm,
                               const float* __restrict__ bt,
                               float* __restrict__ out, int shift) {
    int warp = blockIdx.x * 8 + (threadIdx.x >> 5);
    int lane = threadIdx.x & 31;
    int wi = warp >> 6, tok = warp & 63;
    int b = wi >> 6, widx = wi & 63;
    int hh = ((widx >> 3) << 3) + (tok >> 3);
    int ww = ((widx & 7) << 3) + (tok & 7);
    int h = (hh + shift) & 63;
    int w = (ww + shift) & 63;
    const float* row = x + ((size_t)(b << 12) + (h << 6) + w) * CC;

    float v[4], sum = 0.0f, sq = 0.0f;
#pragma unroll
    for (int i = 0; i < 4; i++) {
        v[i] = row[lane + 32 * i];
        sum += v[i]; sq += v[i] * v[i];
    }
#pragma unroll
    for (int o = 16; o; o >>= 1) {
        sum += __shfl_xor_sync(0xffffffffu, sum, o);
        sq  += __shfl_xor_sync(0xffffffffu, sq, o);
    }
    float mean = sum * (1.0f / 128.0f);
    float var  = sq * (1.0f / 128.0f) - mean * mean;
    float rstd = rsqrtf(var + 1e-5f);
    float* orow = out + (size_t)warp * CC;
#pragma unroll
    for (int i = 0; i < 4; i++) {
        int c = lane + 32 * i;
        orow[c] = (v[i] - mean) * rstd * gm[c] + bt[c];
    }
}

// plain LayerNorm (token layout in == out layout)
__global__ void ln_plain_kernel(const float* __restrict__ x,
                                const float* __restrict__ gm,
                                const float* __restrict__ bt,
                                float* __restrict__ out) {
    int warp = blockIdx.x * 8 + (threadIdx.x >> 5);
    int lane = threadIdx.x & 31;
    const float* row = x + (size_t)warp * CC;
    float v[4], sum = 0.0f, sq = 0.0f;
#pragma unroll
    for (int i = 0; i < 4; i++) {
        v[i] = row[lane + 32 * i];
        sum += v[i]; sq += v[i] * v[i];
    }
#pragma unroll
    for (int o = 16; o; o >>= 1) {
        sum += __shfl_xor_sync(0xffffffffu, sum, o);
        sq  += __shfl_xor_sync(0xffffffffu, sq, o);
    }
    float mean = sum * (1.0f / 128.0f);
    float var  = sq * (1.0f / 128.0f) - mean * mean;
    float rstd = rsqrtf(var + 1e-5f);
    float* orow = out + (size_t)warp * CC;
#pragma unroll
    for (int i = 0; i < 4; i++) {
        int c = lane + 32 * i;
        orow[c] = (v[i] - mean) * rstd * gm[c] + bt[c];
    }
}

// ---------------------------------------------------------------------------
// Window attention: one block per (head, window). 64 threads = 64 query rows.
// bias/mask computed inline from index arithmetic.
// ---------------------------------------------------------------------------
__device__ __forceinline__ int zone_(int h) { return h < 56 ? 0 : (h < 60 ? 1 : 2); }

__global__ __launch_bounds__(64)
void attn_kernel(const float* __restrict__ qkv, const float* __restrict__ rp,
                 float* __restrict__ out, int shift) {
    const int head = blockIdx.x;     // 0..3
    const int wi   = blockIdx.y;     // 0..511
    const int t    = threadIdx.x;    // query row 0..63

    __shared__ float kk[64][32];
    __shared__ float vv[64][32];
    __shared__ float rps[900];       // (225, NHEAD)

    const int base = wi * 64;
    for (int i = t; i < 900; i += 64) rps[i] = rp[i];
    for (int i = t; i < 2048; i += 64) {
        int m = i >> 5, d = i & 31;
        kk[m][d] = qkv[(size_t)(base + m) * 384 + 128 + head * 32 + d];
        vv[m][d] = qkv[(size_t)(base + m) * 384 + 256 + head * 32 + d];
    }
    __syncthreads();

    float q[32];
#pragma unroll
    for (int d = 0; d < 32; d++)
        q[d] = qkv[(size_t)(base + t) * 384 + head * 32 + d] * SCALE_Q;

    const int rn = t >> 3, cn = t & 7;
    const int widx = wi & 63;
    const int wh = widx >> 3, wwc = widx & 7;
    int zr_n = 0, zc_n = 0;
    if (shift) { zr_n = zone_(wh * 8 + rn); zc_n = zone_(wwc * 8 + cn); }

    float s[64];
    float mx = -1e30f;
#pragma unroll
    for (int m = 0; m < 64; m++) {
        float a = 0.0f;
#pragma unroll
        for (int d = 0; d < 32; d++) a += q[d] * kk[m][d];
        int rm = m >> 3, cm = m & 7;
        int ridx = (rn - rm + 7) * 15 + (cn - cm + 7);
        a += rps[ridx * 4 + head];
        if (shift) {
            if (zone_(wh * 8 + rm) != zr_n || zone_(wwc * 8 + cm) != zc_n)
                a += -100.0f;
        }
        s[m] = a;
        mx = fmaxf(mx, a);
    }
    float sum = 0.0f;
#pragma unroll
    for (int m = 0; m < 64; m++) { s[m] = expf(s[m] - mx); sum += s[m]; }
    float inv = 1.0f / sum;

    float o[32];
#pragma unroll
    for (int d = 0; d < 32; d++) o[d] = 0.0f;
#pragma unroll
    for (int m = 0; m < 64; m++) {
        float p = s[m] * inv;
#pragma unroll
        for (int d = 0; d < 32; d++) o[d] += p * vv[m][d];
    }
#pragma unroll
    for (int d = 0; d < 32; d++)
        out[(size_t)(base + t) * CC + head * 32 + d] = o[d];
}

// ---------------------------------------------------------------------------
// Conv1d offset + mask head (K=3, pad=1) over token axis, per warp = 1 position
// ---------------------------------------------------------------------------
__global__ void offmask_kernel(const float* __restrict__ xt,
                               const float* __restrict__ offw, const float* __restrict__ offb,
                               const float* __restrict__ mskw, const float* __restrict__ mskb,
                               float* __restrict__ off, float* __restrict__ msk) {
    __shared__ float swo[1152], swm[1152];   // (3,128,3)
    int tid = threadIdx.x;
    for (int i = tid; i < 1152; i += 256) { swo[i] = offw[i]; swm[i] = mskw[i]; }
    __syncthreads();

    int warp = tid >> 5, lane = tid & 31;
    int pos = blockIdx.x * 8 + warp;
    int b = pos >> 12, l = pos & 4095;

    float ao[3] = {0.f, 0.f, 0.f}, am[3] = {0.f, 0.f, 0.f};
#pragma unroll
    for (int i = 0; i < 4; i++) {
        int c = lane + 32 * i;
        float xv[3];
#pragma unroll
        for (int j = 0; j < 3; j++) {
            int ls = l + j - 1;
            xv[j] = (ls >= 0 && ls < LL)
                  ? xt[((size_t)(b << 12) + ls) * CC + c] : 0.0f;
        }
#pragma unroll
        for (int ko = 0; ko < 3; ko++)
#pragma unroll
            for (int j = 0; j < 3; j++) {
                ao[ko] += xv[j] * swo[ko * 384 + c * 3 + j];
                am[ko] += xv[j] * swm[ko * 384 + c * 3 + j];
            }
    }
#pragma unroll
    for (int o = 16; o; o >>= 1)
#pragma unroll
        for (int ko = 0; ko < 3; ko++) {
            ao[ko] += __shfl_xor_sync(0xffffffffu, ao[ko], o);
            am[ko] += __shfl_xor_sync(0xffffffffu, am[ko], o);
        }
    if (lane == 0) {
#pragma unroll
        for (int ko = 0; ko < 3; ko++) {
            float ov = ao[ko] + offb[ko];
            float mv = am[ko] + mskb[ko];
            off[((size_t)(b * 3 + ko)) * LL + l] = ov;
            msk[((size_t)(b * 3 + ko)) * LL + l] = 1.0f / (1.0f + expf(-mv));
        }
    }
}

// ---------------------------------------------------------------------------
// Deformable sample: out_raw (B,C,L). Block = one (b, 32-token tile).
// Coalesced reads over C; smem transpose for coalesced (C,L) writes.
// ---------------------------------------------------------------------------
__global__ void deform_kernel(const float* __restrict__ xt,
                              const float* __restrict__ off,
                              const float* __restrict__ msk,
                              float* __restrict__ outr) {
    __shared__ float s[128][33];
    __shared__ int   sfp[3][32], scp[3][32];
    __shared__ float sal[3][32], sm[3][32];

    int blk = blockIdx.x;
    int b = blk >> 7;                 // 128 tiles per batch
    int l0 = (blk & 127) << 5;
    int tid = threadIdx.x;

    if (tid < 96) {
        int k = tid / 32, li = tid % 32;
        int l = l0 + li;
        float o  = off[((size_t)(b * 3 + k)) * LL + l];
        float p  = fminf(fmaxf((float)l + o, 0.0f), 4095.0f);
        int fp   = (int)floorf(p);
        int cp   = min(fp + 1, 4095);
        sfp[k][li] = fp; scp[k][li] = cp;
        sal[k][li] = p - (float)fp;
        sm [k][li] = msk[((size_t)(b * 3 + k)) * LL + l];
    }
    __syncthreads();

    for (int e = tid; e < 4096; e += 256) {
        int li = e >> 7, c = e & 127;
        float acc = 0.0f;
#pragma unroll
        for (int k = 0; k < 3; k++) {
            float a  = sal[k][li];
            float xf = xt[((size_t)(b << 12) + sfp[k][li]) * CC + c];
            float xc = xt[((size_t)(b << 12) + scp[k][li]) * CC + c];
            acc += (xf * (1.0f - a) + xc * a) * sm[k][li];
        }
        s[c][li] = acc;
    }
    __syncthreads();
    for (int e = tid; e < 4096; e += 256) {
        int c = e >> 5, li = e & 31;
        outr[(size_t)b * (CC * LL) + (size_t)c * LL + l0 + li] = s[c][li];
    }
}

// ---------------------------------------------------------------------------
// Host launch
// ---------------------------------------------------------------------------
extern "C" void kernel_launch(void* const* d_in, const int* in_sizes, int n_in,
                              void* d_out, int out_size) {
    const float* xt    = (const float*)d_in[0];
    const float* hx    = (const float*)d_in[1];
    const float* cx    = (const float*)d_in[2];
    const float* red_w = (const float*)d_in[3];
    const float* red_b = (const float*)d_in[4];
    const float* n1g   = (const float*)d_in[5];
    const float* n1b   = (const float*)d_in[6];
    const float* qkvw  = (const float*)d_in[7];
    const float* qkvb  = (const float*)d_in[8];
    const float* rp    = (const float*)d_in[9];
    const float* pw    = (const float*)d_in[10];
    const float* pb    = (const float*)d_in[11];
    const float* n2g   = (const float*)d_in[12];
    const float* n2b   = (const float*)d_in[13];
    const float* f1w   = (const float*)d_in[14];
    const float* f1b   = (const float*)d_in[15];
    const float* f2w   = (const float*)d_in[16];
    const float* f2b   = (const float*)d_in[17];
    const float* off_w = (const float*)d_in[18];
    const float* off_b = (const float*)d_in[19];
    const float* msk_w = (const float*)d_in[20];
    const float* msk_b = (const float*)d_in[21];
    const float* lf_w  = (const float*)d_in[22];
    const float* lf_b  = (const float*)d_in[23];
    const float* gf_w  = (const float*)d_in[24];
    const float* gf_b  = (const float*)d_in[25];
    const float* ff_w  = (const float*)d_in[26];
    const float* ff_b  = (const float*)d_in[27];
    float* hy = (float*)d_out;

    float *pg, *pxw, *pqkv, *pattn, *ph1, *poff, *pmsk, *plocal, *pt1, *pt2;
    cudaGetSymbolAddress((void**)&pg,     g_buf);
    cudaGetSymbolAddress((void**)&pxw,    g_xw);
    cudaGetSymbolAddress((void**)&pqkv,   g_qkv);
    cudaGetSymbolAddress((void**)&pattn,  g_attn);
    cudaGetSymbolAddress((void**)&ph1,    g_h1);
    cudaGetSymbolAddress((void**)&poff,   g_off);
    cudaGetSymbolAddress((void**)&pmsk,   g_msk);
    cudaGetSymbolAddress((void**)&plocal, g_local);
    cudaGetSymbolAddress((void**)&pt1,    g_t1);
    cudaGetSymbolAddress((void**)&pt2,    g_t2);

    const dim3 blk256(256);
    const dim3 gN1(1, MROWS / 128), gN3(3, MROWS / 128), gN4(4, MROWS / 128);

    // 1) g = concat(xt, hx) @ red_w + red_b
    gemm128<<<gN1, blk256>>>(ALConcat{xt, hx}, red_w, 2 * CC, CC,
                             EpiBias{pg, red_b});

    // 2) two Swin blocks
    for (int i = 0; i < 2; i++) {
        int shift = (i == 0) ? 0 : 4;
        const float* qkvw_i = qkvw + (size_t)i * CC * 3 * CC;
        const float* qkvb_i = qkvb + (size_t)i * 3 * CC;
        const float* rp_i   = rp   + (size_t)i * 225 * NHEAD;
        const float* pw_i   = pw   + (size_t)i * CC * CC;
        const float* pb_i   = pb   + (size_t)i * CC;
        const float* f1w_i  = f1w  + (size_t)i * CC * 4 * CC;
        const float* f1b_i  = f1b  + (size_t)i * 4 * CC;
        const float* f2w_i  = f2w  + (size_t)i * 4 * CC * CC;
        const float* f2b_i  = f2b  + (size_t)i * CC;

        ln_part_kernel<<<MROWS / 8, blk256>>>(pg, n1g + i * CC, n1b + i * CC,
                                              pxw, shift);
        gemm128<<<gN3, blk256>>>(ALDirect{pxw, CC}, qkvw_i, CC, 3 * CC,
                                 EpiBias{pqkv, qkvb_i});
        attn_kernel<<<dim3(NHEAD, BB * NWIN), 64>>>(pqkv, rp_i, pattn, shift);
        gemm128<<<gN1, blk256>>>(ALDirect{pattn, CC}, pw_i, CC, CC,
                                 EpiProj{pg, pb_i, shift});
        ln_plain_kernel<<<MROWS / 8, blk256>>>(pg, n2g + i * CC, n2b + i * CC, pxw);
        gemm128<<<gN4, blk256>>>(ALDirect{pxw, CC}, f1w_i, CC, 4 * CC,
                                 EpiGelu{ph1, f1b_i});
        gemm128<<<gN1, blk256>>>(ALDirect{ph1, 4 * CC}, f2w_i, 4 * CC, CC,
                                 EpiResid{pg, pg, f2b_i});
    }

    // 3) local branch
    offmask_kernel<<<MROWS / 8, blk256>>>(xt, off_w, off_b, msk_w, msk_b,
                                          poff, pmsk);
    deform_kernel<<<BB * (LL / 32), blk256>>>(xt, poff, pmsk, plocal);

    // 4) fusion + LSTM gating
    gemm128<<<gN1, blk256>>>(ALDirect{plocal, CC}, lf_w, CC, CC,
                             EpiBias{pt1, lf_b});
    gemm128<<<gN1, blk256>>>(ALDirect{pg, CC}, gf_w, CC, CC,
                             EpiMulRelu{pt2, pt1, gf_b});
    gemm128<<<gN1, blk256>>>(ALDirect{pt2, CC}, ff_w, CC, CC,
                             EpiLSTM{hy, cx, ff_b});
}

// round 6
// speedup vs baseline: 1.3076x; 1.3076x over previous
#include <cuda_runtime.h>
#include <cuda_bf16.h>
#include <math.h>
#include <stdint.h>

// ---------------------------------------------------------------------------
// Problem constants
// ---------------------------------------------------------------------------
#define BB   8
#define LL   4096
#define CC   128
#define NHEAD 4
#define MROWS (BB*LL)      // 32768
#define SCALE_Q 0.17677669529663687f

// ---------------------------------------------------------------------------
// Scratch (device globals — no allocation allowed)
// ---------------------------------------------------------------------------
__device__ float g_buf  [MROWS * CC];
__device__ float g_qkv  [MROWS * 3 * CC];
__device__ float g_off  [BB * 3 * LL];
__device__ float g_msk  [BB * 3 * LL];
__device__ float g_t1   [MROWS * CC];

// bf16 hi/lo activation buffers
__device__ __align__(256) __nv_bfloat16 g_Ah[MROWS * 256], g_Al[MROWS * 256]; // bufA (<=K256)
__device__ __align__(256) __nv_bfloat16 g_Bh[MROWS * 512], g_Bl[MROWS * 512]; // bufB (<=K512)

// split + transposed weights, bf16 [N][K]
__device__ __align__(256) __nv_bfloat16 w_red_h[128*256],  w_red_l[128*256];
__device__ __align__(256) __nv_bfloat16 w_qkv_h[2][384*128], w_qkv_l[2][384*128];
__device__ __align__(256) __nv_bfloat16 w_pw_h [2][128*128], w_pw_l [2][128*128];
__device__ __align__(256) __nv_bfloat16 w_f1_h [2][512*128], w_f1_l [2][512*128];
__device__ __align__(256) __nv_bfloat16 w_f2_h [2][128*512], w_f2_l [2][128*512];
__device__ __align__(256) __nv_bfloat16 w_lf_h[128*128], w_lf_l[128*128];
__device__ __align__(256) __nv_bfloat16 w_gf_h[128*128], w_gf_l[128*128];
__device__ __align__(256) __nv_bfloat16 w_ff_h[128*128], w_ff_l[128*128];

// ---------------------------------------------------------------------------
// helpers
// ---------------------------------------------------------------------------
__device__ __forceinline__ uint32_t smem_u32(const void* p) {
    uint32_t a;
    asm("{ .reg .u64 t; cvta.to.shared.u64 t, %1; cvt.u32.u64 %0, t; }"
        : "=r"(a) : "l"(p));
    return a;
}
__device__ __forceinline__ void cp16(uint32_t s, const void* g) {
    asm volatile("cp.async.cg.shared.global [%0], [%1], 16;" :: "r"(s), "l"(g));
}
__device__ __forceinline__ void split1(float v, __nv_bfloat16& h, __nv_bfloat16& l) {
    h = __float2bfloat16(v);
    l = __float2bfloat16(v - __bfloat162float(h));
}

#define LDSM4(r, a) \
    asm volatile("ldmatrix.sync.aligned.m8n8.x4.shared.b16 {%0,%1,%2,%3}, [%4];" \
        : "=r"((r)[0]), "=r"((r)[1]), "=r"((r)[2]), "=r"((r)[3]) : "r"(a))

#define MMA16816(d, a, b0, b1) \
    asm volatile("mma.sync.aligned.m16n8k16.row.col.f32.bf16.bf16.f32 " \
        "{%0,%1,%2,%3}, {%4,%5,%6,%7}, {%8,%9}, {%0,%1,%2,%3};" \
        : "+f"((d)[0]), "+f"((d)[1]), "+f"((d)[2]), "+f"((d)[3]) \
        : "r"((a)[0]), "r"((a)[1]), "r"((a)[2]), "r"((a)[3]), "r"(b0), "r"(b1))

// ---------------------------------------------------------------------------
// Epilogues
// ---------------------------------------------------------------------------
struct EpiBias {
    float* out; const float* bias;
    __device__ __forceinline__ void operator()(int m, int n, int N, float acc) const {
        out[(size_t)m * N + n] = acc + bias[n];
    }
};
struct EpiGeluHL {
    __nv_bfloat16 *hi, *lo; const float* bias;
    __device__ __forceinline__ void operator()(int m, int n, int N, float acc) const {
        float v = acc + bias[n];
        float g = 0.5f * v * (1.0f + erff(v * 0.7071067811865476f));
        size_t i = (size_t)m * N + n;
        __nv_bfloat16 h, l; split1(g, h, l);
        hi[i] = h; lo[i] = l;
    }
};
struct EpiResid {
    float* out; const float* res; const float* bias;
    __device__ __forceinline__ void operator()(int m, int n, int N, float acc) const {
        size_t i = (size_t)m * N + n;
        out[i] = res[i] + acc + bias[n];
    }
};
struct EpiProj {   // window-reverse + unroll(+shift) + residual into out
    float* out; const float* bias; int shift;
    __device__ __forceinline__ void operator()(int m, int n, int N, float acc) const {
        int b    = m >> 12;
        int rb   = m & 4095;
        int widx = rb >> 6;
        int tok  = rb & 63;
        int hh = ((widx >> 3) << 3) + (tok >> 3);
        int ww = ((widx & 7) << 3) + (tok & 7);
        int h = (hh + shift) & 63;
        int w = (ww + shift) & 63;
        size_t dst = ((size_t)(b << 12) + (h << 6) + w) * CC + n;
        out[dst] = out[dst] + acc + bias[n];
    }
};
struct EpiMulReluHL {
    __nv_bfloat16 *hi, *lo; const float* t1; const float* bias;
    __device__ __forceinline__ void operator()(int m, int n, int N, float acc) const {
        size_t i = (size_t)m * N + n;
        float v = fmaxf(0.0f, t1[i] * (acc + bias[n]));
        __nv_bfloat16 h, l; split1(v, h, l);
        hi[i] = h; lo[i] = l;
    }
};
struct EpiLSTM {
    float* hy; const float* cx; const float* bias;
    __device__ __forceinline__ void operator()(int m, int n, int N, float acc) const {
        size_t i = (size_t)m * N + n;
        float f    = acc + bias[n];
        float gate = 1.0f / (1.0f + expf(-f));
        float cell = tanhf(f);
        float cy   = gate * (cx[i] + cell);
        hy[i] = gate * tanhf(cy);
    }
};

// ---------------------------------------------------------------------------
// bf16 hi/lo split GEMM on mma.sync (m16n8k16 bf16), 3 passes (hh, hl, lh).
// CTA tile 128x128, 8 warps (4x2), K-chunk 32, double-buffered cp.async smem.
// smem row stride 80B -> conflict-free ldmatrix. Stage = 4 tiles * 10240B.
// ---------------------------------------------------------------------------
#define TSTRIDE 80
#define TILE_B  10240
#define STAGE_B 40960
#define GEMM_SMEM (2 * STAGE_B)

template <class EP>
__global__ __launch_bounds__(256, 1)
void gemm_mma(const __nv_bfloat16* __restrict__ Ah, const __nv_bfloat16* __restrict__ Al,
              const __nv_bfloat16* __restrict__ Wh, const __nv_bfloat16* __restrict__ Wl,
              int K, int Nfull, EP ep) {
    extern __shared__ char sm[];
    const int tid  = threadIdx.x;
    const int wid  = tid >> 5;
    const int lane = tid & 31;
    const int bm = blockIdx.y * 128;
    const int bn = blockIdx.x * 128;
    const uint32_t sb = smem_u32(sm);
    const int nch = K >> 5;

    float acc[2][8][4];
#pragma unroll
    for (int a = 0; a < 2; a++)
#pragma unroll
        for (int b = 0; b < 8; b++)
#pragma unroll
            for (int c = 0; c < 4; c++) acc[a][b][c] = 0.0f;

    auto load_stage = [&](int i) {
        uint32_t st = sb + (uint32_t)(i & 1) * STAGE_B;
        int kt = i << 5;
#pragma unroll
        for (int t = 0; t < 2; t++) {
            int c = tid + t * 256;           // 0..511
            int r = c >> 2, q = c & 3;
            uint32_t so = (uint32_t)r * TSTRIDE + q * 16;
            size_t ga = (size_t)(bm + r) * K + kt + q * 8;
            size_t gb = (size_t)(bn + r) * K + kt + q * 8;
            cp16(st + so,                 Ah + ga);
            cp16(st + TILE_B + so,        Al + ga);
            cp16(st + 2 * TILE_B + so,    Wh + gb);
            cp16(st + 3 * TILE_B + so,    Wl + gb);
        }
        asm volatile("cp.async.commit_group;");
    };

    load_stage(0);
    for (int i = 0; i < nch; i++) {
        if (i + 1 < nch) {
            load_stage(i + 1);
            asm volatile("cp.async.wait_group 1;");
        } else {
            asm volatile("cp.async.wait_group 0;");
        }
        __syncthreads();

        uint32_t st = sb + (uint32_t)(i & 1) * STAGE_B;
#pragma unroll
        for (int j = 0; j < 2; j++) {
            uint32_t ah[2][4], al[2][4], bh[4][4], bl[4][4];
#pragma unroll
            for (int mt = 0; mt < 2; mt++) {
                uint32_t addr = st +
                    (uint32_t)(((wid & 3) << 5) + (mt << 4) + (lane & 15)) * TSTRIDE +
                    (j << 5) + ((lane >> 4) << 4);
                LDSM4(ah[mt], addr);
                LDSM4(al[mt], addr + TILE_B);
            }
#pragma unroll
            for (int nb = 0; nb < 4; nb++) {
                uint32_t addr = st + 2 * TILE_B +
                    (uint32_t)(((wid >> 2) << 6) + (nb << 4) + (lane & 7) + ((lane >> 4) << 3)) * TSTRIDE +
                    (j << 5) + (((lane >> 3) & 1) << 4);
                LDSM4(bh[nb], addr);
                LDSM4(bl[nb], addr + TILE_B);
            }
#pragma unroll
            for (int mt = 0; mt < 2; mt++)
#pragma unroll
                for (int nt = 0; nt < 8; nt++) {
                    float* d = acc[mt][nt];
                    uint32_t b0h = bh[nt >> 1][(nt & 1) * 2];
                    uint32_t b1h = bh[nt >> 1][(nt & 1) * 2 + 1];
                    uint32_t b0l = bl[nt >> 1][(nt & 1) * 2];
                    uint32_t b1l = bl[nt >> 1][(nt & 1) * 2 + 1];
                    MMA16816(d, ah[mt], b0h, b1h);
                    MMA16816(d, ah[mt], b0l, b1l);
                    MMA16816(d, al[mt], b0h, b1h);
                }
        }
        __syncthreads();
    }

    // epilogue
#pragma unroll
    for (int mt = 0; mt < 2; mt++)
#pragma unroll
        for (int nt = 0; nt < 8; nt++)
#pragma unroll
            for (int rg = 0; rg < 4; rg++) {
                int m = bm + ((wid & 3) << 5) + (mt << 4) + (lane >> 2) + ((rg >> 1) << 3);
                int n = bn + ((wid >> 2) << 6) + (nt << 3) + ((lane & 3) << 1) + (rg & 1);
                ep(m, n, Nfull, acc[mt][nt][rg]);
            }
}

// ---------------------------------------------------------------------------
// Weight transpose + bf16 hi/lo split:  W[K][N] fp32 -> hi/lo[N][K]
// ---------------------------------------------------------------------------
__global__ void wsplit_kernel(const float* __restrict__ W, int K, int N,
                              __nv_bfloat16* __restrict__ hi,
                              __nv_bfloat16* __restrict__ lo) {
    int i = blockIdx.x * 256 + threadIdx.x;
    if (i >= K * N) return;
    int k = i / N, n = i - k * N;
    __nv_bfloat16 h, l; split1(W[i], h, l);
    hi[(size_t)n * K + k] = h;
    lo[(size_t)n * K + k] = l;
}

// concat(xt,hx) -> bufA [M][256] hi/lo
__global__ void cvtcat_kernel(const float* __restrict__ x, const float* __restrict__ hsrc,
                              __nv_bfloat16* __restrict__ hi, __nv_bfloat16* __restrict__ lo) {
    int i = blockIdx.x * 256 + threadIdx.x;     // over MROWS*128
    int m = i >> 7, k = i & 127;
    __nv_bfloat16 h, l;
    split1(x[i], h, l);
    hi[(size_t)m * 256 + k] = h;       lo[(size_t)m * 256 + k] = l;
    split1(hsrc[i], h, l);
    hi[(size_t)m * 256 + 128 + k] = h; lo[(size_t)m * 256 + 128 + k] = l;
}

// fp32 -> hi/lo (same flat layout)
__global__ void cvt_kernel(const float* __restrict__ s,
                           __nv_bfloat16* __restrict__ hi, __nv_bfloat16* __restrict__ lo) {
    int i = blockIdx.x * 256 + threadIdx.x;
    __nv_bfloat16 h, l; split1(s[i], h, l);
    hi[i] = h; lo[i] = l;
}

// ---------------------------------------------------------------------------
// LayerNorm + (roll) + window partition -> bf16 hi/lo [M][128]
// ---------------------------------------------------------------------------
__global__ void ln_part_kernel(const float* __restrict__ x,
                               const float* __restrict__ gm,
                               const float* __restrict__ bt,
                               __nv_bfloat16* __restrict__ ohi,
                               __nv_bfloat16* __restrict__ olo, int shift) {
    int warp = blockIdx.x * 8 + (threadIdx.x >> 5);
    int lane = threadIdx.x & 31;
    int wi = warp >> 6, tok = warp & 63;
    int b = wi >> 6, widx = wi & 63;
    int hh = ((widx >> 3) << 3) + (tok >> 3);
    int ww = ((widx & 7) << 3) + (tok & 7);
    int h = (hh + shift) & 63;
    int w = (ww + shift) & 63;
    const float* row = x + ((size_t)(b << 12) + (h << 6) + w) * CC;

    float v[4], sum = 0.0f, sq = 0.0f;
#pragma unroll
    for (int i = 0; i < 4; i++) {
        v[i] = row[lane + 32 * i];
        sum += v[i]; sq += v[i] * v[i];
    }
#pragma unroll
    for (int o = 16; o; o >>= 1) {
        sum += __shfl_xor_sync(0xffffffffu, sum, o);
        sq  += __shfl_xor_sync(0xffffffffu, sq, o);
    }
    float mean = sum * (1.0f / 128.0f);
    float var  = sq * (1.0f / 128.0f) - mean * mean;
    float rstd = rsqrtf(var + 1e-5f);
#pragma unroll
    for (int i = 0; i < 4; i++) {
        int c = lane + 32 * i;
        float o = (v[i] - mean) * rstd * gm[c] + bt[c];
        __nv_bfloat16 hb, lb; split1(o, hb, lb);
        ohi[(size_t)warp * CC + c] = hb;
        olo[(size_t)warp * CC + c] = lb;
    }
}

__global__ void ln_plain_kernel(const float* __restrict__ x,
                                const float* __restrict__ gm,
                                const float* __restrict__ bt,
                                __nv_bfloat16* __restrict__ ohi,
                                __nv_bfloat16* __restrict__ olo) {
    int warp = blockIdx.x * 8 + (threadIdx.x >> 5);
    int lane = threadIdx.x & 31;
    const float* row = x + (size_t)warp * CC;
    float v[4], sum = 0.0f, sq = 0.0f;
#pragma unroll
    for (int i = 0; i < 4; i++) {
        v[i] = row[lane + 32 * i];
        sum += v[i]; sq += v[i] * v[i];
    }
#pragma unroll
    for (int o = 16; o; o >>= 1) {
        sum += __shfl_xor_sync(0xffffffffu, sum, o);
        sq  += __shfl_xor_sync(0xffffffffu, sq, o);
    }
    float mean = sum * (1.0f / 128.0f);
    float var  = sq * (1.0f / 128.0f) - mean * mean;
    float rstd = rsqrtf(var + 1e-5f);
#pragma unroll
    for (int i = 0; i < 4; i++) {
        int c = lane + 32 * i;
        float o = (v[i] - mean) * rstd * gm[c] + bt[c];
        __nv_bfloat16 hb, lb; split1(o, hb, lb);
        ohi[(size_t)warp * CC + c] = hb;
        olo[(size_t)warp * CC + c] = lb;
    }
}

// ---------------------------------------------------------------------------
// Window attention -> bf16 hi/lo output
// ---------------------------------------------------------------------------
__device__ __forceinline__ int zone_(int h) { return h < 56 ? 0 : (h < 60 ? 1 : 2); }

__global__ __launch_bounds__(64)
void attn_kernel(const float* __restrict__ qkv, const float* __restrict__ rp,
                 __nv_bfloat16* __restrict__ ohi, __nv_bfloat16* __restrict__ olo,
                 int shift) {
    const int head = blockIdx.x;
    const int wi   = blockIdx.y;
    const int t    = threadIdx.x;

    __shared__ float kk[64][32];
    __shared__ float vv[64][32];
    __shared__ float rps[900];

    const int base = wi * 64;
    for (int i = t; i < 900; i += 64) rps[i] = rp[i];
    for (int i = t; i < 2048; i += 64) {
        int m = i >> 5, d = i & 31;
        kk[m][d] = qkv[(size_t)(base + m) * 384 + 128 + head * 32 + d];
        vv[m][d] = qkv[(size_t)(base + m) * 384 + 256 + head * 32 + d];
    }
    __syncthreads();

    float q[32];
#pragma unroll
    for (int d = 0; d < 32; d++)
        q[d] = qkv[(size_t)(base + t) * 384 + head * 32 + d] * SCALE_Q;

    const int rn = t >> 3, cn = t & 7;
    const int widx = wi & 63;
    const int wh = widx >> 3, wwc = widx & 7;
    int zr_n = 0, zc_n = 0;
    if (shift) { zr_n = zone_(wh * 8 + rn); zc_n = zone_(wwc * 8 + cn); }

    float s[64];
    float mx = -1e30f;
#pragma unroll
    for (int m = 0; m < 64; m++) {
        float a = 0.0f;
#pragma unroll
        for (int d = 0; d < 32; d++) a += q[d] * kk[m][d];
        int rm = m >> 3, cm = m & 7;
        int ridx = (rn - rm + 7) * 15 + (cn - cm + 7);
        a += rps[ridx * 4 + head];
        if (shift) {
            if (zone_(wh * 8 + rm) != zr_n || zone_(wwc * 8 + cm) != zc_n)
                a += -100.0f;
        }
        s[m] = a;
        mx = fmaxf(mx, a);
    }
    float sum = 0.0f;
#pragma unroll
    for (int m = 0; m < 64; m++) { s[m] = expf(s[m] - mx); sum += s[m]; }
    float inv = 1.0f / sum;

    float o[32];
#pragma unroll
    for (int d = 0; d < 32; d++) o[d] = 0.0f;
#pragma unroll
    for (int m = 0; m < 64; m++) {
        float p = s[m] * inv;
#pragma unroll
        for (int d = 0; d < 32; d++) o[d] += p * vv[m][d];
    }
#pragma unroll
    for (int d = 0; d < 32; d++) {
        __nv_bfloat16 hb, lb; split1(o[d], hb, lb);
        size_t idx = (size_t)(base + t) * CC + head * 32 + d;
        ohi[idx] = hb; olo[idx] = lb;
    }
}

// ---------------------------------------------------------------------------
// Conv1d offset + mask head
// ---------------------------------------------------------------------------
__global__ void offmask_kernel(const float* __restrict__ xt,
                               const float* __restrict__ offw, const float* __restrict__ offb,
                               const float* __restrict__ mskw, const float* __restrict__ mskb,
                               float* __restrict__ off, float* __restrict__ msk) {
    __shared__ float swo[1152], swm[1152];
    int tid = threadIdx.x;
    for (int i = tid; i < 1152; i += 256) { swo[i] = offw[i]; swm[i] = mskw[i]; }
    __syncthreads();

    int warp = tid >> 5, lane = tid & 31;
    int pos = blockIdx.x * 8 + warp;
    int b = pos >> 12, l = pos & 4095;

    float ao[3] = {0.f, 0.f, 0.f}, am[3] = {0.f, 0.f, 0.f};
#pragma unroll
    for (int i = 0; i < 4; i++) {
        int c = lane + 32 * i;
        float xv[3];
#pragma unroll
        for (int j = 0; j < 3; j++) {
            int ls = l + j - 1;
            xv[j] = (ls >= 0 && ls < LL)
                  ? xt[((size_t)(b << 12) + ls) * CC + c] : 0.0f;
        }
#pragma unroll
        for (int ko = 0; ko < 3; ko++)
#pragma unroll
            for (int j = 0; j < 3; j++) {
                ao[ko] += xv[j] * swo[ko * 384 + c * 3 + j];
                am[ko] += xv[j] * swm[ko * 384 + c * 3 + j];
            }
    }
#pragma unroll
    for (int o = 16; o; o >>= 1)
#pragma unroll
        for (int ko = 0; ko < 3; ko++) {
            ao[ko] += __shfl_xor_sync(0xffffffffu, ao[ko], o);
            am[ko] += __shfl_xor_sync(0xffffffffu, am[ko], o);
        }
    if (lane == 0) {
#pragma unroll
        for (int ko = 0; ko < 3; ko++) {
            float ov = ao[ko] + offb[ko];
            float mv = am[ko] + mskb[ko];
            off[((size_t)(b * 3 + ko)) * LL + l] = ov;
            msk[((size_t)(b * 3 + ko)) * LL + l] = 1.0f / (1.0f + expf(-mv));
        }
    }
}

// ---------------------------------------------------------------------------
// Deformable sample -> bf16 hi/lo at flat (B,C,L) layout == (B,L,C) view
// ---------------------------------------------------------------------------
__global__ void deform_kernel(const float* __restrict__ xt,
                              const float* __restrict__ off,
                              const float* __restrict__ msk,
                              __nv_bfloat16* __restrict__ ohi,
                              __nv_bfloat16* __restrict__ olo) {
    __shared__ float s[128][33];
    __shared__ int   sfp[3][32], scp[3][32];
    __shared__ float sal[3][32], sm[3][32];

    int blk = blockIdx.x;
    int b = blk >> 7;
    int l0 = (blk & 127) << 5;
    int tid = threadIdx.x;

    if (tid < 96) {
        int k = tid / 32, li = tid % 32;
        int l = l0 + li;
        float o  = off[((size_t)(b * 3 + k)) * LL + l];
        float p  = fminf(fmaxf((float)l + o, 0.0f), 4095.0f);
        int fp   = (int)floorf(p);
        int cp   = min(fp + 1, 4095);
        sfp[k][li] = fp; scp[k][li] = cp;
        sal[k][li] = p - (float)fp;
        sm [k][li] = msk[((size_t)(b * 3 + k)) * LL + l];
    }
    __syncthreads();

    for (int e = tid; e < 4096; e += 256) {
        int li = e >> 7, c = e & 127;
        float acc = 0.0f;
#pragma unroll
        for (int k = 0; k < 3; k++) {
            float a  = sal[k][li];
            float xf = xt[((size_t)(b << 12) + sfp[k][li]) * CC + c];
            float xc = xt[((size_t)(b << 12) + scp[k][li]) * CC + c];
            acc += (xf * (1.0f - a) + xc * a) * sm[k][li];
        }
        s[c][li] = acc;
    }
    __syncthreads();
    for (int e = tid; e < 4096; e += 256) {
        int c = e >> 5, li = e & 31;
        size_t idx = (size_t)b * (CC * LL) + (size_t)c * LL + l0 + li;
        __nv_bfloat16 hb, lb; split1(s[c][li], hb, lb);
        ohi[idx] = hb; olo[idx] = lb;
    }
}

// ---------------------------------------------------------------------------
// Host launch
// ---------------------------------------------------------------------------
extern "C" void kernel_launch(void* const* d_in, const int* in_sizes, int n_in,
                              void* d_out, int out_size) {
    const float* xt    = (const float*)d_in[0];
    const float* hx    = (const float*)d_in[1];
    const float* cx    = (const float*)d_in[2];
    const float* red_w = (const float*)d_in[3];
    const float* red_b = (const float*)d_in[4];
    const float* n1g   = (const float*)d_in[5];
    const float* n1b   = (const float*)d_in[6];
    const float* qkvw  = (const float*)d_in[7];
    const float* qkvb  = (const float*)d_in[8];
    const float* rp    = (const float*)d_in[9];
    const float* pw    = (const float*)d_in[10];
    const float* pb    = (const float*)d_in[11];
    const float* n2g   = (const float*)d_in[12];
    const float* n2b   = (const float*)d_in[13];
    const float* f1w   = (const float*)d_in[14];
    const float* f1b   = (const float*)d_in[15];
    const float* f2w   = (const float*)d_in[16];
    const float* f2b   = (const float*)d_in[17];
    const float* off_w = (const float*)d_in[18];
    const float* off_b = (const float*)d_in[19];
    const float* msk_w = (const float*)d_in[20];
    const float* msk_b = (const float*)d_in[21];
    const float* lf_w  = (const float*)d_in[22];
    const float* lf_b  = (const float*)d_in[23];
    const float* gf_w  = (const float*)d_in[24];
    const float* gf_b  = (const float*)d_in[25];
    const float* ff_w  = (const float*)d_in[26];
    const float* ff_b  = (const float*)d_in[27];
    float* hy = (float*)d_out;

    float *pg, *pqkv, *poff, *pmsk, *pt1;
    cudaGetSymbolAddress((void**)&pg,   g_buf);
    cudaGetSymbolAddress((void**)&pqkv, g_qkv);
    cudaGetSymbolAddress((void**)&poff, g_off);
    cudaGetSymbolAddress((void**)&pmsk, g_msk);
    cudaGetSymbolAddress((void**)&pt1,  g_t1);

    __nv_bfloat16 *Ah, *Al, *Bh, *Bl;
    cudaGetSymbolAddress((void**)&Ah, g_Ah);
    cudaGetSymbolAddress((void**)&Al, g_Al);
    cudaGetSymbolAddress((void**)&Bh, g_Bh);
    cudaGetSymbolAddress((void**)&Bl, g_Bl);

    __nv_bfloat16 *redh, *redl, *qkvh, *qkvl, *pwh, *pwl, *f1h, *f1l, *f2h, *f2l;
    __nv_bfloat16 *lfh, *lfl, *gfh, *gfl, *ffh, *ffl;
    cudaGetSymbolAddress((void**)&redh, w_red_h);
    cudaGetSymbolAddress((void**)&redl, w_red_l);
    cudaGetSymbolAddress((void**)&qkvh, w_qkv_h);
    cudaGetSymbolAddress((void**)&qkvl, w_qkv_l);
    cudaGetSymbolAddress((void**)&pwh,  w_pw_h);
    cudaGetSymbolAddress((void**)&pwl,  w_pw_l);
    cudaGetSymbolAddress((void**)&f1h,  w_f1_h);
    cudaGetSymbolAddress((void**)&f1l,  w_f1_l);
    cudaGetSymbolAddress((void**)&f2h,  w_f2_h);
    cudaGetSymbolAddress((void**)&f2l,  w_f2_l);
    cudaGetSymbolAddress((void**)&lfh,  w_lf_h);
    cudaGetSymbolAddress((void**)&lfl,  w_lf_l);
    cudaGetSymbolAddress((void**)&gfh,  w_gf_h);
    cudaGetSymbolAddress((void**)&gfl,  w_gf_l);
    cudaGetSymbolAddress((void**)&ffh,  w_ff_h);
    cudaGetSymbolAddress((void**)&ffl,  w_ff_l);

    cudaFuncSetAttribute(gemm_mma<EpiBias>,      cudaFuncAttributeMaxDynamicSharedMemorySize, GEMM_SMEM);
    cudaFuncSetAttribute(gemm_mma<EpiGeluHL>,    cudaFuncAttributeMaxDynamicSharedMemorySize, GEMM_SMEM);
    cudaFuncSetAttribute(gemm_mma<EpiProj>,      cudaFuncAttributeMaxDynamicSharedMemorySize, GEMM_SMEM);
    cudaFuncSetAttribute(gemm_mma<EpiResid>,     cudaFuncAttributeMaxDynamicSharedMemorySize, GEMM_SMEM);
    cudaFuncSetAttribute(gemm_mma<EpiMulReluHL>, cudaFuncAttributeMaxDynamicSharedMemorySize, GEMM_SMEM);
    cudaFuncSetAttribute(gemm_mma<EpiLSTM>,      cudaFuncAttributeMaxDynamicSharedMemorySize, GEMM_SMEM);

    const dim3 blk256(256);

    // 0) weight split + transpose (tiny)
    wsplit_kernel<<<(256*128 + 255) / 256, blk256>>>(red_w, 256, 128, redh, redl);
    for (int i = 0; i < 2; i++) {
        wsplit_kernel<<<(128*384 + 255) / 256, blk256>>>(qkvw + (size_t)i*128*384, 128, 384, qkvh + (size_t)i*384*128, qkvl + (size_t)i*384*128);
        wsplit_kernel<<<(128*128 + 255) / 256, blk256>>>(pw   + (size_t)i*128*128, 128, 128, pwh  + (size_t)i*128*128, pwl  + (size_t)i*128*128);
        wsplit_kernel<<<(128*512 + 255) / 256, blk256>>>(f1w  + (size_t)i*128*512, 128, 512, f1h  + (size_t)i*512*128, f1l  + (size_t)i*512*128);
        wsplit_kernel<<<(512*128 + 255) / 256, blk256>>>(f2w  + (size_t)i*512*128, 512, 128, f2h  + (size_t)i*128*512, f2l  + (size_t)i*128*512);
    }
    wsplit_kernel<<<(128*128 + 255) / 256, blk256>>>(lf_w, 128, 128, lfh, lfl);
    wsplit_kernel<<<(128*128 + 255) / 256, blk256>>>(gf_w, 128, 128, gfh, gfl);
    wsplit_kernel<<<(128*128 + 255) / 256, blk256>>>(ff_w, 128, 128, ffh, ffl);

    const dim3 gN1(1, MROWS / 128), gN3(3, MROWS / 128), gN4(4, MROWS / 128);

    // 1) g = concat(xt, hx) @ red_w + red_b
    cvtcat_kernel<<<MROWS * 128 / 256, blk256>>>(xt, hx, Ah, Al);
    gemm_mma<<<gN1, blk256, GEMM_SMEM>>>(Ah, Al, redh, redl, 256, 128,
                                         EpiBias{pg, red_b});

    // 2) two Swin blocks
    for (int i = 0; i < 2; i++) {
        int shift = (i == 0) ? 0 : 4;
        const float* qkvb_i = qkvb + (size_t)i * 384;
        const float* rp_i   = rp   + (size_t)i * 225 * NHEAD;
        const float* pb_i   = pb   + (size_t)i * 128;
        const float* f1b_i  = f1b  + (size_t)i * 512;
        const float* f2b_i  = f2b  + (size_t)i * 128;

        ln_part_kernel<<<MROWS / 8, blk256>>>(pg, n1g + i * CC, n1b + i * CC, Ah, Al, shift);
        gemm_mma<<<gN3, blk256, GEMM_SMEM>>>(Ah, Al,
                                             qkvh + (size_t)i*384*128, qkvl + (size_t)i*384*128,
                                             128, 384, EpiBias{pqkv, qkvb_i});
        attn_kernel<<<dim3(NHEAD, BB * 64), 64>>>(pqkv, rp_i, Ah, Al, shift);
        gemm_mma<<<gN1, blk256, GEMM_SMEM>>>(Ah, Al,
                                             pwh + (size_t)i*128*128, pwl + (size_t)i*128*128,
                                             128, 128, EpiProj{pg, pb_i, shift});
        ln_plain_kernel<<<MROWS / 8, blk256>>>(pg, n2g + i * CC, n2b + i * CC, Ah, Al);
        gemm_mma<<<gN4, blk256, GEMM_SMEM>>>(Ah, Al,
                                             f1h + (size_t)i*512*128, f1l + (size_t)i*512*128,
                                             128, 512, EpiGeluHL{Bh, Bl, f1b_i});
        gemm_mma<<<gN1, blk256, GEMM_SMEM>>>(Bh, Bl,
                                             f2h + (size_t)i*128*512, f2l + (size_t)i*128*512,
                                             512, 128, EpiResid{pg, pg, f2b_i});
    }

    // 3) local branch -> bufA hi/lo
    offmask_kernel<<<MROWS / 8, blk256>>>(xt, off_w, off_b, msk_w, msk_b, poff, pmsk);
    deform_kernel<<<BB * (LL / 32), blk256>>>(xt, poff, pmsk, Ah, Al);

    // 4) fusion + LSTM gating
    gemm_mma<<<gN1, blk256, GEMM_SMEM>>>(Ah, Al, lfh, lfl, 128, 128,
                                         EpiBias{pt1, lf_b});
    cvt_kernel<<<MROWS * 128 / 256, blk256>>>(pg, Bh, Bl);
    gemm_mma<<<gN1, blk256, GEMM_SMEM>>>(Bh, Bl, gfh, gfl, 128, 128,
                                         EpiMulReluHL{Ah, Al, pt1, gf_b});
    gemm_mma<<<gN1, blk256, GEMM_SMEM>>>(Ah, Al, ffh, ffl, 128, 128,
                                         EpiLSTM{hy, cx, ff_b});
}

// round 7
// speedup vs baseline: 1.3425x; 1.0267x over previous
#include <cuda_runtime.h>
#include <cuda_bf16.h>
#include <math.h>
#include <stdint.h>

// ---------------------------------------------------------------------------
// Problem constants
// ---------------------------------------------------------------------------
#define BB   8
#define LL   4096
#define CC   128
#define NHEAD 4
#define MROWS (BB*LL)      // 32768
#define SCALE_Q 0.17677669529663687f

// ---------------------------------------------------------------------------
// Scratch (device globals — no allocation allowed)
// ---------------------------------------------------------------------------
__device__ float g_buf  [MROWS * CC];
__device__ float g_qkv  [MROWS * 3 * CC];
__device__ float g_off  [BB * 3 * LL];
__device__ float g_msk  [BB * 3 * LL];

// bf16 hi/lo activation buffers
__device__ __align__(256) __nv_bfloat16 g_Ah[MROWS * 256], g_Al[MROWS * 256];
__device__ __align__(256) __nv_bfloat16 g_Bh[MROWS * 512], g_Bl[MROWS * 512];
__device__ __align__(256) __nv_bfloat16 g_Ch[MROWS * 128], g_Cl[MROWS * 128];

// split + transposed weights, bf16 [N][K]
__device__ __align__(256) __nv_bfloat16 w_red_h[128*256],  w_red_l[128*256];
__device__ __align__(256) __nv_bfloat16 w_qkv_h[2][384*128], w_qkv_l[2][384*128];
__device__ __align__(256) __nv_bfloat16 w_pw_h [2][128*128], w_pw_l [2][128*128];
__device__ __align__(256) __nv_bfloat16 w_f1_h [2][512*128], w_f1_l [2][512*128];
__device__ __align__(256) __nv_bfloat16 w_f2_h [2][128*512], w_f2_l [2][128*512];
__device__ __align__(256) __nv_bfloat16 w_lf_h[128*128], w_lf_l[128*128];
__device__ __align__(256) __nv_bfloat16 w_gf_h[128*128], w_gf_l[128*128];
__device__ __align__(256) __nv_bfloat16 w_ff_h[128*128], w_ff_l[128*128];

// ---------------------------------------------------------------------------
// helpers
// ---------------------------------------------------------------------------
__device__ __forceinline__ uint32_t smem_u32(const void* p) {
    uint32_t a;
    asm("{ .reg .u64 t; cvta.to.shared.u64 t, %1; cvt.u32.u64 %0, t; }"
        : "=r"(a) : "l"(p));
    return a;
}
__device__ __forceinline__ void cp16(uint32_t s, const void* g) {
    asm volatile("cp.async.cg.shared.global [%0], [%1], 16;" :: "r"(s), "l"(g));
}
__device__ __forceinline__ void split1(float v, __nv_bfloat16& h, __nv_bfloat16& l) {
    h = __float2bfloat16(v);
    l = __float2bfloat16(v - __bfloat162float(h));
}

#define LDSM4(r, a) \
    asm volatile("ldmatrix.sync.aligned.m8n8.x4.shared.b16 {%0,%1,%2,%3}, [%4];" \
        : "=r"((r)[0]), "=r"((r)[1]), "=r"((r)[2]), "=r"((r)[3]) : "r"(a))

#define MMA16816(d, a, b0, b1) \
    asm volatile("mma.sync.aligned.m16n8k16.row.col.f32.bf16.bf16.f32 " \
        "{%0,%1,%2,%3}, {%4,%5,%6,%7}, {%8,%9}, {%0,%1,%2,%3};" \
        : "+f"((d)[0]), "+f"((d)[1]), "+f"((d)[2]), "+f"((d)[3]) \
        : "r"((a)[0]), "r"((a)[1]), "r"((a)[2]), "r"((a)[3]), "r"(b0), "r"(b1))

// ---------------------------------------------------------------------------
// Epilogues: ep(m, n0, N, float4) with n0 % 4 == 0, coalesced across threads
// ---------------------------------------------------------------------------
struct EpiBias {
    float* out; const float* bias;
    __device__ __forceinline__ void operator()(int m, int n0, int N, float4 v) const {
        const float4 b = *(const float4*)&bias[n0];
        v.x += b.x; v.y += b.y; v.z += b.z; v.w += b.w;
        *(float4*)&out[(size_t)m * N + n0] = v;
    }
};
struct EpiGeluHL {
    __nv_bfloat16 *hi, *lo; const float* bias;
    __device__ __forceinline__ void operator()(int m, int n0, int N, float4 v) const {
        const float4 b = *(const float4*)&bias[n0];
        float g[4] = {v.x + b.x, v.y + b.y, v.z + b.z, v.w + b.w};
        __nv_bfloat16 h[4], l[4];
#pragma unroll
        for (int k = 0; k < 4; k++) {
            float t = 0.5f * g[k] * (1.0f + erff(g[k] * 0.7071067811865476f));
            split1(t, h[k], l[k]);
        }
        size_t i = (size_t)m * N + n0;
        *(uint2*)&hi[i] = *(uint2*)h;
        *(uint2*)&lo[i] = *(uint2*)l;
    }
};
struct EpiResid {   // out = res + acc + bias (fp32)
    float* out; const float* res; const float* bias;
    __device__ __forceinline__ void operator()(int m, int n0, int N, float4 v) const {
        size_t i = (size_t)m * N + n0;
        const float4 b = *(const float4*)&bias[n0];
        const float4 r = *(const float4*)&res[i];
        v.x += b.x + r.x; v.y += b.y + r.y; v.z += b.z + r.z; v.w += b.w + r.w;
        *(float4*)&out[i] = v;
    }
};
struct EpiResidHL { // (res + acc + bias) -> hi/lo only
    __nv_bfloat16 *hi, *lo; const float* res; const float* bias;
    __device__ __forceinline__ void operator()(int m, int n0, int N, float4 v) const {
        size_t i = (size_t)m * N + n0;
        const float4 b = *(const float4*)&bias[n0];
        const float4 r = *(const float4*)&res[i];
        float g[4] = {v.x + b.x + r.x, v.y + b.y + r.y, v.z + b.z + r.z, v.w + b.w + r.w};
        __nv_bfloat16 h[4], l[4];
#pragma unroll
        for (int k = 0; k < 4; k++) split1(g[k], h[k], l[k]);
        *(uint2*)&hi[i] = *(uint2*)h;
        *(uint2*)&lo[i] = *(uint2*)l;
    }
};
struct EpiProj {   // window-reverse + unroll(+shift) + residual RMW into out
    float* out; const float* bias; int shift;
    __device__ __forceinline__ void operator()(int m, int n0, int N, float4 v) const {
        int b    = m >> 12;
        int rb   = m & 4095;
        int widx = rb >> 6;
        int tok  = rb & 63;
        int hh = ((widx >> 3) << 3) + (tok >> 3);
        int ww = ((widx & 7) << 3) + (tok & 7);
        int h = (hh + shift) & 63;
        int w = (ww + shift) & 63;
        size_t dst = ((size_t)(b << 12) + (h << 6) + w) * CC + n0;
        const float4 bi = *(const float4*)&bias[n0];
        float4 o = *(const float4*)&out[dst];
        o.x += v.x + bi.x; o.y += v.y + bi.y; o.z += v.z + bi.z; o.w += v.w + bi.w;
        *(float4*)&out[dst] = o;
    }
};
struct EpiLSTM {
    float* hy; const float* cx; const float* bias;
    __device__ __forceinline__ void operator()(int m, int n0, int N, float4 v) const {
        size_t i = (size_t)m * N + n0;
        const float4 b = *(const float4*)&bias[n0];
        const float4 c = *(const float4*)&cx[i];
        float f[4] = {v.x + b.x, v.y + b.y, v.z + b.z, v.w + b.w};
        float cc[4] = {c.x, c.y, c.z, c.w};
        float o[4];
#pragma unroll
        for (int k = 0; k < 4; k++) {
            float gate = 1.0f / (1.0f + expf(-f[k]));
            float cell = tanhf(f[k]);
            float cy   = gate * (cc[k] + cell);
            o[k] = gate * tanhf(cy);
        }
        *(float4*)&hy[i] = *(float4*)o;
    }
};

// ---------------------------------------------------------------------------
// bf16 hi/lo split GEMM mainloop on mma.sync (m16n8k16), 3 passes (hh,hl,lh).
// CTA tile 128x128, 8 warps (4x2), K-chunk 32, double-buffered cp.async smem.
// ---------------------------------------------------------------------------
#define TSTRIDE 80
#define TILE_B  10240
#define STAGE_B 40960
#define GEMM_SMEM (2 * STAGE_B)

__device__ __forceinline__ void mma_mainloop(
    const __nv_bfloat16* __restrict__ Ah, const __nv_bfloat16* __restrict__ Al,
    const __nv_bfloat16* __restrict__ Wh, const __nv_bfloat16* __restrict__ Wl,
    int K, int bm, int bn, uint32_t sb, int tid, float acc[2][8][4])
{
    const int wid  = tid >> 5;
    const int lane = tid & 31;
    const int nch = K >> 5;

    auto load_stage = [&](int i) {
        uint32_t st = sb + (uint32_t)(i & 1) * STAGE_B;
        int kt = i << 5;
#pragma unroll
        for (int t = 0; t < 2; t++) {
            int c = tid + t * 256;
            int r = c >> 2, q = c & 3;
            uint32_t so = (uint32_t)r * TSTRIDE + q * 16;
            size_t ga = (size_t)(bm + r) * K + kt + q * 8;
            size_t gb = (size_t)(bn + r) * K + kt + q * 8;
            cp16(st + so,              Ah + ga);
            cp16(st + TILE_B + so,     Al + ga);
            cp16(st + 2 * TILE_B + so, Wh + gb);
            cp16(st + 3 * TILE_B + so, Wl + gb);
        }
        asm volatile("cp.async.commit_group;");
    };

    load_stage(0);
    for (int i = 0; i < nch; i++) {
        if (i + 1 < nch) {
            load_stage(i + 1);
            asm volatile("cp.async.wait_group 1;");
        } else {
            asm volatile("cp.async.wait_group 0;");
        }
        __syncthreads();

        uint32_t st = sb + (uint32_t)(i & 1) * STAGE_B;
#pragma unroll
        for (int j = 0; j < 2; j++) {
            uint32_t ah[2][4], al[2][4], bh[4][4], bl[4][4];
#pragma unroll
            for (int mt = 0; mt < 2; mt++) {
                uint32_t addr = st +
                    (uint32_t)(((wid & 3) << 5) + (mt << 4) + (lane & 15)) * TSTRIDE +
                    (j << 5) + ((lane >> 4) << 4);
                LDSM4(ah[mt], addr);
                LDSM4(al[mt], addr + TILE_B);
            }
#pragma unroll
            for (int nb = 0; nb < 4; nb++) {
                uint32_t addr = st + 2 * TILE_B +
                    (uint32_t)(((wid >> 2) << 6) + (nb << 4) + (lane & 7) + ((lane >> 4) << 3)) * TSTRIDE +
                    (j << 5) + (((lane >> 3) & 1) << 4);
                LDSM4(bh[nb], addr);
                LDSM4(bl[nb], addr + TILE_B);
            }
#pragma unroll
            for (int mt = 0; mt < 2; mt++)
#pragma unroll
                for (int nt = 0; nt < 8; nt++) {
                    float* d = acc[mt][nt];
                    uint32_t b0h = bh[nt >> 1][(nt & 1) * 2];
                    uint32_t b1h = bh[nt >> 1][(nt & 1) * 2 + 1];
                    uint32_t b0l = bl[nt >> 1][(nt & 1) * 2];
                    uint32_t b1l = bl[nt >> 1][(nt & 1) * 2 + 1];
                    MMA16816(d, ah[mt], b0h, b1h);
                    MMA16816(d, ah[mt], b0l, b1l);
                    MMA16816(d, al[mt], b0h, b1h);
                }
        }
        __syncthreads();
    }
}

// stash fragments to smem, then apply epilogue with coalesced float4 runs
#define SOUT_STRIDE 132

template <class EP>
__global__ __launch_bounds__(256, 1)
void gemm_mma(const __nv_bfloat16* __restrict__ Ah, const __nv_bfloat16* __restrict__ Al,
              const __nv_bfloat16* __restrict__ Wh, const __nv_bfloat16* __restrict__ Wl,
              int K, int Nfull, EP ep) {
    extern __shared__ char sm[];
    const int tid  = threadIdx.x;
    const int wid  = tid >> 5;
    const int lane = tid & 31;
    const int bm = blockIdx.y * 128;
    const int bn = blockIdx.x * 128;
    const uint32_t sb = smem_u32(sm);

    float acc[2][8][4];
#pragma unroll
    for (int a = 0; a < 2; a++)
#pragma unroll
        for (int b = 0; b < 8; b++)
#pragma unroll
            for (int c = 0; c < 4; c++) acc[a][b][c] = 0.0f;

    mma_mainloop(Ah, Al, Wh, Wl, K, bm, bn, sb, tid, acc);

    float* sout = (float*)sm;
    const int mb = (wid & 3) << 5, nb = (wid >> 2) << 6;
#pragma unroll
    for (int mt = 0; mt < 2; mt++)
#pragma unroll
        for (int nt = 0; nt < 8; nt++)
#pragma unroll
            for (int rg = 0; rg < 4; rg++) {
                int ml = mb + (mt << 4) + (lane >> 2) + ((rg >> 1) << 3);
                int nl = nb + (nt << 3) + ((lane & 3) << 1) + (rg & 1);
                sout[ml * SOUT_STRIDE + nl] = acc[mt][nt][rg];
            }
    __syncthreads();
#pragma unroll 4
    for (int e = tid; e < 4096; e += 256) {
        int r = e >> 5, c4 = (e & 31) << 2;
        float4 v = *(float4*)&sout[r * SOUT_STRIDE + c4];
        ep(bm + r, bn + c4, Nfull, v);
    }
}

// dual GEMM: fu = relu((A1@W1 + b1) * (A2@W2 + b2)) -> hi/lo. K=128, N=128.
__global__ __launch_bounds__(256, 1)
void gemm_lfgf(const __nv_bfloat16* __restrict__ A1h, const __nv_bfloat16* __restrict__ A1l,
               const __nv_bfloat16* __restrict__ W1h, const __nv_bfloat16* __restrict__ W1l,
               const __nv_bfloat16* __restrict__ A2h, const __nv_bfloat16* __restrict__ A2l,
               const __nv_bfloat16* __restrict__ W2h, const __nv_bfloat16* __restrict__ W2l,
               const float* __restrict__ b1, const float* __restrict__ b2,
               __nv_bfloat16* __restrict__ ohi, __nv_bfloat16* __restrict__ olo) {
    extern __shared__ char sm[];
    const int tid  = threadIdx.x;
    const int wid  = tid >> 5;
    const int lane = tid & 31;
    const int bm = blockIdx.y * 128;
    const int bn = 0;
    const uint32_t sb = smem_u32(sm);

    float acc1[2][8][4], acc2[2][8][4];
#pragma unroll
    for (int a = 0; a < 2; a++)
#pragma unroll
        for (int b = 0; b < 8; b++)
#pragma unroll
            for (int c = 0; c < 4; c++) { acc1[a][b][c] = 0.0f; acc2[a][b][c] = 0.0f; }

    mma_mainloop(A1h, A1l, W1h, W1l, 128, bm, bn, sb, tid, acc1);
    mma_mainloop(A2h, A2l, W2h, W2l, 128, bm, bn, sb, tid, acc2);

    float* sout = (float*)sm;
    const int mb = (wid & 3) << 5, nb = (wid >> 2) << 6;
#pragma unroll
    for (int mt = 0; mt < 2; mt++)
#pragma unroll
        for (int nt = 0; nt < 8; nt++)
#pragma unroll
            for (int rg = 0; rg < 4; rg++) {
                int ml = mb + (mt << 4) + (lane >> 2) + ((rg >> 1) << 3);
                int nl = nb + (nt << 3) + ((lane & 3) << 1) + (rg & 1);
                float v = fmaxf(0.0f, (acc1[mt][nt][rg] + b1[nl]) *
                                      (acc2[mt][nt][rg] + b2[nl]));
                sout[ml * SOUT_STRIDE + nl] = v;
            }
    __syncthreads();
#pragma unroll 4
    for (int e = tid; e < 4096; e += 256) {
        int r = e >> 5, c4 = (e & 31) << 2;
        float4 v = *(float4*)&sout[r * SOUT_STRIDE + c4];
        float g[4] = {v.x, v.y, v.z, v.w};
        __nv_bfloat16 h[4], l[4];
#pragma unroll
        for (int k = 0; k < 4; k++) split1(g[k], h[k], l[k]);
        size_t i = (size_t)(bm + r) * 128 + c4;
        *(uint2*)&ohi[i] = *(uint2*)h;
        *(uint2*)&olo[i] = *(uint2*)l;
    }
}

// ---------------------------------------------------------------------------
// Combined weight transpose + split: 12 jobs in one launch
// ---------------------------------------------------------------------------
struct WJob { const float* src; __nv_bfloat16* hi; __nv_bfloat16* lo; int K, N, start; };
struct WJobs { WJob j[12]; int total; };

__global__ void wsplit_all(WJobs js) {
    int idx = blockIdx.x * 256 + threadIdx.x;
    if (idx >= js.total) return;
    int jj = 0;
#pragma unroll
    for (int t = 1; t < 12; t++) if (idx >= js.j[t].start) jj = t;
    const WJob J = js.j[jj];
    int local = idx - J.start;
    int k = local / J.N, n = local - k * J.N;
    __nv_bfloat16 h, l; split1(J.src[local], h, l);
    J.hi[(size_t)n * J.K + k] = h;
    J.lo[(size_t)n * J.K + k] = l;
}

// concat(xt,hx) -> bufA [M][256] hi/lo
__global__ void cvtcat_kernel(const float* __restrict__ x, const float* __restrict__ hsrc,
                              __nv_bfloat16* __restrict__ hi, __nv_bfloat16* __restrict__ lo) {
    int i = blockIdx.x * 256 + threadIdx.x;
    int m = i >> 7, k = i & 127;
    __nv_bfloat16 h, l;
    split1(x[i], h, l);
    hi[(size_t)m * 256 + k] = h;       lo[(size_t)m * 256 + k] = l;
    split1(hsrc[i], h, l);
    hi[(size_t)m * 256 + 128 + k] = h; lo[(size_t)m * 256 + 128 + k] = l;
}

// ---------------------------------------------------------------------------
// LayerNorm + (roll) + window partition -> bf16 hi/lo [M][128]
// ---------------------------------------------------------------------------
__global__ void ln_part_kernel(const float* __restrict__ x,
                               const float* __restrict__ gm,
                               const float* __restrict__ bt,
                               __nv_bfloat16* __restrict__ ohi,
                               __nv_bfloat16* __restrict__ olo, int shift) {
    int warp = blockIdx.x * 8 + (threadIdx.x >> 5);
    int lane = threadIdx.x & 31;
    int wi = warp >> 6, tok = warp & 63;
    int b = wi >> 6, widx = wi & 63;
    int hh = ((widx >> 3) << 3) + (tok >> 3);
    int ww = ((widx & 7) << 3) + (tok & 7);
    int h = (hh + shift) & 63;
    int w = (ww + shift) & 63;
    const float* row = x + ((size_t)(b << 12) + (h << 6) + w) * CC;

    float v[4], sum = 0.0f, sq = 0.0f;
#pragma unroll
    for (int i = 0; i < 4; i++) {
        v[i] = row[lane + 32 * i];
        sum += v[i]; sq += v[i] * v[i];
    }
#pragma unroll
    for (int o = 16; o; o >>= 1) {
        sum += __shfl_xor_sync(0xffffffffu, sum, o);
        sq  += __shfl_xor_sync(0xffffffffu, sq, o);
    }
    float mean = sum * (1.0f / 128.0f);
    float var  = sq * (1.0f / 128.0f) - mean * mean;
    float rstd = rsqrtf(var + 1e-5f);
#pragma unroll
    for (int i = 0; i < 4; i++) {
        int c = lane + 32 * i;
        float o = (v[i] - mean) * rstd * gm[c] + bt[c];
        __nv_bfloat16 hb, lb; split1(o, hb, lb);
        ohi[(size_t)warp * CC + c] = hb;
        olo[(size_t)warp * CC + c] = lb;
    }
}

__global__ void ln_plain_kernel(const float* __restrict__ x,
                                const float* __restrict__ gm,
                                const float* __restrict__ bt,
                                __nv_bfloat16* __restrict__ ohi,
                                __nv_bfloat16* __restrict__ olo) {
    int warp = blockIdx.x * 8 + (threadIdx.x >> 5);
    int lane = threadIdx.x & 31;
    const float* row = x + (size_t)warp * CC;
    float v[4], sum = 0.0f, sq = 0.0f;
#pragma unroll
    for (int i = 0; i < 4; i++) {
        v[i] = row[lane + 32 * i];
        sum += v[i]; sq += v[i] * v[i];
    }
#pragma unroll
    for (int o = 16; o; o >>= 1) {
        sum += __shfl_xor_sync(0xffffffffu, sum, o);
        sq  += __shfl_xor_sync(0xffffffffu, sq, o);
    }
    float mean = sum * (1.0f / 128.0f);
    float var  = sq * (1.0f / 128.0f) - mean * mean;
    float rstd = rsqrtf(var + 1e-5f);
#pragma unroll
    for (int i = 0; i < 4; i++) {
        int c = lane + 32 * i;
        float o = (v[i] - mean) * rstd * gm[c] + bt[c];
        __nv_bfloat16 hb, lb; split1(o, hb, lb);
        ohi[(size_t)warp * CC + c] = hb;
        olo[(size_t)warp * CC + c] = lb;
    }
}

// ---------------------------------------------------------------------------
// Window attention: block = one window (4 heads x 64 rows = 256 threads),
// single online pass (no max subtraction: logits are tiny; mask -100 -> ~0).
// ---------------------------------------------------------------------------
__device__ __forceinline__ int zone_(int h) { return h < 56 ? 0 : (h < 60 ? 1 : 2); }

#define ATTN_SMEM 69136   // kk 32KB + vv 32KB + rps 3600B

__global__ __launch_bounds__(256)
void attn_kernel(const float* __restrict__ qkv, const float* __restrict__ rp,
                 __nv_bfloat16* __restrict__ ohi, __nv_bfloat16* __restrict__ olo,
                 int shift) {
    extern __shared__ float smf[];
    float* kk  = smf;                 // [4][64][32]
    float* vv  = smf + 8192;          // [4][64][32]
    float* rps = smf + 16384;         // [900]

    const int wi   = blockIdx.x;     // window 0..511
    const int t    = threadIdx.x;
    const int head = t >> 6;
    const int row  = t & 63;
    const int base = wi * 64;

    for (int i = t; i < 900; i += 256) rps[i] = rp[i];
    for (int i = t; i < 8192; i += 256) {
        int m = i >> 7, c = i & 127;
        float kvk = qkv[(size_t)(base + m) * 384 + 128 + c];
        float kvv = qkv[(size_t)(base + m) * 384 + 256 + c];
        kk[((c >> 5) * 64 + m) * 32 + (c & 31)] = kvk;
        vv[((c >> 5) * 64 + m) * 32 + (c & 31)] = kvv;
    }
    __syncthreads();

    float q[32];
#pragma unroll
    for (int d4 = 0; d4 < 8; d4++) {
        float4 qq = *(const float4*)&qkv[(size_t)(base + row) * 384 + head * 32 + d4 * 4];
        q[d4*4+0] = qq.x * SCALE_Q; q[d4*4+1] = qq.y * SCALE_Q;
        q[d4*4+2] = qq.z * SCALE_Q; q[d4*4+3] = qq.w * SCALE_Q;
    }

    const int rn = row >> 3, cn = row & 7;
    const int widx = wi & 63;
    const int wh = widx >> 3, wwc = widx & 7;
    int zr_n = 0, zc_n = 0;
    if (shift) { zr_n = zone_(wh * 8 + rn); zc_n = zone_(wwc * 8 + cn); }

    const float* kh = kk + head * 2048;
    const float* vh = vv + head * 2048;

    float o[32];
#pragma unroll
    for (int d = 0; d < 32; d++) o[d] = 0.0f;
    float sum = 0.0f;

#pragma unroll 4
    for (int m = 0; m < 64; m++) {
        float a = 0.0f;
        const float* kr = kh + m * 32;
#pragma unroll
        for (int d4 = 0; d4 < 8; d4++) {
            float4 kv4 = *(const float4*)&kr[d4 * 4];
            a += q[d4*4+0] * kv4.x + q[d4*4+1] * kv4.y +
                 q[d4*4+2] * kv4.z + q[d4*4+3] * kv4.w;
        }
        int rm = m >> 3, cm = m & 7;
        int ridx = (rn - rm + 7) * 15 + (cn - cm + 7);
        a += rps[ridx * 4 + head];
        if (shift) {
            if (zone_(wh * 8 + rm) != zr_n || zone_(wwc * 8 + cm) != zc_n)
                a += -100.0f;
        }
        float p = __expf(a);
        sum += p;
        const float* vr = vh + m * 32;
#pragma unroll
        for (int d4 = 0; d4 < 8; d4++) {
            float4 vv4 = *(const float4*)&vr[d4 * 4];
            o[d4*4+0] += p * vv4.x; o[d4*4+1] += p * vv4.y;
            o[d4*4+2] += p * vv4.z; o[d4*4+3] += p * vv4.w;
        }
    }
    float inv = 1.0f / sum;
#pragma unroll
    for (int d4 = 0; d4 < 8; d4++) {
        __nv_bfloat16 h[4], l[4];
#pragma unroll
        for (int k = 0; k < 4; k++) split1(o[d4*4+k] * inv, h[k], l[k]);
        size_t idx = (size_t)(base + row) * CC + head * 32 + d4 * 4;
        *(uint2*)&ohi[idx] = *(uint2*)h;
        *(uint2*)&olo[idx] = *(uint2*)l;
    }
}

// ---------------------------------------------------------------------------
// Conv1d offset + mask head
// ---------------------------------------------------------------------------
__global__ void offmask_kernel(const float* __restrict__ xt,
                               const float* __restrict__ offw, const float* __restrict__ offb,
                               const float* __restrict__ mskw, const float* __restrict__ mskb,
                               float* __restrict__ off, float* __restrict__ msk) {
    __shared__ float swo[1152], swm[1152];
    int tid = threadIdx.x;
    for (int i = tid; i < 1152; i += 256) { swo[i] = offw[i]; swm[i] = mskw[i]; }
    __syncthreads();

    int warp = tid >> 5, lane = tid & 31;
    int pos = blockIdx.x * 8 + warp;
    int b = pos >> 12, l = pos & 4095;

    float ao[3] = {0.f, 0.f, 0.f}, am[3] = {0.f, 0.f, 0.f};
#pragma unroll
    for (int i = 0; i < 4; i++) {
        int c = lane + 32 * i;
        float xv[3];
#pragma unroll
        for (int j = 0; j < 3; j++) {
            int ls = l + j - 1;
            xv[j] = (ls >= 0 && ls < LL)
                  ? xt[((size_t)(b << 12) + ls) * CC + c] : 0.0f;
        }
#pragma unroll
        for (int ko = 0; ko < 3; ko++)
#pragma unroll
            for (int j = 0; j < 3; j++) {
                ao[ko] += xv[j] * swo[ko * 384 + c * 3 + j];
                am[ko] += xv[j] * swm[ko * 384 + c * 3 + j];
            }
    }
#pragma unroll
    for (int o = 16; o; o >>= 1)
#pragma unroll
        for (int ko = 0; ko < 3; ko++) {
            ao[ko] += __shfl_xor_sync(0xffffffffu, ao[ko], o);
            am[ko] += __shfl_xor_sync(0xffffffffu, am[ko], o);
        }
    if (lane == 0) {
#pragma unroll
        for (int ko = 0; ko < 3; ko++) {
            float ov = ao[ko] + offb[ko];
            float mv = am[ko] + mskb[ko];
            off[((size_t)(b * 3 + ko)) * LL + l] = ov;
            msk[((size_t)(b * 3 + ko)) * LL + l] = 1.0f / (1.0f + expf(-mv));
        }
    }
}

// ---------------------------------------------------------------------------
// Deformable sample -> bf16 hi/lo at flat (B,C,L) layout == (B,L,C) view
// ---------------------------------------------------------------------------
__global__ void deform_kernel(const float* __restrict__ xt,
                              const float* __restrict__ off,
                              const float* __restrict__ msk,
                              __nv_bfloat16* __restrict__ ohi,
                              __nv_bfloat16* __restrict__ olo) {
    __shared__ float s[128][33];
    __shared__ int   sfp[3][32], scp[3][32];
    __shared__ float sal[3][32], sm[3][32];

    int blk = blockIdx.x;
    int b = blk >> 7;
    int l0 = (blk & 127) << 5;
    int tid = threadIdx.x;

    if (tid < 96) {
        int k = tid / 32, li = tid % 32;
        int l = l0 + li;
        float o  = off[((size_t)(b * 3 + k)) * LL + l];
        float p  = fminf(fmaxf((float)l + o, 0.0f), 4095.0f);
        int fp   = (int)floorf(p);
        int cp   = min(fp + 1, 4095);
        sfp[k][li] = fp; scp[k][li] = cp;
        sal[k][li] = p - (float)fp;
        sm [k][li] = msk[((size_t)(b * 3 + k)) * LL + l];
    }
    __syncthreads();

    for (int e = tid; e < 4096; e += 256) {
        int li = e >> 7, c = e & 127;
        float acc = 0.0f;
#pragma unroll
        for (int k = 0; k < 3; k++) {
            float a  = sal[k][li];
            float xf = xt[((size_t)(b << 12) + sfp[k][li]) * CC + c];
            float xc = xt[((size_t)(b << 12) + scp[k][li]) * CC + c];
            acc += (xf * (1.0f - a) + xc * a) * sm[k][li];
        }
        s[c][li] = acc;
    }
    __syncthreads();
    for (int e = tid; e < 4096; e += 256) {
        int c = e >> 5, li = e & 31;
        size_t idx = (size_t)b * (CC * LL) + (size_t)c * LL + l0 + li;
        __nv_bfloat16 hb, lb; split1(s[c][li], hb, lb);
        ohi[idx] = hb; olo[idx] = lb;
    }
}

// ---------------------------------------------------------------------------
// Host launch
// ---------------------------------------------------------------------------
extern "C" void kernel_launch(void* const* d_in, const int* in_sizes, int n_in,
                              void* d_out, int out_size) {
    const float* xt    = (const float*)d_in[0];
    const float* hx    = (const float*)d_in[1];
    const float* cx    = (const float*)d_in[2];
    const float* red_w = (const float*)d_in[3];
    const float* red_b = (const float*)d_in[4];
    const float* n1g   = (const float*)d_in[5];
    const float* n1b   = (const float*)d_in[6];
    const float* qkvw  = (const float*)d_in[7];
    const float* qkvb  = (const float*)d_in[8];
    const float* rp    = (const float*)d_in[9];
    const float* pw    = (const float*)d_in[10];
    const float* pb    = (const float*)d_in[11];
    const float* n2g   = (const float*)d_in[12];
    const float* n2b   = (const float*)d_in[13];
    const float* f1w   = (const float*)d_in[14];
    const float* f1b   = (const float*)d_in[15];
    const float* f2w   = (const float*)d_in[16];
    const float* f2b   = (const float*)d_in[17];
    const float* off_w = (const float*)d_in[18];
    const float* off_b = (const float*)d_in[19];
    const float* msk_w = (const float*)d_in[20];
    const float* msk_b = (const float*)d_in[21];
    const float* lf_w  = (const float*)d_in[22];
    const float* lf_b  = (const float*)d_in[23];
    const float* gf_w  = (const float*)d_in[24];
    const float* gf_b  = (const float*)d_in[25];
    const float* ff_w  = (const float*)d_in[26];
    const float* ff_b  = (const float*)d_in[27];
    float* hy = (float*)d_out;

    float *pg, *pqkv, *poff, *pmsk;
    cudaGetSymbolAddress((void**)&pg,   g_buf);
    cudaGetSymbolAddress((void**)&pqkv, g_qkv);
    cudaGetSymbolAddress((void**)&poff, g_off);
    cudaGetSymbolAddress((void**)&pmsk, g_msk);

    __nv_bfloat16 *Ah, *Al, *Bh, *Bl, *Ch, *Cl;
    cudaGetSymbolAddress((void**)&Ah, g_Ah);
    cudaGetSymbolAddress((void**)&Al, g_Al);
    cudaGetSymbolAddress((void**)&Bh, g_Bh);
    cudaGetSymbolAddress((void**)&Bl, g_Bl);
    cudaGetSymbolAddress((void**)&Ch, g_Ch);
    cudaGetSymbolAddress((void**)&Cl, g_Cl);

    __nv_bfloat16 *redh, *redl, *qkvh, *qkvl, *pwh, *pwl, *f1h, *f1l, *f2h, *f2l;
    __nv_bfloat16 *lfh, *lfl, *gfh, *gfl, *ffh, *ffl;
    cudaGetSymbolAddress((void**)&redh, w_red_h);
    cudaGetSymbolAddress((void**)&redl, w_red_l);
    cudaGetSymbolAddress((void**)&qkvh, w_qkv_h);
    cudaGetSymbolAddress((void**)&qkvl, w_qkv_l);
    cudaGetSymbolAddress((void**)&pwh,  w_pw_h);
    cudaGetSymbolAddress((void**)&pwl,  w_pw_l);
    cudaGetSymbolAddress((void**)&f1h,  w_f1_h);
    cudaGetSymbolAddress((void**)&f1l,  w_f1_l);
    cudaGetSymbolAddress((void**)&f2h,  w_f2_h);
    cudaGetSymbolAddress((void**)&f2l,  w_f2_l);
    cudaGetSymbolAddress((void**)&lfh,  w_lf_h);
    cudaGetSymbolAddress((void**)&lfl,  w_lf_l);
    cudaGetSymbolAddress((void**)&gfh,  w_gf_h);
    cudaGetSymbolAddress((void**)&gfl,  w_gf_l);
    cudaGetSymbolAddress((void**)&ffh,  w_ff_h);
    cudaGetSymbolAddress((void**)&ffl,  w_ff_l);

    cudaFuncSetAttribute(gemm_mma<EpiBias>,    cudaFuncAttributeMaxDynamicSharedMemorySize, GEMM_SMEM);
    cudaFuncSetAttribute(gemm_mma<EpiGeluHL>,  cudaFuncAttributeMaxDynamicSharedMemorySize, GEMM_SMEM);
    cudaFuncSetAttribute(gemm_mma<EpiProj>,    cudaFuncAttributeMaxDynamicSharedMemorySize, GEMM_SMEM);
    cudaFuncSetAttribute(gemm_mma<EpiResid>,   cudaFuncAttributeMaxDynamicSharedMemorySize, GEMM_SMEM);
    cudaFuncSetAttribute(gemm_mma<EpiResidHL>, cudaFuncAttributeMaxDynamicSharedMemorySize, GEMM_SMEM);
    cudaFuncSetAttribute(gemm_mma<EpiLSTM>,    cudaFuncAttributeMaxDynamicSharedMemorySize, GEMM_SMEM);
    cudaFuncSetAttribute(gemm_lfgf,            cudaFuncAttributeMaxDynamicSharedMemorySize, GEMM_SMEM);
    cudaFuncSetAttribute(attn_kernel,          cudaFuncAttributeMaxDynamicSharedMemorySize, ATTN_SMEM);

    const dim3 blk256(256);

    // 0) all weight splits in one launch
    {
        WJobs js; int off = 0, n = 0;
        auto add = [&](const float* s, __nv_bfloat16* h, __nv_bfloat16* l, int K, int N) {
            js.j[n++] = WJob{s, h, l, K, N, off};
            off += K * N;
        };
        add(red_w, redh, redl, 256, 128);
        for (int i = 0; i < 2; i++) {
            add(qkvw + (size_t)i*128*384, qkvh + (size_t)i*384*128, qkvl + (size_t)i*384*128, 128, 384);
            add(pw   + (size_t)i*128*128, pwh  + (size_t)i*128*128, pwl  + (size_t)i*128*128, 128, 128);
            add(f1w  + (size_t)i*128*512, f1h  + (size_t)i*512*128, f1l  + (size_t)i*512*128, 128, 512);
            add(f2w  + (size_t)i*512*128, f2h  + (size_t)i*128*512, f2l  + (size_t)i*128*512, 512, 128);
        }
        add(lf_w, lfh, lfl, 128, 128);
        add(gf_w, gfh, gfl, 128, 128);
        add(ff_w, ffh, ffl, 128, 128);
        js.total = off;
        wsplit_all<<<(off + 255) / 256, blk256>>>(js);
    }

    const dim3 gN1(1, MROWS / 128), gN3(3, MROWS / 128), gN4(4, MROWS / 128);

    // 1) g = concat(xt, hx) @ red_w + red_b
    cvtcat_kernel<<<MROWS * 128 / 256, blk256>>>(xt, hx, Ah, Al);
    gemm_mma<<<gN1, blk256, GEMM_SMEM>>>(Ah, Al, redh, redl, 256, 128,
                                         EpiBias{pg, red_b});

    // 2) two Swin blocks
    for (int i = 0; i < 2; i++) {
        int shift = (i == 0) ? 0 : 4;
        const float* qkvb_i = qkvb + (size_t)i * 384;
        const float* rp_i   = rp   + (size_t)i * 225 * NHEAD;
        const float* pb_i   = pb   + (size_t)i * 128;
        const float* f1b_i  = f1b  + (size_t)i * 512;
        const float* f2b_i  = f2b  + (size_t)i * 128;

        ln_part_kernel<<<MROWS / 8, blk256>>>(pg, n1g + i * CC, n1b + i * CC, Ah, Al, shift);
        gemm_mma<<<gN3, blk256, GEMM_SMEM>>>(Ah, Al,
                                             qkvh + (size_t)i*384*128, qkvl + (size_t)i*384*128,
                                             128, 384, EpiBias{pqkv, qkvb_i});
        attn_kernel<<<BB * 64, blk256, ATTN_SMEM>>>(pqkv, rp_i, Ah, Al, shift);
        gemm_mma<<<gN1, blk256, GEMM_SMEM>>>(Ah, Al,
                                             pwh + (size_t)i*128*128, pwl + (size_t)i*128*128,
                                             128, 128, EpiProj{pg, pb_i, shift});
        ln_plain_kernel<<<MROWS / 8, blk256>>>(pg, n2g + i * CC, n2b + i * CC, Ah, Al);
        gemm_mma<<<gN4, blk256, GEMM_SMEM>>>(Ah, Al,
                                             f1h + (size_t)i*512*128, f1l + (size_t)i*512*128,
                                             128, 512, EpiGeluHL{Bh, Bl, f1b_i});
        if (i == 0)
            gemm_mma<<<gN1, blk256, GEMM_SMEM>>>(Bh, Bl,
                                                 f2h, f2l,
                                                 512, 128, EpiResid{pg, pg, f2b_i});
        else
            gemm_mma<<<gN1, blk256, GEMM_SMEM>>>(Bh, Bl,
                                                 f2h + (size_t)1*128*512, f2l + (size_t)1*128*512,
                                                 512, 128, EpiResidHL{Ch, Cl, pg, f2b_i});
    }

    // 3) local branch -> Ah/Al
    offmask_kernel<<<MROWS / 8, blk256>>>(xt, off_w, off_b, msk_w, msk_b, poff, pmsk);
    deform_kernel<<<BB * (LL / 32), blk256>>>(xt, poff, pmsk, Ah, Al);

    // 4) fused lf/gf GEMMs + mul + relu -> Bh/Bl ; then ff GEMM + LSTM gate
    gemm_lfgf<<<gN1, blk256, GEMM_SMEM>>>(Ah, Al, lfh, lfl,
                                          Ch, Cl, gfh, gfl,
                                          lf_b, gf_b, Bh, Bl);
    gemm_mma<<<gN1, blk256, GEMM_SMEM>>>(Bh, Bl, ffh, ffl, 128, 128,
                                         EpiLSTM{hy, cx, ff_b});
}

// round 9
// speedup vs baseline: 2.6635x; 1.9839x over previous
#include <cuda_runtime.h>
#include <cuda_fp16.h>
#include <math.h>
#include <stdint.h>

// ---------------------------------------------------------------------------
// Problem constants
// ---------------------------------------------------------------------------
#define BB   8
#define LL   4096
#define CC   128
#define MROWS (BB*LL)      // 32768
#define SCALE_Q 0.17677669529663687f

// ---------------------------------------------------------------------------
// Scratch (device globals — no allocation allowed)
// ---------------------------------------------------------------------------
__device__ float g_buf  [MROWS * CC];        // fp32 running state g
__device__ float g_qkv  [MROWS * 3 * CC];    // qkv fp32; later reused as t1
__device__ float g_off  [BB * 3 * LL];
__device__ float g_msk  [BB * 3 * LL];

// fp16 activation buffers
__device__ __align__(256) __half g_A16[MROWS * 256];   // A operand (<=K256)
__device__ __align__(256) __half g_B16[MROWS * 512];   // FFN hidden (<=K512)
__device__ __align__(256) __half g_C16[MROWS * 128];   // g (fp16 copy)

// split + transposed weights, fp16 hi/lo [N][K]
__device__ __align__(256) __half w_red_h[128*256],  w_red_l[128*256];
__device__ __align__(256) __half w_qkv_h[2][384*128], w_qkv_l[2][384*128];
__device__ __align__(256) __half w_pw_h [2][128*128], w_pw_l [2][128*128];
__device__ __align__(256) __half w_f1_h [2][512*128], w_f1_l [2][512*128];
__device__ __align__(256) __half w_f2_h [2][128*512], w_f2_l [2][128*512];
__device__ __align__(256) __half w_lf_h[128*128], w_lf_l[128*128];
__device__ __align__(256) __half w_gf_h[128*128], w_gf_l[128*128];
__device__ __align__(256) __half w_ff_h[128*128], w_ff_l[128*128];

// ---------------------------------------------------------------------------
// helpers
// ---------------------------------------------------------------------------
__device__ __forceinline__ uint32_t smem_u32(const void* p) {
    uint32_t a;
    asm("{ .reg .u64 t; cvta.to.shared.u64 t, %1; cvt.u32.u64 %0, t; }"
        : "=r"(a) : "l"(p));
    return a;
}
__device__ __forceinline__ void cp16(uint32_t s, const void* g) {
    asm volatile("cp.async.cg.shared.global [%0], [%1], 16;" :: "r"(s), "l"(g));
}
__device__ __forceinline__ void wsplit1(float v, __half& h, __half& l) {
    h = __float2half(v);
    l = __float2half(v - __half2float(h));
}
__device__ __forceinline__ uint32_t pack2h(float a, float b) {
    __half2 p = __floats2half2_rn(a, b);
    return *(uint32_t*)&p;
}

#define LDSM4(r, a) \
    asm volatile("ldmatrix.sync.aligned.m8n8.x4.shared.b16 {%0,%1,%2,%3}, [%4];" \
        : "=r"((r)[0]), "=r"((r)[1]), "=r"((r)[2]), "=r"((r)[3]) : "r"(a))

#define MMA16816(d, a, b0, b1) \
    asm volatile("mma.sync.aligned.m16n8k16.row.col.f32.f16.f16.f32 " \
        "{%0,%1,%2,%3}, {%4,%5,%6,%7}, {%8,%9}, {%0,%1,%2,%3};" \
        : "+f"((d)[0]), "+f"((d)[1]), "+f"((d)[2]), "+f"((d)[3]) \
        : "r"((a)[0]), "r"((a)[1]), "r"((a)[2]), "r"((a)[3]), "r"(b0), "r"(b1))

// ---------------------------------------------------------------------------
// Epilogues: ep(m, n0, N, float4) with n0 % 4 == 0, coalesced across threads
// ---------------------------------------------------------------------------
struct EpiBias {
    float* out; const float* bias;
    __device__ __forceinline__ void operator()(int m, int n0, int N, float4 v) const {
        const float4 b = *(const float4*)&bias[n0];
        v.x += b.x; v.y += b.y; v.z += b.z; v.w += b.w;
        *(float4*)&out[(size_t)m * N + n0] = v;
    }
};
struct EpiGeluH {
    __half* out; const float* bias;
    __device__ __forceinline__ void operator()(int m, int n0, int N, float4 v) const {
        const float4 b = *(const float4*)&bias[n0];
        float g[4] = {v.x + b.x, v.y + b.y, v.z + b.z, v.w + b.w};
#pragma unroll
        for (int k = 0; k < 4; k++)
            g[k] = 0.5f * g[k] * (1.0f + erff(g[k] * 0.7071067811865476f));
        uint2 o; o.x = pack2h(g[0], g[1]); o.y = pack2h(g[2], g[3]);
        *(uint2*)&out[(size_t)m * N + n0] = o;
    }
};
struct EpiResid {   // out = res + acc + bias (fp32)
    float* out; const float* res; const float* bias;
    __device__ __forceinline__ void operator()(int m, int n0, int N, float4 v) const {
        size_t i = (size_t)m * N + n0;
        const float4 b = *(const float4*)&bias[n0];
        const float4 r = *(const float4*)&res[i];
        v.x += b.x + r.x; v.y += b.y + r.y; v.z += b.z + r.z; v.w += b.w + r.w;
        *(float4*)&out[i] = v;
    }
};
struct EpiResidH {  // (res + acc + bias) -> fp16
    __half* out; const float* res; const float* bias;
    __device__ __forceinline__ void operator()(int m, int n0, int N, float4 v) const {
        size_t i = (size_t)m * N + n0;
        const float4 b = *(const float4*)&bias[n0];
        const float4 r = *(const float4*)&res[i];
        uint2 o;
        o.x = pack2h(v.x + b.x + r.x, v.y + b.y + r.y);
        o.y = pack2h(v.z + b.z + r.z, v.w + b.w + r.w);
        *(uint2*)&out[i] = o;
    }
};
struct EpiProj {   // window-reverse + unroll(+shift) + residual RMW into out
    float* out; const float* bias; int shift;
    __device__ __forceinline__ void operator()(int m, int n0, int N, float4 v) const {
        int b    = m >> 12;
        int rb   = m & 4095;
        int widx = rb >> 6;
        int tok  = rb & 63;
        int hh = ((widx >> 3) << 3) + (tok >> 3);
        int ww = ((widx & 7) << 3) + (tok & 7);
        int h = (hh + shift) & 63;
        int w = (ww + shift) & 63;
        size_t dst = ((size_t)(b << 12) + (h << 6) + w) * CC + n0;
        const float4 bi = *(const float4*)&bias[n0];
        float4 o = *(const float4*)&out[dst];
        o.x += v.x + bi.x; o.y += v.y + bi.y; o.z += v.z + bi.z; o.w += v.w + bi.w;
        *(float4*)&out[dst] = o;
    }
};
struct EpiMulReluH {
    __half* out; const float* t1; const float* bias;
    __device__ __forceinline__ void operator()(int m, int n0, int N, float4 v) const {
        size_t i = (size_t)m * N + n0;
        const float4 b = *(const float4*)&bias[n0];
        const float4 t = *(const float4*)&t1[i];
        float g[4] = {fmaxf(0.0f, t.x * (v.x + b.x)), fmaxf(0.0f, t.y * (v.y + b.y)),
                      fmaxf(0.0f, t.z * (v.z + b.z)), fmaxf(0.0f, t.w * (v.w + b.w))};
        uint2 o; o.x = pack2h(g[0], g[1]); o.y = pack2h(g[2], g[3]);
        *(uint2*)&out[i] = o;
    }
};
struct EpiLSTM {
    float* hy; const float* cx; const float* bias;
    __device__ __forceinline__ void operator()(int m, int n0, int N, float4 v) const {
        size_t i = (size_t)m * N + n0;
        const float4 b = *(const float4*)&bias[n0];
        const float4 c = *(const float4*)&cx[i];
        float f[4] = {v.x + b.x, v.y + b.y, v.z + b.z, v.w + b.w};
        float cc[4] = {c.x, c.y, c.z, c.w};
        float o[4];
#pragma unroll
        for (int k = 0; k < 4; k++) {
            float gate = 1.0f / (1.0f + expf(-f[k]));
            float cell = tanhf(f[k]);
            float cy   = gate * (cc[k] + cell);
            o[k] = gate * tanhf(cy);
        }
        *(float4*)&hy[i] = *(float4*)o;
    }
};

// ---------------------------------------------------------------------------
// fp16 2-pass GEMM on mma.sync (m16n8k16): D = A @ (Wh + Wl).
// CTA tile 256x128, 16 warps (8 m x 2 n), K-chunk 32, double-buffered cp.async.
// ---------------------------------------------------------------------------
#define TSTRIDE 80
#define A_BYTES 20480     // 256 rows * 80
#define B_BYTES 10240     // 128 rows * 80
#define STAGE_B 40960
#define GEMM_SMEM 81920
#define SOUT_STRIDE 132

__device__ __forceinline__ void mma_mainloop(
    const __half* __restrict__ A,
    const __half* __restrict__ Wh, const __half* __restrict__ Wl,
    int K, int bm, int bn, uint32_t sb, int tid, float acc[2][8][4])
{
    const int wid = tid >> 5, lane = tid & 31;
    const int mw = wid & 7, nw = wid >> 3;
    const int nch = K >> 5;

    auto load_stage = [&](int i) {
        uint32_t st = sb + (uint32_t)(i & 1) * STAGE_B;
        int kt = i << 5;
        int r = tid >> 2, q = tid & 3;
        uint32_t so = (uint32_t)r * TSTRIDE + q * 16;
        cp16(st + so,                       A  + (size_t)(bm + r) * K + kt + q * 8);
        cp16(st + 128u * TSTRIDE + so,      A  + (size_t)(bm + r + 128) * K + kt + q * 8);
        cp16(st + A_BYTES + so,             Wh + (size_t)(bn + r) * K + kt + q * 8);
        cp16(st + A_BYTES + B_BYTES + so,   Wl + (size_t)(bn + r) * K + kt + q * 8);
        asm volatile("cp.async.commit_group;");
    };

    load_stage(0);
    for (int i = 0; i < nch; i++) {
        if (i + 1 < nch) {
            load_stage(i + 1);
            asm volatile("cp.async.wait_group 1;");
        } else {
            asm volatile("cp.async.wait_group 0;");
        }
        __syncthreads();

        uint32_t st = sb + (uint32_t)(i & 1) * STAGE_B;
#pragma unroll
        for (int j = 0; j < 2; j++) {
            uint32_t a[2][4], bh[4][4], bl[4][4];
#pragma unroll
            for (int mt = 0; mt < 2; mt++) {
                uint32_t addr = st +
                    (uint32_t)((mw << 5) + (mt << 4) + (lane & 15)) * TSTRIDE +
                    (j << 5) + ((lane >> 4) << 4);
                LDSM4(a[mt], addr);
            }
#pragma unroll
            for (int nb = 0; nb < 4; nb++) {
                uint32_t addr = st + A_BYTES +
                    (uint32_t)((nw << 6) + (nb << 4) + (lane & 7) + ((lane >> 4) << 3)) * TSTRIDE +
                    (j << 5) + (((lane >> 3) & 1) << 4);
                LDSM4(bh[nb], addr);
                LDSM4(bl[nb], addr + B_BYTES);
            }
#pragma unroll
            for (int mt = 0; mt < 2; mt++)
#pragma unroll
                for (int nt = 0; nt < 8; nt++) {
                    float* d = acc[mt][nt];
                    MMA16816(d, a[mt], bh[nt >> 1][(nt & 1) * 2], bh[nt >> 1][(nt & 1) * 2 + 1]);
                    MMA16816(d, a[mt], bl[nt >> 1][(nt & 1) * 2], bl[nt >> 1][(nt & 1) * 2 + 1]);
                }
        }
        __syncthreads();
    }
}

template <class EP>
__global__ __launch_bounds__(512, 1)
void gemm_mma(const __half* __restrict__ A,
              const __half* __restrict__ Wh, const __half* __restrict__ Wl,
              int K, int Nfull, EP ep) {
    extern __shared__ char sm[];
    const int tid  = threadIdx.x;
    const int wid  = tid >> 5;
    const int lane = tid & 31;
    const int mw = wid & 7, nw = wid >> 3;
    const int bm = blockIdx.y * 256;
    const int bn = blockIdx.x * 128;
    const uint32_t sb = smem_u32(sm);

    float acc[2][8][4];
#pragma unroll
    for (int a = 0; a < 2; a++)
#pragma unroll
        for (int b = 0; b < 8; b++)
#pragma unroll
            for (int c = 0; c < 4; c++) acc[a][b][c] = 0.0f;

    mma_mainloop(A, Wh, Wl, K, bm, bn, sb, tid, acc);

    float* sout = (float*)sm;
#pragma unroll
    for (int rd = 0; rd < 2; rd++) {
        if ((mw >> 2) == rd) {
            const int mb = (mw & 3) << 5, nb = nw << 6;
#pragma unroll
            for (int mt = 0; mt < 2; mt++)
#pragma unroll
                for (int nt = 0; nt < 8; nt++)
#pragma unroll
                    for (int rg = 0; rg < 4; rg++) {
                        int ml = mb + (mt << 4) + (lane >> 2) + ((rg >> 1) << 3);
                        int nl = nb + (nt << 3) + ((lane & 3) << 1) + (rg & 1);
                        sout[ml * SOUT_STRIDE + nl] = acc[mt][nt][rg];
                    }
        }
        __syncthreads();
#pragma unroll 2
        for (int e = tid; e < 4096; e += 512) {
            int r = e >> 5, c4 = (e & 31) << 2;
            float4 v = *(float4*)&sout[r * SOUT_STRIDE + c4];
            ep(bm + (rd << 7) + r, bn + c4, Nfull, v);
        }
        __syncthreads();
    }
}

// ---------------------------------------------------------------------------
// Combined weight transpose + fp16 hi/lo split: 12 jobs in one launch
// ---------------------------------------------------------------------------
struct WJob { const float* src; __half* hi; __half* lo; int K, N, start; };
struct WJobs { WJob j[12]; int total; };

__global__ void wsplit_all(WJobs js) {
    int idx = blockIdx.x * 256 + threadIdx.x;
    if (idx >= js.total) return;
    int jj = 0;
#pragma unroll
    for (int t = 1; t < 12; t++) if (idx >= js.j[t].start) jj = t;
    const WJob J = js.j[jj];
    int local = idx - J.start;
    int k = local / J.N, n = local - k * J.N;
    __half h, l; wsplit1(J.src[local], h, l);
    J.hi[(size_t)n * J.K + k] = h;
    J.lo[(size_t)n * J.K + k] = l;
}

// concat(xt,hx) -> A16 [M][256]
__global__ void cvtcat_kernel(const float* __restrict__ x, const float* __restrict__ hsrc,
                              __half* __restrict__ o) {
    int i = blockIdx.x * 256 + threadIdx.x;
    int m = i >> 7, k = i & 127;
    o[(size_t)m * 256 + k]       = __float2half(x[i]);
    o[(size_t)m * 256 + 128 + k] = __float2half(hsrc[i]);
}

// ---------------------------------------------------------------------------
// LayerNorm + (roll) + window partition -> fp16 [M][128]
// ---------------------------------------------------------------------------
__global__ void ln_part_kernel(const float* __restrict__ x,
                               const float* __restrict__ gm,
                               const float* __restrict__ bt,
                               __half* __restrict__ out, int shift) {
    int warp = blockIdx.x * 8 + (threadIdx.x >> 5);
    int lane = threadIdx.x & 31;
    int wi = warp >> 6, tok = warp & 63;
    int b = wi >> 6, widx = wi & 63;
    int hh = ((widx >> 3) << 3) + (tok >> 3);
    int ww = ((widx & 7) << 3) + (tok & 7);
    int h = (hh + shift) & 63;
    int w = (ww + shift) & 63;
    const float* row = x + ((size_t)(b << 12) + (h << 6) + w) * CC;

    float4 v = *(const float4*)&row[lane * 4];
    float sum = v.x + v.y + v.z + v.w;
    float sq  = v.x * v.x + v.y * v.y + v.z * v.z + v.w * v.w;
#pragma unroll
    for (int o = 16; o; o >>= 1) {
        sum += __shfl_xor_sync(0xffffffffu, sum, o);
        sq  += __shfl_xor_sync(0xffffffffu, sq, o);
    }
    float mean = sum * (1.0f / 128.0f);
    float var  = sq * (1.0f / 128.0f) - mean * mean;
    float rstd = rsqrtf(var + 1e-5f);
    const float4 g4 = *(const float4*)&gm[lane * 4];
    const float4 b4 = *(const float4*)&bt[lane * 4];
    uint2 o;
    o.x = pack2h((v.x - mean) * rstd * g4.x + b4.x, (v.y - mean) * rstd * g4.y + b4.y);
    o.y = pack2h((v.z - mean) * rstd * g4.z + b4.z, (v.w - mean) * rstd * g4.w + b4.w);
    *(uint2*)&out[(size_t)warp * CC + lane * 4] = o;
}

__global__ void ln_plain_kernel(const float* __restrict__ x,
                                const float* __restrict__ gm,
                                const float* __restrict__ bt,
                                __half* __restrict__ out) {
    int warp = blockIdx.x * 8 + (threadIdx.x >> 5);
    int lane = threadIdx.x & 31;
    const float* row = x + (size_t)warp * CC;
    float4 v = *(const float4*)&row[lane * 4];
    float sum = v.x + v.y + v.z + v.w;
    float sq  = v.x * v.x + v.y * v.y + v.z * v.z + v.w * v.w;
#pragma unroll
    for (int o = 16; o; o >>= 1) {
        sum += __shfl_xor_sync(0xffffffffu, sum, o);
        sq  += __shfl_xor_sync(0xffffffffu, sq, o);
    }
    float mean = sum * (1.0f / 128.0f);
    float var  = sq * (1.0f / 128.0f) - mean * mean;
    float rstd = rsqrtf(var + 1e-5f);
    const float4 g4 = *(const float4*)&gm[lane * 4];
    const float4 b4 = *(const float4*)&bt[lane * 4];
    uint2 o;
    o.x = pack2h((v.x - mean) * rstd * g4.x + b4.x, (v.y - mean) * rstd * g4.y + b4.y);
    o.y = pack2h((v.z - mean) * rstd * g4.z + b4.z, (v.w - mean) * rstd * g4.w + b4.w);
    *(uint2*)&out[(size_t)warp * CC + lane * 4] = o;
}

// ---------------------------------------------------------------------------
// Window attention -> fp16 output. Block = one window (256 thr = 4 heads x 64)
// ---------------------------------------------------------------------------
__device__ __forceinline__ int zone_(int h) { return h < 56 ? 0 : (h < 60 ? 1 : 2); }

#define ATTN_SMEM 69136   // kk 32KB + vv 32KB + rps 3600B

__global__ __launch_bounds__(256)
void attn_kernel(const float* __restrict__ qkv, const float* __restrict__ rp,
                 __half* __restrict__ out, int shift) {
    extern __shared__ float smf[];
    float* kk  = smf;
    float* vv  = smf + 8192;
    float* rps = smf + 16384;

    const int wi   = blockIdx.x;
    const int t    = threadIdx.x;
    const int head = t >> 6;
    const int row  = t & 63;
    const int base = wi * 64;

    for (int i = t; i < 900; i += 256) rps[i] = rp[i];
    for (int i = t; i < 8192; i += 256) {
        int m = i >> 7, c = i & 127;
        float kvk = qkv[(size_t)(base + m) * 384 + 128 + c];
        float kvv = qkv[(size_t)(base + m) * 384 + 256 + c];
        kk[((c >> 5) * 64 + m) * 32 + (c & 31)] = kvk;
        vv[((c >> 5) * 64 + m) * 32 + (c & 31)] = kvv;
    }
    __syncthreads();

    float q[32];
#pragma unroll
    for (int d4 = 0; d4 < 8; d4++) {
        float4 qq = *(const float4*)&qkv[(size_t)(base + row) * 384 + head * 32 + d4 * 4];
        q[d4*4+0] = qq.x * SCALE_Q; q[d4*4+1] = qq.y * SCALE_Q;
        q[d4*4+2] = qq.z * SCALE_Q; q[d4*4+3] = qq.w * SCALE_Q;
    }

    const int rn = row >> 3, cn = row & 7;
    const int widx = wi & 63;
    const int wh = widx >> 3, wwc = widx & 7;
    int zr_n = 0, zc_n = 0;
    if (shift) { zr_n = zone_(wh * 8 + rn); zc_n = zone_(wwc * 8 + cn); }

    const float* kh = kk + head * 2048;
    const float* vh = vv + head * 2048;

    float o[32];
#pragma unroll
    for (int d = 0; d < 32; d++) o[d] = 0.0f;
    float sum = 0.0f;

#pragma unroll 4
    for (int m = 0; m < 64; m++) {
        float a = 0.0f;
        const float* kr = kh + m * 32;
#pragma unroll
        for (int d4 = 0; d4 < 8; d4++) {
            float4 kv4 = *(const float4*)&kr[d4 * 4];
            a += q[d4*4+0] * kv4.x + q[d4*4+1] * kv4.y +
                 q[d4*4+2] * kv4.z + q[d4*4+3] * kv4.w;
        }
        int rm = m >> 3, cm = m & 7;
        int ridx = (rn - rm + 7) * 15 + (cn - cm + 7);
        a += rps[ridx * 4 + head];
        if (shift) {
            if (zone_(wh * 8 + rm) != zr_n || zone_(wwc * 8 + cm) != zc_n)
                a += -100.0f;
        }
        float p = __expf(a);
        sum += p;
        const float* vr = vh + m * 32;
#pragma unroll
        for (int d4 = 0; d4 < 8; d4++) {
            float4 vv4 = *(const float4*)&vr[d4 * 4];
            o[d4*4+0] += p * vv4.x; o[d4*4+1] += p * vv4.y;
            o[d4*4+2] += p * vv4.z; o[d4*4+3] += p * vv4.w;
        }
    }
    float inv = 1.0f / sum;
#pragma unroll
    for (int d4 = 0; d4 < 8; d4++) {
        uint2 ov;
        ov.x = pack2h(o[d4*4+0] * inv, o[d4*4+1] * inv);
        ov.y = pack2h(o[d4*4+2] * inv, o[d4*4+3] * inv);
        *(uint2*)&out[(size_t)(base + row) * CC + head * 32 + d4 * 4] = ov;
    }
}

// ---------------------------------------------------------------------------
// Conv1d offset + mask head
// ---------------------------------------------------------------------------
__global__ void offmask_kernel(const float* __restrict__ xt,
                               const float* __restrict__ offw, const float* __restrict__ offb,
                               const float* __restrict__ mskw, const float* __restrict__ mskb,
                               float* __restrict__ off, float* __restrict__ msk) {
    __shared__ float swo[1152], swm[1152];
    int tid = threadIdx.x;
    for (int i = tid; i < 1152; i += 256) { swo[i] = offw[i]; swm[i] = mskw[i]; }
    __syncthreads();

    int warp = tid >> 5, lane = tid & 31;
    int pos = blockIdx.x * 8 + warp;
    int b = pos >> 12, l = pos & 4095;

    float ao[3] = {0.f, 0.f, 0.f}, am[3] = {0.f, 0.f, 0.f};
#pragma unroll
    for (int i = 0; i < 4; i++) {
        int c = lane + 32 * i;
        float xv[3];
#pragma unroll
        for (int j = 0; j < 3; j++) {
            int ls = l + j - 1;
            xv[j] = (ls >= 0 && ls < LL)
                  ? xt[((size_t)(b << 12) + ls) * CC + c] : 0.0f;
        }
#pragma unroll
        for (int ko = 0; ko < 3; ko++)
#pragma unroll
            for (int j = 0; j < 3; j++) {
                ao[ko] += xv[j] * swo[ko * 384 + c * 3 + j];
                am[ko] += xv[j] * swm[ko * 384 + c * 3 + j];
            }
    }
#pragma unroll
    for (int o = 16; o; o >>= 1)
#pragma unroll
        for (int ko = 0; ko < 3; ko++) {
            ao[ko] += __shfl_xor_sync(0xffffffffu, ao[ko], o);
            am[ko] += __shfl_xor_sync(0xffffffffu, am[ko], o);
        }
    if (lane == 0) {
#pragma unroll
        for (int ko = 0; ko < 3; ko++) {
            float ov = ao[ko] + offb[ko];
            float mv = am[ko] + mskb[ko];
            off[((size_t)(b * 3 + ko)) * LL + l] = ov;
            msk[((size_t)(b * 3 + ko)) * LL + l] = 1.0f / (1.0f + expf(-mv));
        }
    }
}

// ---------------------------------------------------------------------------
// Deformable sample -> fp16 at flat (B,C,L) layout == (B,L,C) view
// ---------------------------------------------------------------------------
__global__ void deform_kernel(const float* __restrict__ xt,
                              const float* __restrict__ off,
                              const float* __restrict__ msk,
                              __half* __restrict__ out) {
    __shared__ float s[128][33];
    __shared__ int   sfp[3][32], scp[3][32];
    __shared__ float sal[3][32], sm[3][32];

    int blk = blockIdx.x;
    int b = blk >> 7;
    int l0 = (blk & 127) << 5;
    int tid = threadIdx.x;

    if (tid < 96) {
        int k = tid / 32, li = tid % 32;
        int l = l0 + li;
        float o  = off[((size_t)(b * 3 + k)) * LL + l];
        float p  = fminf(fmaxf((float)l + o, 0.0f), 4095.0f);
        int fp   = (int)floorf(p);
        int cp   = min(fp + 1, 4095);
        sfp[k][li] = fp; scp[k][li] = cp;
        sal[k][li] = p - (float)fp;
        sm [k][li] = msk[((size_t)(b * 3 + k)) * LL + l];
    }
    __syncthreads();

    for (int e = tid; e < 4096; e += 256) {
        int li = e >> 7, c = e & 127;
        float acc = 0.0f;
#pragma unroll
        for (int k = 0; k < 3; k++) {
            float a  = sal[k][li];
            float xf = xt[((size_t)(b << 12) + sfp[k][li]) * CC + c];
            float xc = xt[((size_t)(b << 12) + scp[k][li]) * CC + c];
            acc += (xf * (1.0f - a) + xc * a) * sm[k][li];
        }
        s[c][li] = acc;
    }
    __syncthreads();
    for (int e = tid; e < 4096; e += 256) {
        int c = e >> 5, li = e & 31;
        size_t idx = (size_t)b * (CC * LL) + (size_t)c * LL + l0 + li;
        out[idx] = __float2half(s[c][li]);
    }
}

// ---------------------------------------------------------------------------
// Host launch
// ---------------------------------------------------------------------------
extern "C" void kernel_launch(void* const* d_in, const int* in_sizes, int n_in,
                              void* d_out, int out_size) {
    const float* xt    = (const float*)d_in[0];
    const float* hx    = (const float*)d_in[1];
    const float* cx    = (const float*)d_in[2];
    const float* red_w = (const float*)d_in[3];
    const float* red_b = (const float*)d_in[4];
    const float* n1g   = (const float*)d_in[5];
    const float* n1b   = (const float*)d_in[6];
    const float* qkvw  = (const float*)d_in[7];
    const float* qkvb  = (const float*)d_in[8];
    const float* rp    = (const float*)d_in[9];
    const float* pw    = (const float*)d_in[10];
    const float* pb    = (const float*)d_in[11];
    const float* n2g   = (const float*)d_in[12];
    const float* n2b   = (const float*)d_in[13];
    const float* f1w   = (const float*)d_in[14];
    const float* f1b   = (const float*)d_in[15];
    const float* f2w   = (const float*)d_in[16];
    const float* f2b   = (const float*)d_in[17];
    const float* off_w = (const float*)d_in[18];
    const float* off_b = (const float*)d_in[19];
    const float* msk_w = (const float*)d_in[20];
    const float* msk_b = (const float*)d_in[21];
    const float* lf_w  = (const float*)d_in[22];
    const float* lf_b  = (const float*)d_in[23];
    const float* gf_w  = (const float*)d_in[24];
    const float* gf_b  = (const float*)d_in[25];
    const float* ff_w  = (const float*)d_in[26];
    const float* ff_b  = (const float*)d_in[27];
    float* hy = (float*)d_out;

    float *pg, *pqkv, *poff, *pmsk;
    cudaGetSymbolAddress((void**)&pg,   g_buf);
    cudaGetSymbolAddress((void**)&pqkv, g_qkv);
    cudaGetSymbolAddress((void**)&poff, g_off);
    cudaGetSymbolAddress((void**)&pmsk, g_msk);
    float* pt1 = pqkv;   // reuse qkv scratch as t1 in phase 4

    __half *A16, *B16, *C16;
    cudaGetSymbolAddress((void**)&A16, g_A16);
    cudaGetSymbolAddress((void**)&B16, g_B16);
    cudaGetSymbolAddress((void**)&C16, g_C16);

    __half *redh, *redl, *qkvh, *qkvl, *pwh, *pwl, *f1h, *f1l, *f2h, *f2l;
    __half *lfh, *lfl, *gfh, *gfl, *ffh, *ffl;
    cudaGetSymbolAddress((void**)&redh, w_red_h);
    cudaGetSymbolAddress((void**)&redl, w_red_l);
    cudaGetSymbolAddress((void**)&qkvh, w_qkv_h);
    cudaGetSymbolAddress((void**)&qkvl, w_qkv_l);
    cudaGetSymbolAddress((void**)&pwh,  w_pw_h);
    cudaGetSymbolAddress((void**)&pwl,  w_pw_l);
    cudaGetSymbolAddress((void**)&f1h,  w_f1_h);
    cudaGetSymbolAddress((void**)&f1l,  w_f1_l);
    cudaGetSymbolAddress((void**)&f2h,  w_f2_h);
    cudaGetSymbolAddress((void**)&f2l,  w_f2_l);
    cudaGetSymbolAddress((void**)&lfh,  w_lf_h);
    cudaGetSymbolAddress((void**)&lfl,  w_lf_l);
    cudaGetSymbolAddress((void**)&gfh,  w_gf_h);
    cudaGetSymbolAddress((void**)&gfl,  w_gf_l);
    cudaGetSymbolAddress((void**)&ffh,  w_ff_h);
    cudaGetSymbolAddress((void**)&ffl,  w_ff_l);

    cudaFuncSetAttribute(gemm_mma<EpiBias>,     cudaFuncAttributeMaxDynamicSharedMemorySize, GEMM_SMEM);
    cudaFuncSetAttribute(gemm_mma<EpiGeluH>,    cudaFuncAttributeMaxDynamicSharedMemorySize, GEMM_SMEM);
    cudaFuncSetAttribute(gemm_mma<EpiProj>,     cudaFuncAttributeMaxDynamicSharedMemorySize, GEMM_SMEM);
    cudaFuncSetAttribute(gemm_mma<EpiResid>,    cudaFuncAttributeMaxDynamicSharedMemorySize, GEMM_SMEM);
    cudaFuncSetAttribute(gemm_mma<EpiResidH>,   cudaFuncAttributeMaxDynamicSharedMemorySize, GEMM_SMEM);
    cudaFuncSetAttribute(gemm_mma<EpiMulReluH>, cudaFuncAttributeMaxDynamicSharedMemorySize, GEMM_SMEM);
    cudaFuncSetAttribute(gemm_mma<EpiLSTM>,     cudaFuncAttributeMaxDynamicSharedMemorySize, GEMM_SMEM);
    cudaFuncSetAttribute(attn_kernel,           cudaFuncAttributeMaxDynamicSharedMemorySize, ATTN_SMEM);

    const dim3 blk256(256), blk512(512);

    // 0) all weight splits in one launch
    {
        WJobs js; int off = 0, n = 0;
        auto add = [&](const float* s, __half* h, __half* l, int K, int N) {
            js.j[n++] = WJob{s, h, l, K, N, off};
            off += K * N;
        };
        add(red_w, redh, redl, 256, 128);
        for (int i = 0; i < 2; i++) {
            add(qkvw + (size_t)i*128*384, qkvh + (size_t)i*384*128, qkvl + (size_t)i*384*128, 128, 384);
            add(pw   + (size_t)i*128*128, pwh  + (size_t)i*128*128, pwl  + (size_t)i*128*128, 128, 128);
            add(f1w  + (size_t)i*128*512, f1h  + (size_t)i*512*128, f1l  + (size_t)i*512*128, 128, 512);
            add(f2w  + (size_t)i*512*128, f2h  + (size_t)i*128*512, f2l  + (size_t)i*128*512, 512, 128);
        }
        add(lf_w, lfh, lfl, 128, 128);
        add(gf_w, gfh, gfl, 128, 128);
        add(ff_w, ffh, ffl, 128, 128);
        js.total = off;
        wsplit_all<<<(off + 255) / 256, blk256>>>(js);
    }

    const dim3 gN1(1, 128), gN3(3, 128), gN4(4, 128);

    // 1) g = concat(xt, hx) @ red_w + red_b
    cvtcat_kernel<<<MROWS * 128 / 256, blk256>>>(xt, hx, A16);
    gemm_mma<<<gN1, blk512, GEMM_SMEM>>>(A16, redh, redl, 256, 128,
                                         EpiBias{pg, red_b});

    // 2) two Swin blocks
    for (int i = 0; i < 2; i++) {
        int shift = (i == 0) ? 0 : 4;
        const float* qkvb_i = qkvb + (size_t)i * 384;
        const float* rp_i   = rp   + (size_t)i * 225 * 4;
        const float* pb_i   = pb   + (size_t)i * 128;
        const float* f1b_i  = f1b  + (size_t)i * 512;
        const float* f2b_i  = f2b  + (size_t)i * 128;

        ln_part_kernel<<<MROWS / 8, blk256>>>(pg, n1g + i * CC, n1b + i * CC, A16, shift);
        gemm_mma<<<gN3, blk512, GEMM_SMEM>>>(A16,
                                             qkvh + (size_t)i*384*128, qkvl + (size_t)i*384*128,
                                             128, 384, EpiBias{pqkv, qkvb_i});
        attn_kernel<<<BB * 64, blk256, ATTN_SMEM>>>(pqkv, rp_i, A16, shift);
        gemm_mma<<<gN1, blk512, GEMM_SMEM>>>(A16,
                                             pwh + (size_t)i*128*128, pwl + (size_t)i*128*128,
                                             128, 128, EpiProj{pg, pb_i, shift});
        ln_plain_kernel<<<MROWS / 8, blk256>>>(pg, n2g + i * CC, n2b + i * CC, A16);
        gemm_mma<<<gN4, blk512, GEMM_SMEM>>>(A16,
                                             f1h + (size_t)i*512*128, f1l + (size_t)i*512*128,
                                             128, 512, EpiGeluH{B16, f1b_i});
        if (i == 0)
            gemm_mma<<<gN1, blk512, GEMM_SMEM>>>(B16, f2h, f2l,
                                                 512, 128, EpiResid{pg, pg, f2b_i});
        else
            gemm_mma<<<gN1, blk512, GEMM_SMEM>>>(B16,
                                                 f2h + (size_t)1*128*512, f2l + (size_t)1*128*512,
                                                 512, 128, EpiResidH{C16, pg, f2b_i});
    }

    // 3) local branch -> A16
    offmask_kernel<<<MROWS / 8, blk256>>>(xt, off_w, off_b, msk_w, msk_b, poff, pmsk);
    deform_kernel<<<BB * (LL / 32), blk256>>>(xt, poff, pmsk, A16);

    // 4) fusion + LSTM gating (t1 staged in g_qkv scratch)
    gemm_mma<<<gN1, blk512, GEMM_SMEM>>>(A16, lfh, lfl, 128, 128,
                                         EpiBias{pt1, lf_b});
    gemm_mma<<<gN1, blk512, GEMM_SMEM>>>(C16, gfh, gfl, 128, 128,
                                         EpiMulReluH{A16, pt1, gf_b});
    gemm_mma<<<gN1, blk512, GEMM_SMEM>>>(A16, ffh, ffl, 128, 128,
                                         EpiLSTM{hy, cx, ff_b});
}

// round 10
// speedup vs baseline: 3.2471x; 1.2191x over previous
#include <cuda_runtime.h>
#include <cuda_fp16.h>
#include <math.h>
#include <stdint.h>

// ---------------------------------------------------------------------------
// Problem constants
// ---------------------------------------------------------------------------
#define BB   8
#define LL   4096
#define CC   128
#define MROWS (BB*LL)      // 32768
#define SCALE_Q 0.17677669529663687f

// ---------------------------------------------------------------------------
// Scratch (device globals — no allocation allowed)
// ---------------------------------------------------------------------------
__device__ float g_buf  [MROWS * CC];        // fp32 running state g
__device__ float g_t1   [MROWS * CC];        // t1 in phase 4
__device__ float g_off  [BB * 3 * LL];
__device__ float g_msk  [BB * 3 * LL];

// fp16 activation buffers
__device__ __align__(256) __half g_A16[MROWS * 256];   // A operand (<=K256)
__device__ __align__(256) __half g_B16[MROWS * 512];   // qkv (384) / FFN hidden (512)
__device__ __align__(256) __half g_C16[MROWS * 128];   // g (fp16 copy)

// converted + transposed weights, fp16 [N][K]
__device__ __align__(256) __half w_red[128*256];
__device__ __align__(256) __half w_qkv[2][384*128];
__device__ __align__(256) __half w_pw [2][128*128];
__device__ __align__(256) __half w_f1 [2][512*128];
__device__ __align__(256) __half w_f2 [2][128*512];
__device__ __align__(256) __half w_lf[128*128];
__device__ __align__(256) __half w_gf[128*128];
__device__ __align__(256) __half w_ff[128*128];

// ---------------------------------------------------------------------------
// helpers
// ---------------------------------------------------------------------------
__device__ __forceinline__ uint32_t smem_u32(const void* p) {
    uint32_t a;
    asm("{ .reg .u64 t; cvta.to.shared.u64 t, %1; cvt.u32.u64 %0, t; }"
        : "=r"(a) : "l"(p));
    return a;
}
__device__ __forceinline__ void cp16(uint32_t s, const void* g) {
    asm volatile("cp.async.cg.shared.global [%0], [%1], 16;" :: "r"(s), "l"(g));
}
__device__ __forceinline__ uint32_t pack2h(float a, float b) {
    __half2 p = __floats2half2_rn(a, b);
    return *(uint32_t*)&p;
}

#define LDSM4(r, a) \
    asm volatile("ldmatrix.sync.aligned.m8n8.x4.shared.b16 {%0,%1,%2,%3}, [%4];" \
        : "=r"((r)[0]), "=r"((r)[1]), "=r"((r)[2]), "=r"((r)[3]) : "r"(a))

#define MMA16816(d, a, b0, b1) \
    asm volatile("mma.sync.aligned.m16n8k16.row.col.f32.f16.f16.f32 " \
        "{%0,%1,%2,%3}, {%4,%5,%6,%7}, {%8,%9}, {%0,%1,%2,%3};" \
        : "+f"((d)[0]), "+f"((d)[1]), "+f"((d)[2]), "+f"((d)[3]) \
        : "r"((a)[0]), "r"((a)[1]), "r"((a)[2]), "r"((a)[3]), "r"(b0), "r"(b1))

// ---------------------------------------------------------------------------
// Epilogues: ep(m, n0, N, float4) with n0 % 4 == 0, coalesced across threads
// ---------------------------------------------------------------------------
struct EpiBias {
    float* out; const float* bias;
    __device__ __forceinline__ void operator()(int m, int n0, int N, float4 v) const {
        const float4 b = *(const float4*)&bias[n0];
        v.x += b.x; v.y += b.y; v.z += b.z; v.w += b.w;
        *(float4*)&out[(size_t)m * N + n0] = v;
    }
};
struct EpiBiasH {     // acc + bias -> fp16
    __half* out; const float* bias;
    __device__ __forceinline__ void operator()(int m, int n0, int N, float4 v) const {
        const float4 b = *(const float4*)&bias[n0];
        uint2 o;
        o.x = pack2h(v.x + b.x, v.y + b.y);
        o.y = pack2h(v.z + b.z, v.w + b.w);
        *(uint2*)&out[(size_t)m * N + n0] = o;
    }
};
struct EpiGeluH {
    __half* out; const float* bias;
    __device__ __forceinline__ void operator()(int m, int n0, int N, float4 v) const {
        const float4 b = *(const float4*)&bias[n0];
        float g[4] = {v.x + b.x, v.y + b.y, v.z + b.z, v.w + b.w};
#pragma unroll
        for (int k = 0; k < 4; k++)
            g[k] = 0.5f * g[k] * (1.0f + erff(g[k] * 0.7071067811865476f));
        uint2 o; o.x = pack2h(g[0], g[1]); o.y = pack2h(g[2], g[3]);
        *(uint2*)&out[(size_t)m * N + n0] = o;
    }
};
struct EpiResid {   // out = res + acc + bias (fp32)
    float* out; const float* res; const float* bias;
    __device__ __forceinline__ void operator()(int m, int n0, int N, float4 v) const {
        size_t i = (size_t)m * N + n0;
        const float4 b = *(const float4*)&bias[n0];
        const float4 r = *(const float4*)&res[i];
        v.x += b.x + r.x; v.y += b.y + r.y; v.z += b.z + r.z; v.w += b.w + r.w;
        *(float4*)&out[i] = v;
    }
};
struct EpiResidH {  // (res + acc + bias) -> fp16
    __half* out; const float* res; const float* bias;
    __device__ __forceinline__ void operator()(int m, int n0, int N, float4 v) const {
        size_t i = (size_t)m * N + n0;
        const float4 b = *(const float4*)&bias[n0];
        const float4 r = *(const float4*)&res[i];
        uint2 o;
        o.x = pack2h(v.x + b.x + r.x, v.y + b.y + r.y);
        o.y = pack2h(v.z + b.z + r.z, v.w + b.w + r.w);
        *(uint2*)&out[i] = o;
    }
};
struct EpiProj {   // window-reverse + unroll(+shift) + residual RMW into out
    float* out; const float* bias; int shift;
    __device__ __forceinline__ void operator()(int m, int n0, int N, float4 v) const {
        int b    = m >> 12;
        int rb   = m & 4095;
        int widx = rb >> 6;
        int tok  = rb & 63;
        int hh = ((widx >> 3) << 3) + (tok >> 3);
        int ww = ((widx & 7) << 3) + (tok & 7);
        int h = (hh + shift) & 63;
        int w = (ww + shift) & 63;
        size_t dst = ((size_t)(b << 12) + (h << 6) + w) * CC + n0;
        const float4 bi = *(const float4*)&bias[n0];
        float4 o = *(const float4*)&out[dst];
        o.x += v.x + bi.x; o.y += v.y + bi.y; o.z += v.z + bi.z; o.w += v.w + bi.w;
        *(float4*)&out[dst] = o;
    }
};
struct EpiMulReluH {
    __half* out; const float* t1; const float* bias;
    __device__ __forceinline__ void operator()(int m, int n0, int N, float4 v) const {
        size_t i = (size_t)m * N + n0;
        const float4 b = *(const float4*)&bias[n0];
        const float4 t = *(const float4*)&t1[i];
        float g[4] = {fmaxf(0.0f, t.x * (v.x + b.x)), fmaxf(0.0f, t.y * (v.y + b.y)),
                      fmaxf(0.0f, t.z * (v.z + b.z)), fmaxf(0.0f, t.w * (v.w + b.w))};
        uint2 o; o.x = pack2h(g[0], g[1]); o.y = pack2h(g[2], g[3]);
        *(uint2*)&out[i] = o;
    }
};
struct EpiLSTM {
    float* hy; const float* cx; const float* bias;
    __device__ __forceinline__ void operator()(int m, int n0, int N, float4 v) const {
        size_t i = (size_t)m * N + n0;
        const float4 b = *(const float4*)&bias[n0];
        const float4 c = *(const float4*)&cx[i];
        float f[4] = {v.x + b.x, v.y + b.y, v.z + b.z, v.w + b.w};
        float cc[4] = {c.x, c.y, c.z, c.w};
        float o[4];
#pragma unroll
        for (int k = 0; k < 4; k++) {
            float gate = 1.0f / (1.0f + expf(-f[k]));
            float cell = tanhf(f[k]);
            float cy   = gate * (cc[k] + cell);
            o[k] = gate * tanhf(cy);
        }
        *(float4*)&hy[i] = *(float4*)o;
    }
};

// ---------------------------------------------------------------------------
// fp16 single-pass GEMM on mma.sync (m16n8k16): D = A @ W.
// CTA tile 256x128, 16 warps (8 m x 2 n), K-chunk 32, double-buffered cp.async.
// ---------------------------------------------------------------------------
#define TSTRIDE 80
#define A_BYTES 20480     // 256 rows * 80
#define B_BYTES 10240     // 128 rows * 80
#define STAGE_B 30720
#define GEMM_SMEM 67584   // max(2*STAGE_B=61440, sout 128*132*4=67584)
#define SOUT_STRIDE 132

__device__ __forceinline__ void mma_mainloop(
    const __half* __restrict__ A, const __half* __restrict__ W,
    int K, int bm, int bn, uint32_t sb, int tid, float acc[2][8][4])
{
    const int wid = tid >> 5, lane = tid & 31;
    const int mw = wid & 7, nw = wid >> 3;
    const int nch = K >> 5;

    auto load_stage = [&](int i) {
        uint32_t st = sb + (uint32_t)(i & 1) * STAGE_B;
        int kt = i << 5;
        int r = tid >> 2, q = tid & 3;
        uint32_t so = (uint32_t)r * TSTRIDE + q * 16;
        cp16(st + so,                  A + (size_t)(bm + r) * K + kt + q * 8);
        cp16(st + 128u * TSTRIDE + so, A + (size_t)(bm + r + 128) * K + kt + q * 8);
        cp16(st + A_BYTES + so,        W + (size_t)(bn + r) * K + kt + q * 8);
        asm volatile("cp.async.commit_group;");
    };

    load_stage(0);
    for (int i = 0; i < nch; i++) {
        if (i + 1 < nch) {
            load_stage(i + 1);
            asm volatile("cp.async.wait_group 1;");
        } else {
            asm volatile("cp.async.wait_group 0;");
        }
        __syncthreads();

        uint32_t st = sb + (uint32_t)(i & 1) * STAGE_B;
#pragma unroll
        for (int j = 0; j < 2; j++) {
            uint32_t a[2][4], bh[4][4];
#pragma unroll
            for (int mt = 0; mt < 2; mt++) {
                uint32_t addr = st +
                    (uint32_t)((mw << 5) + (mt << 4) + (lane & 15)) * TSTRIDE +
                    (j << 5) + ((lane >> 4) << 4);
                LDSM4(a[mt], addr);
            }
#pragma unroll
            for (int nb = 0; nb < 4; nb++) {
                uint32_t addr = st + A_BYTES +
                    (uint32_t)((nw << 6) + (nb << 4) + (lane & 7) + ((lane >> 4) << 3)) * TSTRIDE +
                    (j << 5) + (((lane >> 3) & 1) << 4);
                LDSM4(bh[nb], addr);
            }
#pragma unroll
            for (int mt = 0; mt < 2; mt++)
#pragma unroll
                for (int nt = 0; nt < 8; nt++)
                    MMA16816(acc[mt][nt], a[mt],
                             bh[nt >> 1][(nt & 1) * 2], bh[nt >> 1][(nt & 1) * 2 + 1]);
        }
        __syncthreads();
    }
}

template <class EP>
__global__ __launch_bounds__(512, 1)
void gemm_mma(const __half* __restrict__ A, const __half* __restrict__ W,
              int K, int Nfull, EP ep) {
    extern __shared__ char sm[];
    const int tid  = threadIdx.x;
    const int wid  = tid >> 5;
    const int lane = tid & 31;
    const int mw = wid & 7, nw = wid >> 3;
    const int bm = blockIdx.y * 256;
    const int bn = blockIdx.x * 128;
    const uint32_t sb = smem_u32(sm);

    float acc[2][8][4];
#pragma unroll
    for (int a = 0; a < 2; a++)
#pragma unroll
        for (int b = 0; b < 8; b++)
#pragma unroll
            for (int c = 0; c < 4; c++) acc[a][b][c] = 0.0f;

    mma_mainloop(A, W, K, bm, bn, sb, tid, acc);

    float* sout = (float*)sm;
#pragma unroll
    for (int rd = 0; rd < 2; rd++) {
        if ((mw >> 2) == rd) {
            const int mb = (mw & 3) << 5, nb = nw << 6;
#pragma unroll
            for (int mt = 0; mt < 2; mt++)
#pragma unroll
                for (int nt = 0; nt < 8; nt++)
#pragma unroll
                    for (int rg = 0; rg < 4; rg++) {
                        int ml = mb + (mt << 4) + (lane >> 2) + ((rg >> 1) << 3);
                        int nl = nb + (nt << 3) + ((lane & 3) << 1) + (rg & 1);
                        sout[ml * SOUT_STRIDE + nl] = acc[mt][nt][rg];
                    }
        }
        __syncthreads();
#pragma unroll 2
        for (int e = tid; e < 4096; e += 512) {
            int r = e >> 5, c4 = (e & 31) << 2;
            float4 v = *(float4*)&sout[r * SOUT_STRIDE + c4];
            ep(bm + (rd << 7) + r, bn + c4, Nfull, v);
        }
        __syncthreads();
    }
}

// ---------------------------------------------------------------------------
// Combined weight transpose + fp16 convert: 12 jobs in one launch
// ---------------------------------------------------------------------------
struct WJob { const float* src; __half* dst; int K, N, start; };
struct WJobs { WJob j[12]; int total; };

__global__ void wcvt_all(WJobs js) {
    int idx = blockIdx.x * 256 + threadIdx.x;
    if (idx >= js.total) return;
    int jj = 0;
#pragma unroll
    for (int t = 1; t < 12; t++) if (idx >= js.j[t].start) jj = t;
    const WJob J = js.j[jj];
    int local = idx - J.start;
    int k = local / J.N, n = local - k * J.N;
    J.dst[(size_t)n * J.K + k] = __float2half(J.src[local]);
}

// concat(xt,hx) -> A16 [M][256]
__global__ void cvtcat_kernel(const float* __restrict__ x, const float* __restrict__ hsrc,
                              __half* __restrict__ o) {
    int i = blockIdx.x * 256 + threadIdx.x;
    int m = i >> 7, k = i & 127;
    o[(size_t)m * 256 + k]       = __float2half(x[i]);
    o[(size_t)m * 256 + 128 + k] = __float2half(hsrc[i]);
}

// ---------------------------------------------------------------------------
// LayerNorm + (roll) + window partition -> fp16 [M][128]
// ---------------------------------------------------------------------------
__global__ void ln_part_kernel(const float* __restrict__ x,
                               const float* __restrict__ gm,
                               const float* __restrict__ bt,
                               __half* __restrict__ out, int shift) {
    int warp = blockIdx.x * 8 + (threadIdx.x >> 5);
    int lane = threadIdx.x & 31;
    int wi = warp >> 6, tok = warp & 63;
    int b = wi >> 6, widx = wi & 63;
    int hh = ((widx >> 3) << 3) + (tok >> 3);
    int ww = ((widx & 7) << 3) + (tok & 7);
    int h = (hh + shift) & 63;
    int w = (ww + shift) & 63;
    const float* row = x + ((size_t)(b << 12) + (h << 6) + w) * CC;

    float4 v = *(const float4*)&row[lane * 4];
    float sum = v.x + v.y + v.z + v.w;
    float sq  = v.x * v.x + v.y * v.y + v.z * v.z + v.w * v.w;
#pragma unroll
    for (int o = 16; o; o >>= 1) {
        sum += __shfl_xor_sync(0xffffffffu, sum, o);
        sq  += __shfl_xor_sync(0xffffffffu, sq, o);
    }
    float mean = sum * (1.0f / 128.0f);
    float var  = sq * (1.0f / 128.0f) - mean * mean;
    float rstd = rsqrtf(var + 1e-5f);
    const float4 g4 = *(const float4*)&gm[lane * 4];
    const float4 b4 = *(const float4*)&bt[lane * 4];
    uint2 o;
    o.x = pack2h((v.x - mean) * rstd * g4.x + b4.x, (v.y - mean) * rstd * g4.y + b4.y);
    o.y = pack2h((v.z - mean) * rstd * g4.z + b4.z, (v.w - mean) * rstd * g4.w + b4.w);
    *(uint2*)&out[(size_t)warp * CC + lane * 4] = o;
}

__global__ void ln_plain_kernel(const float* __restrict__ x,
                                const float* __restrict__ gm,
                                const float* __restrict__ bt,
                                __half* __restrict__ out) {
    int warp = blockIdx.x * 8 + (threadIdx.x >> 5);
    int lane = threadIdx.x & 31;
    const float* row = x + (size_t)warp * CC;
    float4 v = *(const float4*)&row[lane * 4];
    float sum = v.x + v.y + v.z + v.w;
    float sq  = v.x * v.x + v.y * v.y + v.z * v.z + v.w * v.w;
#pragma unroll
    for (int o = 16; o; o >>= 1) {
        sum += __shfl_xor_sync(0xffffffffu, sum, o);
        sq  += __shfl_xor_sync(0xffffffffu, sq, o);
    }
    float mean = sum * (1.0f / 128.0f);
    float var  = sq * (1.0f / 128.0f) - mean * mean;
    float rstd = rsqrtf(var + 1e-5f);
    const float4 g4 = *(const float4*)&gm[lane * 4];
    const float4 b4 = *(const float4*)&bt[lane * 4];
    uint2 o;
    o.x = pack2h((v.x - mean) * rstd * g4.x + b4.x, (v.y - mean) * rstd * g4.y + b4.y);
    o.y = pack2h((v.z - mean) * rstd * g4.z + b4.z, (v.w - mean) * rstd * g4.w + b4.w);
    *(uint2*)&out[(size_t)warp * CC + lane * 4] = o;
}

// ---------------------------------------------------------------------------
// Window attention, qkv in fp16 -> fp16 output.
// Block = one window (256 thr = 4 heads x 64 rows)
// ---------------------------------------------------------------------------
__device__ __forceinline__ int zone_(int h) { return h < 56 ? 0 : (h < 60 ? 1 : 2); }

#define ATTN_SMEM 69136   // kk 32KB + vv 32KB + rps 3600B

__global__ __launch_bounds__(256)
void attn_kernel(const __half* __restrict__ qkv, const float* __restrict__ rp,
                 __half* __restrict__ out, int shift) {
    extern __shared__ float smf[];
    float* kk  = smf;
    float* vv  = smf + 8192;
    float* rps = smf + 16384;

    const int wi   = blockIdx.x;
    const int t    = threadIdx.x;
    const int head = t >> 6;
    const int row  = t & 63;
    const int base = wi * 64;

    for (int i = t; i < 900; i += 256) rps[i] = rp[i];
    for (int i = t; i < 4096; i += 256) {
        int m = i >> 6, c2 = (i & 63) << 1;
        __half2 hk = *(const __half2*)&qkv[(size_t)(base + m) * 384 + 128 + c2];
        __half2 hv = *(const __half2*)&qkv[(size_t)(base + m) * 384 + 256 + c2];
        float2 fk = __half22float2(hk);
        float2 fv = __half22float2(hv);
        int part = c2 >> 5, off = c2 & 31;
        kk[(part * 64 + m) * 32 + off]     = fk.x;
        kk[(part * 64 + m) * 32 + off + 1] = fk.y;
        vv[(part * 64 + m) * 32 + off]     = fv.x;
        vv[(part * 64 + m) * 32 + off + 1] = fv.y;
    }
    __syncthreads();

    float q[32];
#pragma unroll
    for (int d8 = 0; d8 < 4; d8++) {
        uint4 raw = *(const uint4*)&qkv[(size_t)(base + row) * 384 + head * 32 + d8 * 8];
        const __half2* hp = (const __half2*)&raw;
#pragma unroll
        for (int p = 0; p < 4; p++) {
            float2 f = __half22float2(hp[p]);
            q[d8*8 + p*2]     = f.x * SCALE_Q;
            q[d8*8 + p*2 + 1] = f.y * SCALE_Q;
        }
    }

    const int rn = row >> 3, cn = row & 7;
    const int widx = wi & 63;
    const int wh = widx >> 3, wwc = widx & 7;
    int zr_n = 0, zc_n = 0;
    if (shift) { zr_n = zone_(wh * 8 + rn); zc_n = zone_(wwc * 8 + cn); }

    const float* kh = kk + head * 2048;
    const float* vh = vv + head * 2048;

    float o[32];
#pragma unroll
    for (int d = 0; d < 32; d++) o[d] = 0.0f;
    float sum = 0.0f;

#pragma unroll 4
    for (int m = 0; m < 64; m++) {
        float a = 0.0f;
        const float* kr = kh + m * 32;
#pragma unroll
        for (int d4 = 0; d4 < 8; d4++) {
            float4 kv4 = *(const float4*)&kr[d4 * 4];
            a += q[d4*4+0] * kv4.x + q[d4*4+1] * kv4.y +
                 q[d4*4+2] * kv4.z + q[d4*4+3] * kv4.w;
        }
        int rm = m >> 3, cm = m & 7;
        int ridx = (rn - rm + 7) * 15 + (cn - cm + 7);
        a += rps[ridx * 4 + head];
        if (shift) {
            if (zone_(wh * 8 + rm) != zr_n || zone_(wwc * 8 + cm) != zc_n)
                a += -100.0f;
        }
        float p = __expf(a);
        sum += p;
        const float* vr = vh + m * 32;
#pragma unroll
        for (int d4 = 0; d4 < 8; d4++) {
            float4 vv4 = *(const float4*)&vr[d4 * 4];
            o[d4*4+0] += p * vv4.x; o[d4*4+1] += p * vv4.y;
            o[d4*4+2] += p * vv4.z; o[d4*4+3] += p * vv4.w;
        }
    }
    float inv = 1.0f / sum;
#pragma unroll
    for (int d4 = 0; d4 < 8; d4++) {
        uint2 ov;
        ov.x = pack2h(o[d4*4+0] * inv, o[d4*4+1] * inv);
        ov.y = pack2h(o[d4*4+2] * inv, o[d4*4+3] * inv);
        *(uint2*)&out[(size_t)(base + row) * CC + head * 32 + d4 * 4] = ov;
    }
}

// ---------------------------------------------------------------------------
// Conv1d offset + mask head
// ---------------------------------------------------------------------------
__global__ void offmask_kernel(const float* __restrict__ xt,
                               const float* __restrict__ offw, const float* __restrict__ offb,
                               const float* __restrict__ mskw, const float* __restrict__ mskb,
                               float* __restrict__ off, float* __restrict__ msk) {
    __shared__ float swo[1152], swm[1152];
    int tid = threadIdx.x;
    for (int i = tid; i < 1152; i += 256) { swo[i] = offw[i]; swm[i] = mskw[i]; }
    __syncthreads();

    int warp = tid >> 5, lane = tid & 31;
    int pos = blockIdx.x * 8 + warp;
    int b = pos >> 12, l = pos & 4095;

    float ao[3] = {0.f, 0.f, 0.f}, am[3] = {0.f, 0.f, 0.f};
#pragma unroll
    for (int i = 0; i < 4; i++) {
        int c = lane + 32 * i;
        float xv[3];
#pragma unroll
        for (int j = 0; j < 3; j++) {
            int ls = l + j - 1;
            xv[j] = (ls >= 0 && ls < LL)
                  ? xt[((size_t)(b << 12) + ls) * CC + c] : 0.0f;
        }
#pragma unroll
        for (int ko = 0; ko < 3; ko++)
#pragma unroll
            for (int j = 0; j < 3; j++) {
                ao[ko] += xv[j] * swo[ko * 384 + c * 3 + j];
                am[ko] += xv[j] * swm[ko * 384 + c * 3 + j];
            }
    }
#pragma unroll
    for (int o = 16; o; o >>= 1)
#pragma unroll
        for (int ko = 0; ko < 3; ko++) {
            ao[ko] += __shfl_xor_sync(0xffffffffu, ao[ko], o);
            am[ko] += __shfl_xor_sync(0xffffffffu, am[ko], o);
        }
    if (lane == 0) {
#pragma unroll
        for (int ko = 0; ko < 3; ko++) {
            float ov = ao[ko] + offb[ko];
            float mv = am[ko] + mskb[ko];
            off[((size_t)(b * 3 + ko)) * LL + l] = ov;
            msk[((size_t)(b * 3 + ko)) * LL + l] = 1.0f / (1.0f + expf(-mv));
        }
    }
}

// ---------------------------------------------------------------------------
// Deformable sample -> fp16 at flat (B,C,L) layout == (B,L,C) view
// ---------------------------------------------------------------------------
__global__ void deform_kernel(const float* __restrict__ xt,
                              const float* __restrict__ off,
                              const float* __restrict__ msk,
                              __half* __restrict__ out) {
    __shared__ float s[128][33];
    __shared__ int   sfp[3][32], scp[3][32];
    __shared__ float sal[3][32], sm[3][32];

    int blk = blockIdx.x;
    int b = blk >> 7;
    int l0 = (blk & 127) << 5;
    int tid = threadIdx.x;

    if (tid < 96) {
        int k = tid / 32, li = tid % 32;
        int l = l0 + li;
        float o  = off[((size_t)(b * 3 + k)) * LL + l];
        float p  = fminf(fmaxf((float)l + o, 0.0f), 4095.0f);
        int fp   = (int)floorf(p);
        int cp   = min(fp + 1, 4095);
        sfp[k][li] = fp; scp[k][li] = cp;
        sal[k][li] = p - (float)fp;
        sm [k][li] = msk[((size_t)(b * 3 + k)) * LL + l];
    }
    __syncthreads();

    for (int e = tid; e < 4096; e += 256) {
        int li = e >> 7, c = e & 127;
        float acc = 0.0f;
#pragma unroll
        for (int k = 0; k < 3; k++) {
            float a  = sal[k][li];
            float xf = xt[((size_t)(b << 12) + sfp[k][li]) * CC + c];
            float xc = xt[((size_t)(b << 12) + scp[k][li]) * CC + c];
            acc += (xf * (1.0f - a) + xc * a) * sm[k][li];
        }
        s[c][li] = acc;
    }
    __syncthreads();
    for (int e = tid; e < 4096; e += 256) {
        int c = e >> 5, li = e & 31;
        size_t idx = (size_t)b * (CC * LL) + (size_t)c * LL + l0 + li;
        out[idx] = __float2half(s[c][li]);
    }
}

// ---------------------------------------------------------------------------
// Host launch
// ---------------------------------------------------------------------------
extern "C" void kernel_launch(void* const* d_in, const int* in_sizes, int n_in,
                              void* d_out, int out_size) {
    const float* xt    = (const float*)d_in[0];
    const float* hx    = (const float*)d_in[1];
    const float* cx    = (const float*)d_in[2];
    const float* red_w = (const float*)d_in[3];
    const float* red_b = (const float*)d_in[4];
    const float* n1g   = (const float*)d_in[5];
    const float* n1b   = (const float*)d_in[6];
    const float* qkvw  = (const float*)d_in[7];
    const float* qkvb  = (const float*)d_in[8];
    const float* rp    = (const float*)d_in[9];
    const float* pw    = (const float*)d_in[10];
    const float* pb    = (const float*)d_in[11];
    const float* n2g   = (const float*)d_in[12];
    const float* n2b   = (const float*)d_in[13];
    const float* f1w   = (const float*)d_in[14];
    const float* f1b   = (const float*)d_in[15];
    const float* f2w   = (const float*)d_in[16];
    const float* f2b   = (const float*)d_in[17];
    const float* off_w = (const float*)d_in[18];
    const float* off_b = (const float*)d_in[19];
    const float* msk_w = (const float*)d_in[20];
    const float* msk_b = (const float*)d_in[21];
    const float* lf_w  = (const float*)d_in[22];
    const float* lf_b  = (const float*)d_in[23];
    const float* gf_w  = (const float*)d_in[24];
    const float* gf_b  = (const float*)d_in[25];
    const float* ff_w  = (const float*)d_in[26];
    const float* ff_b  = (const float*)d_in[27];
    float* hy = (float*)d_out;

    float *pg, *pt1, *poff, *pmsk;
    cudaGetSymbolAddress((void**)&pg,   g_buf);
    cudaGetSymbolAddress((void**)&pt1,  g_t1);
    cudaGetSymbolAddress((void**)&poff, g_off);
    cudaGetSymbolAddress((void**)&pmsk, g_msk);

    __half *A16, *B16, *C16;
    cudaGetSymbolAddress((void**)&A16, g_A16);
    cudaGetSymbolAddress((void**)&B16, g_B16);
    cudaGetSymbolAddress((void**)&C16, g_C16);

    __half *redw, *qkvw16, *pww, *f1ww, *f2ww, *lfw, *gfw, *ffw;
    cudaGetSymbolAddress((void**)&redw,   w_red);
    cudaGetSymbolAddress((void**)&qkvw16, w_qkv);
    cudaGetSymbolAddress((void**)&pww,    w_pw);
    cudaGetSymbolAddress((void**)&f1ww,   w_f1);
    cudaGetSymbolAddress((void**)&f2ww,   w_f2);
    cudaGetSymbolAddress((void**)&lfw,    w_lf);
    cudaGetSymbolAddress((void**)&gfw,    w_gf);
    cudaGetSymbolAddress((void**)&ffw,    w_ff);

    cudaFuncSetAttribute(gemm_mma<EpiBias>,     cudaFuncAttributeMaxDynamicSharedMemorySize, GEMM_SMEM);
    cudaFuncSetAttribute(gemm_mma<EpiBiasH>,    cudaFuncAttributeMaxDynamicSharedMemorySize, GEMM_SMEM);
    cudaFuncSetAttribute(gemm_mma<EpiGeluH>,    cudaFuncAttributeMaxDynamicSharedMemorySize, GEMM_SMEM);
    cudaFuncSetAttribute(gemm_mma<EpiProj>,     cudaFuncAttributeMaxDynamicSharedMemorySize, GEMM_SMEM);
    cudaFuncSetAttribute(gemm_mma<EpiResid>,    cudaFuncAttributeMaxDynamicSharedMemorySize, GEMM_SMEM);
    cudaFuncSetAttribute(gemm_mma<EpiResidH>,   cudaFuncAttributeMaxDynamicSharedMemorySize, GEMM_SMEM);
    cudaFuncSetAttribute(gemm_mma<EpiMulReluH>, cudaFuncAttributeMaxDynamicSharedMemorySize, GEMM_SMEM);
    cudaFuncSetAttribute(gemm_mma<EpiLSTM>,     cudaFuncAttributeMaxDynamicSharedMemorySize, GEMM_SMEM);
    cudaFuncSetAttribute(attn_kernel,           cudaFuncAttributeMaxDynamicSharedMemorySize, ATTN_SMEM);

    const dim3 blk256(256), blk512(512);

    // 0) all weight converts in one launch
    {
        WJobs js; int off = 0, n = 0;
        auto add = [&](const float* s, __half* d, int K, int N) {
            js.j[n++] = WJob{s, d, K, N, off};
            off += K * N;
        };
        add(red_w, redw, 256, 128);
        for (int i = 0; i < 2; i++) {
            add(qkvw + (size_t)i*128*384, qkvw16 + (size_t)i*384*128, 128, 384);
            add(pw   + (size_t)i*128*128, pww    + (size_t)i*128*128, 128, 128);
            add(f1w  + (size_t)i*128*512, f1ww   + (size_t)i*512*128, 128, 512);
            add(f2w  + (size_t)i*512*128, f2ww   + (size_t)i*128*512, 512, 128);
        }
        add(lf_w, lfw, 128, 128);
        add(gf_w, gfw, 128, 128);
        add(ff_w, ffw, 128, 128);
        js.total = off;
        wcvt_all<<<(off + 255) / 256, blk256>>>(js);
    }

    const dim3 gN1(1, 128), gN3(3, 128), gN4(4, 128);

    // 1) g = concat(xt, hx) @ red_w + red_b
    cvtcat_kernel<<<MROWS * 128 / 256, blk256>>>(xt, hx, A16);
    gemm_mma<<<gN1, blk512, GEMM_SMEM>>>(A16, redw, 256, 128, EpiBias{pg, red_b});

    // 2) two Swin blocks
    for (int i = 0; i < 2; i++) {
        int shift = (i == 0) ? 0 : 4;
        const float* qkvb_i = qkvb + (size_t)i * 384;
        const float* rp_i   = rp   + (size_t)i * 225 * 4;
        const float* pb_i   = pb   + (size_t)i * 128;
        const float* f1b_i  = f1b  + (size_t)i * 512;
        const float* f2b_i  = f2b  + (size_t)i * 128;

        ln_part_kernel<<<MROWS / 8, blk256>>>(pg, n1g + i * CC, n1b + i * CC, A16, shift);
        gemm_mma<<<gN3, blk512, GEMM_SMEM>>>(A16, qkvw16 + (size_t)i*384*128,
                                             128, 384, EpiBiasH{B16, qkvb_i});
        attn_kernel<<<BB * 64, blk256, ATTN_SMEM>>>(B16, rp_i, A16, shift);
        gemm_mma<<<gN1, blk512, GEMM_SMEM>>>(A16, pww + (size_t)i*128*128,
                                             128, 128, EpiProj{pg, pb_i, shift});
        ln_plain_kernel<<<MROWS / 8, blk256>>>(pg, n2g + i * CC, n2b + i * CC, A16);
        gemm_mma<<<gN4, blk512, GEMM_SMEM>>>(A16, f1ww + (size_t)i*512*128,
                                             128, 512, EpiGeluH{B16, f1b_i});
        if (i == 0)
            gemm_mma<<<gN1, blk512, GEMM_SMEM>>>(B16, f2ww,
                                                 512, 128, EpiResid{pg, pg, f2b_i});
        else
            gemm_mma<<<gN1, blk512, GEMM_SMEM>>>(B16, f2ww + (size_t)1*128*512,
                                                 512, 128, EpiResidH{C16, pg, f2b_i});
    }

    // 3) local branch -> A16
    offmask_kernel<<<MROWS / 8, blk256>>>(xt, off_w, off_b, msk_w, msk_b, poff, pmsk);
    deform_kernel<<<BB * (LL / 32), blk256>>>(xt, poff, pmsk, A16);

    // 4) fusion + LSTM gating
    gemm_mma<<<gN1, blk512, GEMM_SMEM>>>(A16, lfw, 128, 128, EpiBias{pt1, lf_b});
    gemm_mma<<<gN1, blk512, GEMM_SMEM>>>(C16, gfw, 128, 128, EpiMulReluH{A16, pt1, gf_b});
    gemm_mma<<<gN1, blk512, GEMM_SMEM>>>(A16, ffw, 128, 128, EpiLSTM{hy, cx, ff_b});
}

// round 11
// speedup vs baseline: 3.3059x; 1.0181x over previous
#include <cuda_runtime.h>
#include <cuda_fp16.h>
#include <math.h>
#include <stdint.h>

// ---------------------------------------------------------------------------
// Problem constants
// ---------------------------------------------------------------------------
#define BB   8
#define LL   4096
#define CC   128
#define MROWS (BB*LL)      // 32768
#define SCALE_Q 0.17677669529663687f

// ---------------------------------------------------------------------------
// Scratch (device globals — no allocation allowed)
// ---------------------------------------------------------------------------
__device__ float g_buf  [MROWS * CC];        // fp32 running state g
__device__ float g_t1   [MROWS * CC];        // t1 in phase 4
__device__ float g_off  [BB * 3 * LL];
__device__ float g_msk  [BB * 3 * LL];

// fp16 activation buffers
__device__ __align__(256) __half g_A16[MROWS * 256];   // concat input / attn out / deform / fu
__device__ __align__(256) __half g_B16[MROWS * 512];   // qkv (384) / FFN hidden (512)
__device__ __align__(256) __half g_C16[MROWS * 128];   // LN outputs / g fp16 copy

// converted + transposed weights, fp16 [N][K]
__device__ __align__(256) __half w_red[128*256];
__device__ __align__(256) __half w_qkv[2][384*128];
__device__ __align__(256) __half w_pw [2][128*128];
__device__ __align__(256) __half w_f1 [2][512*128];
__device__ __align__(256) __half w_f2 [2][128*512];
__device__ __align__(256) __half w_lf[128*128];
__device__ __align__(256) __half w_gf[128*128];
__device__ __align__(256) __half w_ff[128*128];

// ---------------------------------------------------------------------------
// helpers
// ---------------------------------------------------------------------------
__device__ __forceinline__ uint32_t smem_u32(const void* p) {
    uint32_t a;
    asm("{ .reg .u64 t; cvta.to.shared.u64 t, %1; cvt.u32.u64 %0, t; }"
        : "=r"(a) : "l"(p));
    return a;
}
__device__ __forceinline__ void cp16(uint32_t s, const void* g) {
    asm volatile("cp.async.cg.shared.global [%0], [%1], 16;" :: "r"(s), "l"(g));
}
__device__ __forceinline__ uint32_t pack2h(float a, float b) {
    __half2 p = __floats2half2_rn(a, b);
    return *(uint32_t*)&p;
}

#define LDSM4(r, a) \
    asm volatile("ldmatrix.sync.aligned.m8n8.x4.shared.b16 {%0,%1,%2,%3}, [%4];" \
        : "=r"((r)[0]), "=r"((r)[1]), "=r"((r)[2]), "=r"((r)[3]) : "r"(a))

#define MMA16816(d, a, b0, b1) \
    asm volatile("mma.sync.aligned.m16n8k16.row.col.f32.f16.f16.f32 " \
        "{%0,%1,%2,%3}, {%4,%5,%6,%7}, {%8,%9}, {%0,%1,%2,%3};" \
        : "+f"((d)[0]), "+f"((d)[1]), "+f"((d)[2]), "+f"((d)[3]) \
        : "r"((a)[0]), "r"((a)[1]), "r"((a)[2]), "r"((a)[3]), "r"(b0), "r"(b1))

// warp LN of one 128-col row: lanes hold 4 consecutive values each
__device__ __forceinline__ void warp_ln_stats(float4 v, float& mean, float& rstd) {
    float sum = v.x + v.y + v.z + v.w;
    float sq  = v.x * v.x + v.y * v.y + v.z * v.z + v.w * v.w;
#pragma unroll
    for (int o = 16; o; o >>= 1) {
        sum += __shfl_xor_sync(0xffffffffu, sum, o);
        sq  += __shfl_xor_sync(0xffffffffu, sq, o);
    }
    mean = sum * (1.0f / 128.0f);
    float var = sq * (1.0f / 128.0f) - mean * mean;
    rstd = rsqrtf(var + 1e-5f);
}

// ---------------------------------------------------------------------------
// Epilogues: ep(m, n0, N, float4), n0 % 4 == 0.
// Contract: one warp processes one full output row (32 lanes x float4),
// convergent — warp shuffles are legal inside.
// ---------------------------------------------------------------------------
struct EpiBias {
    float* out; const float* bias;
    __device__ __forceinline__ void operator()(int m, int n0, int N, float4 v) const {
        const float4 b = *(const float4*)&bias[n0];
        v.x += b.x; v.y += b.y; v.z += b.z; v.w += b.w;
        *(float4*)&out[(size_t)m * N + n0] = v;
    }
};
struct EpiBiasH {     // acc + bias -> fp16
    __half* out; const float* bias;
    __device__ __forceinline__ void operator()(int m, int n0, int N, float4 v) const {
        const float4 b = *(const float4*)&bias[n0];
        uint2 o;
        o.x = pack2h(v.x + b.x, v.y + b.y);
        o.y = pack2h(v.z + b.z, v.w + b.w);
        *(uint2*)&out[(size_t)m * N + n0] = o;
    }
};
// acc + bias -> g (fp32) ; LN + roll-partition permute -> a16 (fp16)
struct EpiBiasLN {
    float* g; const float* bias;
    __half* a16; const float* lng; const float* lnb; int shift;
    __device__ __forceinline__ void operator()(int m, int n0, int N, float4 v) const {
        const float4 b = *(const float4*)&bias[n0];
        v.x += b.x; v.y += b.y; v.z += b.z; v.w += b.w;
        *(float4*)&g[(size_t)m * CC + n0] = v;
        float mean, rstd; warp_ln_stats(v, mean, rstd);
        const float4 G  = *(const float4*)&lng[n0];
        const float4 Bt = *(const float4*)&lnb[n0];
        int bb = m >> 12, hw = m & 4095;
        int hp = ((hw >> 6) - shift) & 63;
        int wp = ((hw & 63) - shift) & 63;
        int dst = (bb << 12) + ((((hp >> 3) << 3) + (wp >> 3)) << 6)
                + ((hp & 7) << 3) + (wp & 7);
        uint2 o;
        o.x = pack2h((v.x - mean) * rstd * G.x + Bt.x, (v.y - mean) * rstd * G.y + Bt.y);
        o.y = pack2h((v.z - mean) * rstd * G.z + Bt.z, (v.w - mean) * rstd * G.w + Bt.w);
        *(uint2*)&a16[(size_t)dst * CC + n0] = o;
    }
};
// res + acc + bias -> g ; LN + roll-partition permute -> a16
struct EpiResidLN {
    float* g; const float* res; const float* bias;
    __half* a16; const float* lng; const float* lnb; int shift;
    __device__ __forceinline__ void operator()(int m, int n0, int N, float4 v) const {
        size_t i = (size_t)m * CC + n0;
        const float4 b = *(const float4*)&bias[n0];
        const float4 r = *(const float4*)&res[i];
        v.x += b.x + r.x; v.y += b.y + r.y; v.z += b.z + r.z; v.w += b.w + r.w;
        *(float4*)&g[i] = v;
        float mean, rstd; warp_ln_stats(v, mean, rstd);
        const float4 G  = *(const float4*)&lng[n0];
        const float4 Bt = *(const float4*)&lnb[n0];
        int bb = m >> 12, hw = m & 4095;
        int hp = ((hw >> 6) - shift) & 63;
        int wp = ((hw & 63) - shift) & 63;
        int dst = (bb << 12) + ((((hp >> 3) << 3) + (wp >> 3)) << 6)
                + ((hp & 7) << 3) + (wp & 7);
        uint2 o;
        o.x = pack2h((v.x - mean) * rstd * G.x + Bt.x, (v.y - mean) * rstd * G.y + Bt.y);
        o.y = pack2h((v.z - mean) * rstd * G.z + Bt.z, (v.w - mean) * rstd * G.w + Bt.w);
        *(uint2*)&a16[(size_t)dst * CC + n0] = o;
    }
};
struct EpiResidH {  // (res + acc + bias) -> fp16
    __half* out; const float* res; const float* bias;
    __device__ __forceinline__ void operator()(int m, int n0, int N, float4 v) const {
        size_t i = (size_t)m * N + n0;
        const float4 b = *(const float4*)&bias[n0];
        const float4 r = *(const float4*)&res[i];
        uint2 o;
        o.x = pack2h(v.x + b.x + r.x, v.y + b.y + r.y);
        o.y = pack2h(v.z + b.z + r.z, v.w + b.w + r.w);
        *(uint2*)&out[i] = o;
    }
};
// window-reverse(+shift) residual RMW into g ; LN -> a16 (token layout)
struct EpiProjLN {
    float* g; const float* bias; int shift;
    __half* a16; const float* lng; const float* lnb;
    __device__ __forceinline__ void operator()(int m, int n0, int N, float4 v) const {
        int bb   = m >> 12;
        int rb   = m & 4095;
        int widx = rb >> 6;
        int tok  = rb & 63;
        int hh = ((widx >> 3) << 3) + (tok >> 3);
        int ww = ((widx & 7) << 3) + (tok & 7);
        int h = (hh + shift) & 63;
        int w = (ww + shift) & 63;
        size_t dst = (size_t)(bb << 12) + (h << 6) + w;
        size_t di = dst * CC + n0;
        const float4 bi = *(const float4*)&bias[n0];
        float4 o = *(const float4*)&g[di];
        o.x += v.x + bi.x; o.y += v.y + bi.y; o.z += v.z + bi.z; o.w += v.w + bi.w;
        *(float4*)&g[di] = o;
        float mean, rstd; warp_ln_stats(o, mean, rstd);
        const float4 G  = *(const float4*)&lng[n0];
        const float4 Bt = *(const float4*)&lnb[n0];
        uint2 ov;
        ov.x = pack2h((o.x - mean) * rstd * G.x + Bt.x, (o.y - mean) * rstd * G.y + Bt.y);
        ov.y = pack2h((o.z - mean) * rstd * G.z + Bt.z, (o.w - mean) * rstd * G.w + Bt.w);
        *(uint2*)&a16[di] = ov;
    }
};
struct EpiGeluH {
    __half* out; const float* bias;
    __device__ __forceinline__ void operator()(int m, int n0, int N, float4 v) const {
        const float4 b = *(const float4*)&bias[n0];
        float g[4] = {v.x + b.x, v.y + b.y, v.z + b.z, v.w + b.w};
#pragma unroll
        for (int k = 0; k < 4; k++)
            g[k] = 0.5f * g[k] * (1.0f + erff(g[k] * 0.7071067811865476f));
        uint2 o; o.x = pack2h(g[0], g[1]); o.y = pack2h(g[2], g[3]);
        *(uint2*)&out[(size_t)m * N + n0] = o;
    }
};
struct EpiMulReluH {
    __half* out; const float* t1; const float* bias;
    __device__ __forceinline__ void operator()(int m, int n0, int N, float4 v) const {
        size_t i = (size_t)m * N + n0;
        const float4 b = *(const float4*)&bias[n0];
        const float4 t = *(const float4*)&t1[i];
        float g[4] = {fmaxf(0.0f, t.x * (v.x + b.x)), fmaxf(0.0f, t.y * (v.y + b.y)),
                      fmaxf(0.0f, t.z * (v.z + b.z)), fmaxf(0.0f, t.w * (v.w + b.w))};
        uint2 o; o.x = pack2h(g[0], g[1]); o.y = pack2h(g[2], g[3]);
        *(uint2*)&out[i] = o;
    }
};
struct EpiLSTM {
    float* hy; const float* cx; const float* bias;
    __device__ __forceinline__ void operator()(int m, int n0, int N, float4 v) const {
        size_t i = (size_t)m * N + n0;
        const float4 b = *(const float4*)&bias[n0];
        const float4 c = *(const float4*)&cx[i];
        float f[4] = {v.x + b.x, v.y + b.y, v.z + b.z, v.w + b.w};
        float cc[4] = {c.x, c.y, c.z, c.w};
        float o[4];
#pragma unroll
        for (int k = 0; k < 4; k++) {
            float gate = 1.0f / (1.0f + expf(-f[k]));
            float cell = tanhf(f[k]);
            float cy   = gate * (cc[k] + cell);
            o[k] = gate * tanhf(cy);
        }
        *(float4*)&hy[i] = *(float4*)o;
    }
};

// ---------------------------------------------------------------------------
// fp16 single-pass GEMM on mma.sync (m16n8k16): D = A @ W.
// CTA tile 256x128, 16 warps (8 m x 2 n), K-chunk 32, double-buffered cp.async.
// Epilogue: full 256x128 tile staged in smem, one sync, warp-per-row apply.
// ---------------------------------------------------------------------------
#define TSTRIDE 80
#define A_BYTES 20480     // 256 rows * 80
#define B_BYTES 10240     // 128 rows * 80
#define STAGE_B 30720
#define SOUT_STRIDE 132
#define GEMM_SMEM 135168  // max(2*STAGE_B=61440, sout 256*132*4=135168)

__device__ __forceinline__ void mma_mainloop(
    const __half* __restrict__ A, const __half* __restrict__ W,
    int K, int bm, int bn, uint32_t sb, int tid, float acc[2][8][4])
{
    const int wid = tid >> 5, lane = tid & 31;
    const int mw = wid & 7, nw = wid >> 3;
    const int nch = K >> 5;

    auto load_stage = [&](int i) {
        uint32_t st = sb + (uint32_t)(i & 1) * STAGE_B;
        int kt = i << 5;
        int r = tid >> 2, q = tid & 3;
        uint32_t so = (uint32_t)r * TSTRIDE + q * 16;
        cp16(st + so,                  A + (size_t)(bm + r) * K + kt + q * 8);
        cp16(st + 128u * TSTRIDE + so, A + (size_t)(bm + r + 128) * K + kt + q * 8);
        cp16(st + A_BYTES + so,        W + (size_t)(bn + r) * K + kt + q * 8);
        asm volatile("cp.async.commit_group;");
    };

    load_stage(0);
    for (int i = 0; i < nch; i++) {
        if (i + 1 < nch) {
            load_stage(i + 1);
            asm volatile("cp.async.wait_group 1;");
        } else {
            asm volatile("cp.async.wait_group 0;");
        }
        __syncthreads();

        uint32_t st = sb + (uint32_t)(i & 1) * STAGE_B;
#pragma unroll
        for (int j = 0; j < 2; j++) {
            uint32_t a[2][4], bh[4][4];
#pragma unroll
            for (int mt = 0; mt < 2; mt++) {
                uint32_t addr = st +
                    (uint32_t)((mw << 5) + (mt << 4) + (lane & 15)) * TSTRIDE +
                    (j << 5) + ((lane >> 4) << 4);
                LDSM4(a[mt], addr);
            }
#pragma unroll
            for (int nb = 0; nb < 4; nb++) {
                uint32_t addr = st + A_BYTES +
                    (uint32_t)((nw << 6) + (nb << 4) + (lane & 7) + ((lane >> 4) << 3)) * TSTRIDE +
                    (j << 5) + (((lane >> 3) & 1) << 4);
                LDSM4(bh[nb], addr);
            }
#pragma unroll
            for (int mt = 0; mt < 2; mt++)
#pragma unroll
                for (int nt = 0; nt < 8; nt++)
                    MMA16816(acc[mt][nt], a[mt],
                             bh[nt >> 1][(nt & 1) * 2], bh[nt >> 1][(nt & 1) * 2 + 1]);
        }
        __syncthreads();
    }
}

template <class EP>
__global__ __launch_bounds__(512, 1)
void gemm_mma(const __half* __restrict__ A, const __half* __restrict__ W,
              int K, int Nfull, EP ep) {
    extern __shared__ char sm[];
    const int tid  = threadIdx.x;
    const int wid  = tid >> 5;
    const int lane = tid & 31;
    const int mw = wid & 7, nw = wid >> 3;
    const int bm = blockIdx.y * 256;
    const int bn = blockIdx.x * 128;
    const uint32_t sb = smem_u32(sm);

    float acc[2][8][4];
#pragma unroll
    for (int a = 0; a < 2; a++)
#pragma unroll
        for (int b = 0; b < 8; b++)
#pragma unroll
            for (int c = 0; c < 4; c++) acc[a][b][c] = 0.0f;

    mma_mainloop(A, W, K, bm, bn, sb, tid, acc);

    float* sout = (float*)sm;
    const int mb = mw << 5, nb = nw << 6;
#pragma unroll
    for (int mt = 0; mt < 2; mt++)
#pragma unroll
        for (int nt = 0; nt < 8; nt++)
#pragma unroll
            for (int rg = 0; rg < 4; rg++) {
                int ml = mb + (mt << 4) + (lane >> 2) + ((rg >> 1) << 3);
                int nl = nb + (nt << 3) + ((lane & 3) << 1) + (rg & 1);
                sout[ml * SOUT_STRIDE + nl] = acc[mt][nt][rg];
            }
    __syncthreads();
#pragma unroll 4
    for (int e = tid; e < 8192; e += 512) {
        int r = e >> 5, c4 = (e & 31) << 2;
        float4 v = *(float4*)&sout[r * SOUT_STRIDE + c4];
        ep(bm + r, bn + c4, Nfull, v);
    }
}

// ---------------------------------------------------------------------------
// Combined weight transpose + fp16 convert: 12 jobs in one launch
// ---------------------------------------------------------------------------
struct WJob { const float* src; __half* dst; int K, N, start; };
struct WJobs { WJob j[12]; int total; };

__global__ void wcvt_all(WJobs js) {
    int idx = blockIdx.x * 256 + threadIdx.x;
    if (idx >= js.total) return;
    int jj = 0;
#pragma unroll
    for (int t = 1; t < 12; t++) if (idx >= js.j[t].start) jj = t;
    const WJob J = js.j[jj];
    int local = idx - J.start;
    int k = local / J.N, n = local - k * J.N;
    J.dst[(size_t)n * J.K + k] = __float2half(J.src[local]);
}

// concat(xt,hx) -> A16 [M][256]
__global__ void cvtcat_kernel(const float* __restrict__ x, const float* __restrict__ hsrc,
                              __half* __restrict__ o) {
    int i = blockIdx.x * 256 + threadIdx.x;
    int m = i >> 7, k = i & 127;
    o[(size_t)m * 256 + k]       = __float2half(x[i]);
    o[(size_t)m * 256 + 128 + k] = __float2half(hsrc[i]);
}

// ---------------------------------------------------------------------------
// Window attention, qkv in fp16 -> fp16 output.
// Block = one window (256 thr = 4 heads x 64 rows)
// ---------------------------------------------------------------------------
__device__ __forceinline__ int zone_(int h) { return h < 56 ? 0 : (h < 60 ? 1 : 2); }

#define ATTN_SMEM 69136   // kk 32KB + vv 32KB + rps 3600B

__global__ __launch_bounds__(256)
void attn_kernel(const __half* __restrict__ qkv, const float* __restrict__ rp,
                 __half* __restrict__ out, int shift) {
    extern __shared__ float smf[];
    float* kk  = smf;
    float* vv  = smf + 8192;
    float* rps = smf + 16384;

    const int wi   = blockIdx.x;
    const int t    = threadIdx.x;
    const int head = t >> 6;
    const int row  = t & 63;
    const int base = wi * 64;

    for (int i = t; i < 900; i += 256) rps[i] = rp[i];
    for (int i = t; i < 4096; i += 256) {
        int m = i >> 6, c2 = (i & 63) << 1;
        __half2 hk = *(const __half2*)&qkv[(size_t)(base + m) * 384 + 128 + c2];
        __half2 hv = *(const __half2*)&qkv[(size_t)(base + m) * 384 + 256 + c2];
        float2 fk = __half22float2(hk);
        float2 fv = __half22float2(hv);
        int part = c2 >> 5, off = c2 & 31;
        kk[(part * 64 + m) * 32 + off]     = fk.x;
        kk[(part * 64 + m) * 32 + off + 1] = fk.y;
        vv[(part * 64 + m) * 32 + off]     = fv.x;
        vv[(part * 64 + m) * 32 + off + 1] = fv.y;
    }
    __syncthreads();

    float q[32];
#pragma unroll
    for (int d8 = 0; d8 < 4; d8++) {
        uint4 raw = *(const uint4*)&qkv[(size_t)(base + row) * 384 + head * 32 + d8 * 8];
        const __half2* hp = (const __half2*)&raw;
#pragma unroll
        for (int p = 0; p < 4; p++) {
            float2 f = __half22float2(hp[p]);
            q[d8*8 + p*2]     = f.x * SCALE_Q;
            q[d8*8 + p*2 + 1] = f.y * SCALE_Q;
        }
    }

    const int rn = row >> 3, cn = row & 7;
    const int widx = wi & 63;
    const int wh = widx >> 3, wwc = widx & 7;
    int zr_n = 0, zc_n = 0;
    if (shift) { zr_n = zone_(wh * 8 + rn); zc_n = zone_(wwc * 8 + cn); }

    const float* kh = kk + head * 2048;
    const float* vh = vv + head * 2048;

    float o[32];
#pragma unroll
    for (int d = 0; d < 32; d++) o[d] = 0.0f;
    float sum = 0.0f;

#pragma unroll 4
    for (int m = 0; m < 64; m++) {
        float a = 0.0f;
        const float* kr = kh + m * 32;
#pragma unroll
        for (int d4 = 0; d4 < 8; d4++) {
            float4 kv4 = *(const float4*)&kr[d4 * 4];
            a += q[d4*4+0] * kv4.x + q[d4*4+1] * kv4.y +
                 q[d4*4+2] * kv4.z + q[d4*4+3] * kv4.w;
        }
        int rm = m >> 3, cm = m & 7;
        int ridx = (rn - rm + 7) * 15 + (cn - cm + 7);
        a += rps[ridx * 4 + head];
        if (shift) {
            if (zone_(wh * 8 + rm) != zr_n || zone_(wwc * 8 + cm) != zc_n)
                a += -100.0f;
        }
        float p = __expf(a);
        sum += p;
        const float* vr = vh + m * 32;
#pragma unroll
        for (int d4 = 0; d4 < 8; d4++) {
            float4 vv4 = *(const float4*)&vr[d4 * 4];
            o[d4*4+0] += p * vv4.x; o[d4*4+1] += p * vv4.y;
            o[d4*4+2] += p * vv4.z; o[d4*4+3] += p * vv4.w;
        }
    }
    float inv = 1.0f / sum;
#pragma unroll
    for (int d4 = 0; d4 < 8; d4++) {
        uint2 ov;
        ov.x = pack2h(o[d4*4+0] * inv, o[d4*4+1] * inv);
        ov.y = pack2h(o[d4*4+2] * inv, o[d4*4+3] * inv);
        *(uint2*)&out[(size_t)(base + row) * CC + head * 32 + d4 * 4] = ov;
    }
}

// ---------------------------------------------------------------------------
// Conv1d offset + mask head
// ---------------------------------------------------------------------------
__global__ void offmask_kernel(const float* __restrict__ xt,
                               const float* __restrict__ offw, const float* __restrict__ offb,
                               const float* __restrict__ mskw, const float* __restrict__ mskb,
                               float* __restrict__ off, float* __restrict__ msk) {
    __shared__ float swo[1152], swm[1152];
    int tid = threadIdx.x;
    for (int i = tid; i < 1152; i += 256) { swo[i] = offw[i]; swm[i] = mskw[i]; }
    __syncthreads();

    int warp = tid >> 5, lane = tid & 31;
    int pos = blockIdx.x * 8 + warp;
    int b = pos >> 12, l = pos & 4095;

    float ao[3] = {0.f, 0.f, 0.f}, am[3] = {0.f, 0.f, 0.f};
#pragma unroll
    for (int i = 0; i < 4; i++) {
        int c = lane + 32 * i;
        float xv[3];
#pragma unroll
        for (int j = 0; j < 3; j++) {
            int ls = l + j - 1;
            xv[j] = (ls >= 0 && ls < LL)
                  ? xt[((size_t)(b << 12) + ls) * CC + c] : 0.0f;
        }
#pragma unroll
        for (int ko = 0; ko < 3; ko++)
#pragma unroll
            for (int j = 0; j < 3; j++) {
                ao[ko] += xv[j] * swo[ko * 384 + c * 3 + j];
                am[ko] += xv[j] * swm[ko * 384 + c * 3 + j];
            }
    }
#pragma unroll
    for (int o = 16; o; o >>= 1)
#pragma unroll
        for (int ko = 0; ko < 3; ko++) {
            ao[ko] += __shfl_xor_sync(0xffffffffu, ao[ko], o);
            am[ko] += __shfl_xor_sync(0xffffffffu, am[ko], o);
        }
    if (lane == 0) {
#pragma unroll
        for (int ko = 0; ko < 3; ko++) {
            float ov = ao[ko] + offb[ko];
            float mv = am[ko] + mskb[ko];
            off[((size_t)(b * 3 + ko)) * LL + l] = ov;
            msk[((size_t)(b * 3 + ko)) * LL + l] = 1.0f / (1.0f + expf(-mv));
        }
    }
}

// ---------------------------------------------------------------------------
// Deformable sample -> fp16 at flat (B,C,L) layout == (B,L,C) view
// ---------------------------------------------------------------------------
__global__ void deform_kernel(const float* __restrict__ xt,
                              const float* __restrict__ off,
                              const float* __restrict__ msk,
                              __half* __restrict__ out) {
    __shared__ float s[128][33];
    __shared__ int   sfp[3][32], scp[3][32];
    __shared__ float sal[3][32], sm[3][32];

    int blk = blockIdx.x;
    int b = blk >> 7;
    int l0 = (blk & 127) << 5;
    int tid = threadIdx.x;

    if (tid < 96) {
        int k = tid / 32, li = tid % 32;
        int l = l0 + li;
        float o  = off[((size_t)(b * 3 + k)) * LL + l];
        float p  = fminf(fmaxf((float)l + o, 0.0f), 4095.0f);
        int fp   = (int)floorf(p);
        int cp   = min(fp + 1, 4095);
        sfp[k][li] = fp; scp[k][li] = cp;
        sal[k][li] = p - (float)fp;
        sm [k][li] = msk[((size_t)(b * 3 + k)) * LL + l];
    }
    __syncthreads();

    for (int e = tid; e < 4096; e += 256) {
        int li = e >> 7, c = e & 127;
        float acc = 0.0f;
#pragma unroll
        for (int k = 0; k < 3; k++) {
            float a  = sal[k][li];
            float xf = xt[((size_t)(b << 12) + sfp[k][li]) * CC + c];
            float xc = xt[((size_t)(b << 12) + scp[k][li]) * CC + c];
            acc += (xf * (1.0f - a) + xc * a) * sm[k][li];
        }
        s[c][li] = acc;
    }
    __syncthreads();
    for (int e = tid; e < 4096; e += 256) {
        int c = e >> 5, li = e & 31;
        size_t idx = (size_t)b * (CC * LL) + (size_t)c * LL + l0 + li;
        out[idx] = __float2half(s[c][li]);
    }
}

// ---------------------------------------------------------------------------
// Host launch
// ---------------------------------------------------------------------------
extern "C" void kernel_launch(void* const* d_in, const int* in_sizes, int n_in,
                              void* d_out, int out_size) {
    const float* xt    = (const float*)d_in[0];
    const float* hx    = (const float*)d_in[1];
    const float* cx    = (const float*)d_in[2];
    const float* red_w = (const float*)d_in[3];
    const float* red_b = (const float*)d_in[4];
    const float* n1g   = (const float*)d_in[5];
    const float* n1b   = (const float*)d_in[6];
    const float* qkvw  = (const float*)d_in[7];
    const float* qkvb  = (const float*)d_in[8];
    const float* rp    = (const float*)d_in[9];
    const float* pw    = (const float*)d_in[10];
    const float* pb    = (const float*)d_in[11];
    const float* n2g   = (const float*)d_in[12];
    const float* n2b   = (const float*)d_in[13];
    const float* f1w   = (const float*)d_in[14];
    const float* f1b   = (const float*)d_in[15];
    const float* f2w   = (const float*)d_in[16];
    const float* f2b   = (const float*)d_in[17];
    const float* off_w = (const float*)d_in[18];
    const float* off_b = (const float*)d_in[19];
    const float* msk_w = (const float*)d_in[20];
    const float* msk_b = (const float*)d_in[21];
    const float* lf_w  = (const float*)d_in[22];
    const float* lf_b  = (const float*)d_in[23];
    const float* gf_w  = (const float*)d_in[24];
    const float* gf_b  = (const float*)d_in[25];
    const float* ff_w  = (const float*)d_in[26];
    const float* ff_b  = (const float*)d_in[27];
    float* hy = (float*)d_out;

    float *pg, *pt1, *poff, *pmsk;
    cudaGetSymbolAddress((void**)&pg,   g_buf);
    cudaGetSymbolAddress((void**)&pt1,  g_t1);
    cudaGetSymbolAddress((void**)&poff, g_off);
    cudaGetSymbolAddress((void**)&pmsk, g_msk);

    __half *A16, *B16, *C16;
    cudaGetSymbolAddress((void**)&A16, g_A16);
    cudaGetSymbolAddress((void**)&B16, g_B16);
    cudaGetSymbolAddress((void**)&C16, g_C16);

    __half *redw, *qkvw16, *pww, *f1ww, *f2ww, *lfw, *gfw, *ffw;
    cudaGetSymbolAddress((void**)&redw,   w_red);
    cudaGetSymbolAddress((void**)&qkvw16, w_qkv);
    cudaGetSymbolAddress((void**)&pww,    w_pw);
    cudaGetSymbolAddress((void**)&f1ww,   w_f1);
    cudaGetSymbolAddress((void**)&f2ww,   w_f2);
    cudaGetSymbolAddress((void**)&lfw,    w_lf);
    cudaGetSymbolAddress((void**)&gfw,    w_gf);
    cudaGetSymbolAddress((void**)&ffw,    w_ff);

    cudaFuncSetAttribute(gemm_mma<EpiBias>,     cudaFuncAttributeMaxDynamicSharedMemorySize, GEMM_SMEM);
    cudaFuncSetAttribute(gemm_mma<EpiBiasH>,    cudaFuncAttributeMaxDynamicSharedMemorySize, GEMM_SMEM);
    cudaFuncSetAttribute(gemm_mma<EpiBiasLN>,   cudaFuncAttributeMaxDynamicSharedMemorySize, GEMM_SMEM);
    cudaFuncSetAttribute(gemm_mma<EpiGeluH>,    cudaFuncAttributeMaxDynamicSharedMemorySize, GEMM_SMEM);
    cudaFuncSetAttribute(gemm_mma<EpiProjLN>,   cudaFuncAttributeMaxDynamicSharedMemorySize, GEMM_SMEM);
    cudaFuncSetAttribute(gemm_mma<EpiResidLN>,  cudaFuncAttributeMaxDynamicSharedMemorySize, GEMM_SMEM);
    cudaFuncSetAttribute(gemm_mma<EpiResidH>,   cudaFuncAttributeMaxDynamicSharedMemorySize, GEMM_SMEM);
    cudaFuncSetAttribute(gemm_mma<EpiMulReluH>, cudaFuncAttributeMaxDynamicSharedMemorySize, GEMM_SMEM);
    cudaFuncSetAttribute(gemm_mma<EpiLSTM>,     cudaFuncAttributeMaxDynamicSharedMemorySize, GEMM_SMEM);
    cudaFuncSetAttribute(attn_kernel,           cudaFuncAttributeMaxDynamicSharedMemorySize, ATTN_SMEM);

    const dim3 blk256(256), blk512(512);

    // 0) all weight converts in one launch
    {
        WJobs js; int off = 0, n = 0;
        auto add = [&](const float* s, __half* d, int K, int N) {
            js.j[n++] = WJob{s, d, K, N, off};
            off += K * N;
        };
        add(red_w, redw, 256, 128);
        for (int i = 0; i < 2; i++) {
            add(qkvw + (size_t)i*128*384, qkvw16 + (size_t)i*384*128, 128, 384);
            add(pw   + (size_t)i*128*128, pww    + (size_t)i*128*128, 128, 128);
            add(f1w  + (size_t)i*128*512, f1ww   + (size_t)i*512*128, 128, 512);
            add(f2w  + (size_t)i*512*128, f2ww   + (size_t)i*128*512, 512, 128);
        }
        add(lf_w, lfw, 128, 128);
        add(gf_w, gfw, 128, 128);
        add(ff_w, ffw, 128, 128);
        js.total = off;
        wcvt_all<<<(off + 255) / 256, blk256>>>(js);
    }

    const dim3 gN1(1, 128), gN3(3, 128), gN4(4, 128);

    // 1) g = concat(xt, hx) @ red_w + red_b ; fused ln1(shift=0) -> C16
    cvtcat_kernel<<<MROWS * 128 / 256, blk256>>>(xt, hx, A16);
    gemm_mma<<<gN1, blk512, GEMM_SMEM>>>(A16, redw, 256, 128,
        EpiBiasLN{pg, red_b, C16, n1g, n1b, 0});

    // 2) two Swin blocks (LNs fused into GEMM epilogues)
    for (int i = 0; i < 2; i++) {
        int shift = (i == 0) ? 0 : 4;
        const float* qkvb_i = qkvb + (size_t)i * 384;
        const float* rp_i   = rp   + (size_t)i * 225 * 4;
        const float* pb_i   = pb   + (size_t)i * 128;
        const float* f1b_i  = f1b  + (size_t)i * 512;
        const float* f2b_i  = f2b  + (size_t)i * 128;

        gemm_mma<<<gN3, blk512, GEMM_SMEM>>>(C16, qkvw16 + (size_t)i*384*128,
                                             128, 384, EpiBiasH{B16, qkvb_i});
        attn_kernel<<<BB * 64, blk256, ATTN_SMEM>>>(B16, rp_i, A16, shift);
        gemm_mma<<<gN1, blk512, GEMM_SMEM>>>(A16, pww + (size_t)i*128*128, 128, 128,
            EpiProjLN{pg, pb_i, shift, C16, n2g + i * CC, n2b + i * CC});
        gemm_mma<<<gN4, blk512, GEMM_SMEM>>>(C16, f1ww + (size_t)i*512*128,
                                             128, 512, EpiGeluH{B16, f1b_i});
        if (i == 0)
            gemm_mma<<<gN1, blk512, GEMM_SMEM>>>(B16, f2ww, 512, 128,
                EpiResidLN{pg, pg, f2b_i, C16, n1g + CC, n1b + CC, 4});
        else
            gemm_mma<<<gN1, blk512, GEMM_SMEM>>>(B16, f2ww + (size_t)1*128*512,
                                                 512, 128, EpiResidH{C16, pg, f2b_i});
    }

    // 3) local branch -> A16
    offmask_kernel<<<MROWS / 8, blk256>>>(xt, off_w, off_b, msk_w, msk_b, poff, pmsk);
    deform_kernel<<<BB * (LL / 32), blk256>>>(xt, poff, pmsk, A16);

    // 4) fusion + LSTM gating
    gemm_mma<<<gN1, blk512, GEMM_SMEM>>>(A16, lfw, 128, 128, EpiBias{pt1, lf_b});
    gemm_mma<<<gN1, blk512, GEMM_SMEM>>>(C16, gfw, 128, 128, EpiMulReluH{A16, pt1, gf_b});
    gemm_mma<<<gN1, blk512, GEMM_SMEM>>>(A16, ffw, 128, 128, EpiLSTM{hy, cx, ff_b});
}

// round 13
// speedup vs baseline: 3.5164x; 1.0637x over previous
#include <cuda_runtime.h>
#include <cuda_fp16.h>
#include <math.h>
#include <stdint.h>

// ---------------------------------------------------------------------------
// Problem constants
// ---------------------------------------------------------------------------
#define BB   8
#define LL   4096
#define CC   128
#define MROWS (BB*LL)      // 32768
#define SCALE_Q 0.17677669529663687f

// ---------------------------------------------------------------------------
// Scratch (device globals — no allocation allowed)
// ---------------------------------------------------------------------------
__device__ float g_buf  [MROWS * CC];        // fp32 running state g
__device__ float g_t1   [MROWS * CC];        // t1 in phase 4
__device__ float g_off  [BB * 3 * LL];
__device__ float g_msk  [BB * 3 * LL];

// fp16 activation buffers
__device__ __align__(256) __half g_A16[MROWS * 256];   // concat input / attn out / deform / fu
__device__ __align__(256) __half g_B16[MROWS * 512];   // qkv (384) / FFN hidden (512)
__device__ __align__(256) __half g_C16[MROWS * 128];   // LN outputs / g fp16 copy

// converted + transposed weights, fp16 [N][K]
__device__ __align__(256) __half w_red[128*256];
__device__ __align__(256) __half w_qkv[2][384*128];
__device__ __align__(256) __half w_pw [2][128*128];
__device__ __align__(256) __half w_f1 [2][512*128];
__device__ __align__(256) __half w_f2 [2][128*512];
__device__ __align__(256) __half w_lf[128*128];
__device__ __align__(256) __half w_gf[128*128];
__device__ __align__(256) __half w_ff[128*128];

// ---------------------------------------------------------------------------
// helpers
// ---------------------------------------------------------------------------
__device__ __forceinline__ uint32_t smem_u32(const void* p) {
    uint32_t a;
    asm("{ .reg .u64 t; cvta.to.shared.u64 t, %1; cvt.u32.u64 %0, t; }"
        : "=r"(a) : "l"(p));
    return a;
}
__device__ __forceinline__ void cp16(uint32_t s, const void* g) {
    asm volatile("cp.async.cg.shared.global [%0], [%1], 16;" :: "r"(s), "l"(g));
}
__device__ __forceinline__ uint32_t pack2h(float a, float b) {
    __half2 p = __floats2half2_rn(a, b);
    return *(uint32_t*)&p;
}

#define LDSM4(r, a) \
    asm volatile("ldmatrix.sync.aligned.m8n8.x4.shared.b16 {%0,%1,%2,%3}, [%4];" \
        : "=r"((r)[0]), "=r"((r)[1]), "=r"((r)[2]), "=r"((r)[3]) : "r"(a))

#define MMA16816(d, a, b0, b1) \
    asm volatile("mma.sync.aligned.m16n8k16.row.col.f32.f16.f16.f32 " \
        "{%0,%1,%2,%3}, {%4,%5,%6,%7}, {%8,%9}, {%0,%1,%2,%3};" \
        : "+f"((d)[0]), "+f"((d)[1]), "+f"((d)[2]), "+f"((d)[3]) \
        : "r"((a)[0]), "r"((a)[1]), "r"((a)[2]), "r"((a)[3]), "r"(b0), "r"(b1))

// warp LN of one 128-col row: lanes hold 4 consecutive values each
__device__ __forceinline__ void warp_ln_stats(float4 v, float& mean, float& rstd) {
    float sum = v.x + v.y + v.z + v.w;
    float sq  = v.x * v.x + v.y * v.y + v.z * v.z + v.w * v.w;
#pragma unroll
    for (int o = 16; o; o >>= 1) {
        sum += __shfl_xor_sync(0xffffffffu, sum, o);
        sq  += __shfl_xor_sync(0xffffffffu, sq, o);
    }
    mean = sum * (1.0f / 128.0f);
    float var = sq * (1.0f / 128.0f) - mean * mean;
    rstd = rsqrtf(var + 1e-5f);
}

// ---------------------------------------------------------------------------
// Epilogues: ep(m, n0, N, float4), n0 % 4 == 0.
// Contract: one warp processes one full output row (32 lanes x float4),
// convergent — warp shuffles are legal inside.
// ---------------------------------------------------------------------------
struct EpiBias {
    float* out; const float* bias;
    __device__ __forceinline__ void operator()(int m, int n0, int N, float4 v) const {
        const float4 b = *(const float4*)&bias[n0];
        v.x += b.x; v.y += b.y; v.z += b.z; v.w += b.w;
        *(float4*)&out[(size_t)m * N + n0] = v;
    }
};
struct EpiBiasH {     // acc + bias -> fp16
    __half* out; const float* bias;
    __device__ __forceinline__ void operator()(int m, int n0, int N, float4 v) const {
        const float4 b = *(const float4*)&bias[n0];
        uint2 o;
        o.x = pack2h(v.x + b.x, v.y + b.y);
        o.y = pack2h(v.z + b.z, v.w + b.w);
        *(uint2*)&out[(size_t)m * N + n0] = o;
    }
};
// acc + bias -> g (fp32) ; LN + roll-partition permute -> a16 (fp16)
struct EpiBiasLN {
    float* g; const float* bias;
    __half* a16; const float* lng; const float* lnb; int shift;
    __device__ __forceinline__ void operator()(int m, int n0, int N, float4 v) const {
        const float4 b = *(const float4*)&bias[n0];
        v.x += b.x; v.y += b.y; v.z += b.z; v.w += b.w;
        *(float4*)&g[(size_t)m * CC + n0] = v;
        float mean, rstd; warp_ln_stats(v, mean, rstd);
        const float4 G  = *(const float4*)&lng[n0];
        const float4 Bt = *(const float4*)&lnb[n0];
        int bb = m >> 12, hw = m & 4095;
        int hp = ((hw >> 6) - shift) & 63;
        int wp = ((hw & 63) - shift) & 63;
        int dst = (bb << 12) + ((((hp >> 3) << 3) + (wp >> 3)) << 6)
                + ((hp & 7) << 3) + (wp & 7);
        uint2 o;
        o.x = pack2h((v.x - mean) * rstd * G.x + Bt.x, (v.y - mean) * rstd * G.y + Bt.y);
        o.y = pack2h((v.z - mean) * rstd * G.z + Bt.z, (v.w - mean) * rstd * G.w + Bt.w);
        *(uint2*)&a16[(size_t)dst * CC + n0] = o;
    }
};
// res + acc + bias -> g ; LN + roll-partition permute -> a16
struct EpiResidLN {
    float* g; const float* res; const float* bias;
    __half* a16; const float* lng; const float* lnb; int shift;
    __device__ __forceinline__ void operator()(int m, int n0, int N, float4 v) const {
        size_t i = (size_t)m * CC + n0;
        const float4 b = *(const float4*)&bias[n0];
        const float4 r = *(const float4*)&res[i];
        v.x += b.x + r.x; v.y += b.y + r.y; v.z += b.z + r.z; v.w += b.w + r.w;
        *(float4*)&g[i] = v;
        float mean, rstd; warp_ln_stats(v, mean, rstd);
        const float4 G  = *(const float4*)&lng[n0];
        const float4 Bt = *(const float4*)&lnb[n0];
        int bb = m >> 12, hw = m & 4095;
        int hp = ((hw >> 6) - shift) & 63;
        int wp = ((hw & 63) - shift) & 63;
        int dst = (bb << 12) + ((((hp >> 3) << 3) + (wp >> 3)) << 6)
                + ((hp & 7) << 3) + (wp & 7);
        uint2 o;
        o.x = pack2h((v.x - mean) * rstd * G.x + Bt.x, (v.y - mean) * rstd * G.y + Bt.y);
        o.y = pack2h((v.z - mean) * rstd * G.z + Bt.z, (v.w - mean) * rstd * G.w + Bt.w);
        *(uint2*)&a16[(size_t)dst * CC + n0] = o;
    }
};
struct EpiResidH {  // (res + acc + bias) -> fp16
    __half* out; const float* res; const float* bias;
    __device__ __forceinline__ void operator()(int m, int n0, int N, float4 v) const {
        size_t i = (size_t)m * N + n0;
        const float4 b = *(const float4*)&bias[n0];
        const float4 r = *(const float4*)&res[i];
        uint2 o;
        o.x = pack2h(v.x + b.x + r.x, v.y + b.y + r.y);
        o.y = pack2h(v.z + b.z + r.z, v.w + b.w + r.w);
        *(uint2*)&out[i] = o;
    }
};
// window-reverse(+shift) residual RMW into g ; LN -> a16 (token layout)
struct EpiProjLN {
    float* g; const float* bias; int shift;
    __half* a16; const float* lng; const float* lnb;
    __device__ __forceinline__ void operator()(int m, int n0, int N, float4 v) const {
        int bb   = m >> 12;
        int rb   = m & 4095;
        int widx = rb >> 6;
        int tok  = rb & 63;
        int hh = ((widx >> 3) << 3) + (tok >> 3);
        int ww = ((widx & 7) << 3) + (tok & 7);
        int h = (hh + shift) & 63;
        int w = (ww + shift) & 63;
        size_t dst = (size_t)(bb << 12) + (h << 6) + w;
        size_t di = dst * CC + n0;
        const float4 bi = *(const float4*)&bias[n0];
        float4 o = *(const float4*)&g[di];
        o.x += v.x + bi.x; o.y += v.y + bi.y; o.z += v.z + bi.z; o.w += v.w + bi.w;
        *(float4*)&g[di] = o;
        float mean, rstd; warp_ln_stats(o, mean, rstd);
        const float4 G  = *(const float4*)&lng[n0];
        const float4 Bt = *(const float4*)&lnb[n0];
        uint2 ov;
        ov.x = pack2h((o.x - mean) * rstd * G.x + Bt.x, (o.y - mean) * rstd * G.y + Bt.y);
        ov.y = pack2h((o.z - mean) * rstd * G.z + Bt.z, (o.w - mean) * rstd * G.w + Bt.w);
        *(uint2*)&a16[di] = ov;
    }
};
struct EpiGeluH {
    __half* out; const float* bias;
    __device__ __forceinline__ void operator()(int m, int n0, int N, float4 v) const {
        const float4 b = *(const float4*)&bias[n0];
        float g[4] = {v.x + b.x, v.y + b.y, v.z + b.z, v.w + b.w};
#pragma unroll
        for (int k = 0; k < 4; k++)
            g[k] = 0.5f * g[k] * (1.0f + erff(g[k] * 0.7071067811865476f));
        uint2 o; o.x = pack2h(g[0], g[1]); o.y = pack2h(g[2], g[3]);
        *(uint2*)&out[(size_t)m * N + n0] = o;
    }
};
struct EpiMulReluH {
    __half* out; const float* t1; const float* bias;
    __device__ __forceinline__ void operator()(int m, int n0, int N, float4 v) const {
        size_t i = (size_t)m * N + n0;
        const float4 b = *(const float4*)&bias[n0];
        const float4 t = *(const float4*)&t1[i];
        float g[4] = {fmaxf(0.0f, t.x * (v.x + b.x)), fmaxf(0.0f, t.y * (v.y + b.y)),
                      fmaxf(0.0f, t.z * (v.z + b.z)), fmaxf(0.0f, t.w * (v.w + b.w))};
        uint2 o; o.x = pack2h(g[0], g[1]); o.y = pack2h(g[2], g[3]);
        *(uint2*)&out[i] = o;
    }
};
struct EpiLSTM {
    float* hy; const float* cx; const float* bias;
    __device__ __forceinline__ void operator()(int m, int n0, int N, float4 v) const {
        size_t i = (size_t)m * N + n0;
        const float4 b = *(const float4*)&bias[n0];
        const float4 c = *(const float4*)&cx[i];
        float f[4] = {v.x + b.x, v.y + b.y, v.z + b.z, v.w + b.w};
        float cc[4] = {c.x, c.y, c.z, c.w};
        float o[4];
#pragma unroll
        for (int k = 0; k < 4; k++) {
            float gate = 1.0f / (1.0f + expf(-f[k]));
            float cell = tanhf(f[k]);
            float cy   = gate * (cc[k] + cell);
            o[k] = gate * tanhf(cy);
        }
        *(float4*)&hy[i] = *(float4*)o;
    }
};

// ---------------------------------------------------------------------------
// fp16 single-pass GEMM on mma.sync (m16n8k16): D = A @ W.
// CTA tile 128x128, 8 warps (4m x 2n), K-chunk 32, 3-stage cp.async pipeline,
// ONE __syncthreads per chunk. 2 CTAs/SM (regs<=128, smem 66KB).
// ---------------------------------------------------------------------------
#define TSTRIDE 80
#define A_BYTES 10240     // 128 rows * 80
#define STAGE_B 20480     // A tile + W tile
#define SOUT_STRIDE 132
#define GEMM_SMEM 67584   // max(3*STAGE_B=61440, sout 128*132*4=67584)

__device__ __forceinline__ void mma_mainloop(
    const __half* __restrict__ A, const __half* __restrict__ W,
    int K, int bm, int bn, uint32_t sb, int tid, float acc[2][8][4])
{
    const int wid = tid >> 5, lane = tid & 31;
    const int mw = wid & 3, nw = wid >> 2;
    const int nch = K >> 5;

    auto load_stage = [&](int i) {
        uint32_t st = sb + (uint32_t)(i % 3) * STAGE_B;
        int kt = i << 5;
        int r = tid >> 2, q = tid & 3;          // rows 0..63, quarter 0..3
        uint32_t so = (uint32_t)r * TSTRIDE + q * 16;
        cp16(st + so,                       A + (size_t)(bm + r) * K + kt + q * 8);
        cp16(st + 64u * TSTRIDE + so,       A + (size_t)(bm + r + 64) * K + kt + q * 8);
        cp16(st + A_BYTES + so,             W + (size_t)(bn + r) * K + kt + q * 8);
        cp16(st + A_BYTES + 64u * TSTRIDE + so,
                                            W + (size_t)(bn + r + 64) * K + kt + q * 8);
        asm volatile("cp.async.commit_group;");
    };

    load_stage(0);
    load_stage(1);
    for (int i = 0; i < nch; i++) {
        if (i + 1 < nch) asm volatile("cp.async.wait_group 1;");
        else             asm volatile("cp.async.wait_group 0;");
        __syncthreads();
        if (i + 2 < nch) load_stage(i + 2);

        uint32_t st = sb + (uint32_t)(i % 3) * STAGE_B;
#pragma unroll
        for (int j = 0; j < 2; j++) {
            uint32_t a[2][4], bh[4][4];
#pragma unroll
            for (int mt = 0; mt < 2; mt++) {
                uint32_t addr = st +
                    (uint32_t)((mw << 5) + (mt << 4) + (lane & 15)) * TSTRIDE +
                    (j << 5) + ((lane >> 4) << 4);
                LDSM4(a[mt], addr);
            }
#pragma unroll
            for (int nb = 0; nb < 4; nb++) {
                uint32_t addr = st + A_BYTES +
                    (uint32_t)((nw << 6) + (nb << 4) + (lane & 7) + ((lane >> 4) << 3)) * TSTRIDE +
                    (j << 5) + (((lane >> 3) & 1) << 4);
                LDSM4(bh[nb], addr);
            }
#pragma unroll
            for (int mt = 0; mt < 2; mt++)
#pragma unroll
                for (int nt = 0; nt < 8; nt++)
                    MMA16816(acc[mt][nt], a[mt],
                             bh[nt >> 1][(nt & 1) * 2], bh[nt >> 1][(nt & 1) * 2 + 1]);
        }
    }
    __syncthreads();   // last compute done before sout aliases the stages
}

template <class EP>
__global__ __launch_bounds__(256, 2)
void gemm_mma(const __half* __restrict__ A, const __half* __restrict__ W,
              int K, int Nfull, EP ep) {
    extern __shared__ char sm[];
    const int tid  = threadIdx.x;
    const int wid  = tid >> 5;
    const int lane = tid & 31;
    const int mw = wid & 3, nw = wid >> 2;
    const int bm = blockIdx.y * 128;
    const int bn = blockIdx.x * 128;
    const uint32_t sb = smem_u32(sm);

    float acc[2][8][4];
#pragma unroll
    for (int a = 0; a < 2; a++)
#pragma unroll
        for (int b = 0; b < 8; b++)
#pragma unroll
            for (int c = 0; c < 4; c++) acc[a][b][c] = 0.0f;

    mma_mainloop(A, W, K, bm, bn, sb, tid, acc);

    float* sout = (float*)sm;
    const int mb = mw << 5, nb = nw << 6;
#pragma unroll
    for (int mt = 0; mt < 2; mt++)
#pragma unroll
        for (int nt = 0; nt < 8; nt++)
#pragma unroll
            for (int rg = 0; rg < 4; rg++) {
                int ml = mb + (mt << 4) + (lane >> 2) + ((rg >> 1) << 3);
                int nl = nb + (nt << 3) + ((lane & 3) << 1) + (rg & 1);
                sout[ml * SOUT_STRIDE + nl] = acc[mt][nt][rg];
            }
    __syncthreads();
#pragma unroll 4
    for (int e = tid; e < 4096; e += 256) {
        int r = e >> 5, c4 = (e & 31) << 2;
        float4 v = *(float4*)&sout[r * SOUT_STRIDE + c4];
        ep(bm + r, bn + c4, Nfull, v);
    }
}

// ---------------------------------------------------------------------------
// Combined weight transpose + fp16 convert: 12 jobs in one launch
// ---------------------------------------------------------------------------
struct WJob { const float* src; __half* dst; int K, N, start; };
struct WJobs { WJob j[12]; int total; };

__global__ void wcvt_all(WJobs js) {
    int idx = blockIdx.x * 256 + threadIdx.x;
    if (idx >= js.total) return;
    int jj = 0;
#pragma unroll
    for (int t = 1; t < 12; t++) if (idx >= js.j[t].start) jj = t;
    const WJob J = js.j[jj];
    int local = idx - J.start;
    int k = local / J.N, n = local - k * J.N;
    J.dst[(size_t)n * J.K + k] = __float2half(J.src[local]);
}

// concat(xt,hx) -> A16 [M][256]
__global__ void cvtcat_kernel(const float* __restrict__ x, const float* __restrict__ hsrc,
                              __half* __restrict__ o) {
    int i = blockIdx.x * 256 + threadIdx.x;
    int m = i >> 7, k = i & 127;
    o[(size_t)m * 256 + k]       = __float2half(x[i]);
    o[(size_t)m * 256 + 128 + k] = __float2half(hsrc[i]);
}

// ---------------------------------------------------------------------------
// Window attention, qkv in fp16 -> fp16 output.
// Block = one window (256 thr = 4 heads x 64 rows)
// ---------------------------------------------------------------------------
__device__ __forceinline__ int zone_(int h) { return h < 56 ? 0 : (h < 60 ? 1 : 2); }

#define ATTN_SMEM 69136   // kk 32KB + vv 32KB + rps 3600B

__global__ __launch_bounds__(256)
void attn_kernel(const __half* __restrict__ qkv, const float* __restrict__ rp,
                 __half* __restrict__ out, int shift) {
    extern __shared__ float smf[];
    float* kk  = smf;
    float* vv  = smf + 8192;
    float* rps = smf + 16384;

    const int wi   = blockIdx.x;
    const int t    = threadIdx.x;
    const int head = t >> 6;
    const int row  = t & 63;
    const int base = wi * 64;

    for (int i = t; i < 900; i += 256) rps[i] = rp[i];
    for (int i = t; i < 4096; i += 256) {
        int m = i >> 6, c2 = (i & 63) << 1;
        __half2 hk = *(const __half2*)&qkv[(size_t)(base + m) * 384 + 128 + c2];
        __half2 hv = *(const __half2*)&qkv[(size_t)(base + m) * 384 + 256 + c2];
        float2 fk = __half22float2(hk);
        float2 fv = __half22float2(hv);
        int part = c2 >> 5, off = c2 & 31;
        kk[(part * 64 + m) * 32 + off]     = fk.x;
        kk[(part * 64 + m) * 32 + off + 1] = fk.y;
        vv[(part * 64 + m) * 32 + off]     = fv.x;
        vv[(part * 64 + m) * 32 + off + 1] = fv.y;
    }
    __syncthreads();

    float q[32];
#pragma unroll
    for (int d8 = 0; d8 < 4; d8++) {
        uint4 raw = *(const uint4*)&qkv[(size_t)(base + row) * 384 + head * 32 + d8 * 8];
        const __half2* hp = (const __half2*)&raw;
#pragma unroll
        for (int p = 0; p < 4; p++) {
            float2 f = __half22float2(hp[p]);
            q[d8*8 + p*2]     = f.x * SCALE_Q;
            q[d8*8 + p*2 + 1] = f.y * SCALE_Q;
        }
    }

    const int rn = row >> 3, cn = row & 7;
    const int widx = wi & 63;
    const int wh = widx >> 3, wwc = widx & 7;
    int zr_n = 0, zc_n = 0;
    if (shift) { zr_n = zone_(wh * 8 + rn); zc_n = zone_(wwc * 8 + cn); }

    const float* kh = kk + head * 2048;
    const float* vh = vv + head * 2048;

    float o[32];
#pragma unroll
    for (int d = 0; d < 32; d++) o[d] = 0.0f;
    float sum = 0.0f;

#pragma unroll 4
    for (int m = 0; m < 64; m++) {
        float a = 0.0f;
        const float* kr = kh + m * 32;
#pragma unroll
        for (int d4 = 0; d4 < 8; d4++) {
            float4 kv4 = *(const float4*)&kr[d4 * 4];
            a += q[d4*4+0] * kv4.x + q[d4*4+1] * kv4.y +
                 q[d4*4+2] * kv4.z + q[d4*4+3] * kv4.w;
        }
        int rm = m >> 3, cm = m & 7;
        int ridx = (rn - rm + 7) * 15 + (cn - cm + 7);
        a += rps[ridx * 4 + head];
        if (shift) {
            if (zone_(wh * 8 + rm) != zr_n || zone_(wwc * 8 + cm) != zc_n)
                a += -100.0f;
        }
        float p = __expf(a);
        sum += p;
        const float* vr = vh + m * 32;
#pragma unroll
        for (int d4 = 0; d4 < 8; d4++) {
            float4 vv4 = *(const float4*)&vr[d4 * 4];
            o[d4*4+0] += p * vv4.x; o[d4*4+1] += p * vv4.y;
            o[d4*4+2] += p * vv4.z; o[d4*4+3] += p * vv4.w;
        }
    }
    float inv = 1.0f / sum;
#pragma unroll
    for (int d4 = 0; d4 < 8; d4++) {
        uint2 ov;
        ov.x = pack2h(o[d4*4+0] * inv, o[d4*4+1] * inv);
        ov.y = pack2h(o[d4*4+2] * inv, o[d4*4+3] * inv);
        *(uint2*)&out[(size_t)(base + row) * CC + head * 32 + d4 * 4] = ov;
    }
}

// ---------------------------------------------------------------------------
// Conv1d offset + mask head
// ---------------------------------------------------------------------------
__global__ void offmask_kernel(const float* __restrict__ xt,
                               const float* __restrict__ offw, const float* __restrict__ offb,
                               const float* __restrict__ mskw, const float* __restrict__ mskb,
                               float* __restrict__ off, float* __restrict__ msk) {
    __shared__ float swo[1152], swm[1152];
    int tid = threadIdx.x;
    for (int i = tid; i < 1152; i += 256) { swo[i] = offw[i]; swm[i] = mskw[i]; }
    __syncthreads();

    int warp = tid >> 5, lane = tid & 31;
    int pos = blockIdx.x * 8 + warp;
    int b = pos >> 12, l = pos & 4095;

    float ao[3] = {0.f, 0.f, 0.f}, am[3] = {0.f, 0.f, 0.f};
#pragma unroll
    for (int i = 0; i < 4; i++) {
        int c = lane + 32 * i;
        float xv[3];
#pragma unroll
        for (int j = 0; j < 3; j++) {
            int ls = l + j - 1;
            xv[j] = (ls >= 0 && ls < LL)
                  ? xt[((size_t)(b << 12) + ls) * CC + c] : 0.0f;
        }
#pragma unroll
        for (int ko = 0; ko < 3; ko++)
#pragma unroll
            for (int j = 0; j < 3; j++) {
                ao[ko] += xv[j] * swo[ko * 384 + c * 3 + j];
                am[ko] += xv[j] * swm[ko * 384 + c * 3 + j];
            }
    }
#pragma unroll
    for (int o = 16; o; o >>= 1)
#pragma unroll
        for (int ko = 0; ko < 3; ko++) {
            ao[ko] += __shfl_xor_sync(0xffffffffu, ao[ko], o);
            am[ko] += __shfl_xor_sync(0xffffffffu, am[ko], o);
        }
    if (lane == 0) {
#pragma unroll
        for (int ko = 0; ko < 3; ko++) {
            float ov = ao[ko] + offb[ko];
            float mv = am[ko] + mskb[ko];
            off[((size_t)(b * 3 + ko)) * LL + l] = ov;
            msk[((size_t)(b * 3 + ko)) * LL + l] = 1.0f / (1.0f + expf(-mv));
        }
    }
}

// ---------------------------------------------------------------------------
// Deformable sample -> fp16 at flat (B,C,L) layout == (B,L,C) view
// ---------------------------------------------------------------------------
__global__ void deform_kernel(const float* __restrict__ xt,
                              const float* __restrict__ off,
                              const float* __restrict__ msk,
                              __half* __restrict__ out) {
    __shared__ float s[128][33];
    __shared__ int   sfp[3][32], scp[3][32];
    __shared__ float sal[3][32], sm[3][32];

    int blk = blockIdx.x;
    int b = blk >> 7;
    int l0 = (blk & 127) << 5;
    int tid = threadIdx.x;

    if (tid < 96) {
        int k = tid / 32, li = tid % 32;
        int l = l0 + li;
        float o  = off[((size_t)(b * 3 + k)) * LL + l];
        float p  = fminf(fmaxf((float)l + o, 0.0f), 4095.0f);
        int fp   = (int)floorf(p);
        int cp   = min(fp + 1, 4095);
        sfp[k][li] = fp; scp[k][li] = cp;
        sal[k][li] = p - (float)fp;
        sm [k][li] = msk[((size_t)(b * 3 + k)) * LL + l];
    }
    __syncthreads();

    for (int e = tid; e < 4096; e += 256) {
        int li = e >> 7, c = e & 127;
        float acc = 0.0f;
#pragma unroll
        for (int k = 0; k < 3; k++) {
            float a  = sal[k][li];
            float xf = xt[((size_t)(b << 12) + sfp[k][li]) * CC + c];
            float xc = xt[((size_t)(b << 12) + scp[k][li]) * CC + c];
            acc += (xf * (1.0f - a) + xc * a) * sm[k][li];
        }
        s[c][li] = acc;
    }
    __syncthreads();
    for (int e = tid; e < 4096; e += 256) {
        int c = e >> 5, li = e & 31;
        size_t idx = (size_t)b * (CC * LL) + (size_t)c * LL + l0 + li;
        out[idx] = __float2half(s[c][li]);
    }
}

// ---------------------------------------------------------------------------
// Host launch
// ---------------------------------------------------------------------------
extern "C" void kernel_launch(void* const* d_in, const int* in_sizes, int n_in,
                              void* d_out, int out_size) {
    const float* xt    = (const float*)d_in[0];
    const float* hx    = (const float*)d_in[1];
    const float* cx    = (const float*)d_in[2];
    const float* red_w = (const float*)d_in[3];
    const float* red_b = (const float*)d_in[4];
    const float* n1g   = (const float*)d_in[5];
    const float* n1b   = (const float*)d_in[6];
    const float* qkvw  = (const float*)d_in[7];
    const float* qkvb  = (const float*)d_in[8];
    const float* rp    = (const float*)d_in[9];
    const float* pw    = (const float*)d_in[10];
    const float* pb    = (const float*)d_in[11];
    const float* n2g   = (const float*)d_in[12];
    const float* n2b   = (const float*)d_in[13];
    const float* f1w   = (const float*)d_in[14];
    const float* f1b   = (const float*)d_in[15];
    const float* f2w   = (const float*)d_in[16];
    const float* f2b   = (const float*)d_in[17];
    const float* off_w = (const float*)d_in[18];
    const float* off_b = (const float*)d_in[19];
    const float* msk_w = (const float*)d_in[20];
    const float* msk_b = (const float*)d_in[21];
    const float* lf_w  = (const float*)d_in[22];
    const float* lf_b  = (const float*)d_in[23];
    const float* gf_w  = (const float*)d_in[24];
    const float* gf_b  = (const float*)d_in[25];
    const float* ff_w  = (const float*)d_in[26];
    const float* ff_b  = (const float*)d_in[27];
    float* hy = (float*)d_out;

    float *pg, *pt1, *poff, *pmsk;
    cudaGetSymbolAddress((void**)&pg,   g_buf);
    cudaGetSymbolAddress((void**)&pt1,  g_t1);
    cudaGetSymbolAddress((void**)&poff, g_off);
    cudaGetSymbolAddress((void**)&pmsk, g_msk);

    __half *A16, *B16, *C16;
    cudaGetSymbolAddress((void**)&A16, g_A16);
    cudaGetSymbolAddress((void**)&B16, g_B16);
    cudaGetSymbolAddress((void**)&C16, g_C16);

    __half *redw, *qkvw16, *pww, *f1ww, *f2ww, *lfw, *gfw, *ffw;
    cudaGetSymbolAddress((void**)&redw,   w_red);
    cudaGetSymbolAddress((void**)&qkvw16, w_qkv);
    cudaGetSymbolAddress((void**)&pww,    w_pw);
    cudaGetSymbolAddress((void**)&f1ww,   w_f1);
    cudaGetSymbolAddress((void**)&f2ww,   w_f2);
    cudaGetSymbolAddress((void**)&lfw,    w_lf);
    cudaGetSymbolAddress((void**)&gfw,    w_gf);
    cudaGetSymbolAddress((void**)&ffw,    w_ff);

    cudaFuncSetAttribute(gemm_mma<EpiBias>,     cudaFuncAttributeMaxDynamicSharedMemorySize, GEMM_SMEM);
    cudaFuncSetAttribute(gemm_mma<EpiBiasH>,    cudaFuncAttributeMaxDynamicSharedMemorySize, GEMM_SMEM);
    cudaFuncSetAttribute(gemm_mma<EpiBiasLN>,   cudaFuncAttributeMaxDynamicSharedMemorySize, GEMM_SMEM);
    cudaFuncSetAttribute(gemm_mma<EpiGeluH>,    cudaFuncAttributeMaxDynamicSharedMemorySize, GEMM_SMEM);
    cudaFuncSetAttribute(gemm_mma<EpiProjLN>,   cudaFuncAttributeMaxDynamicSharedMemorySize, GEMM_SMEM);
    cudaFuncSetAttribute(gemm_mma<EpiResidLN>,  cudaFuncAttributeMaxDynamicSharedMemorySize, GEMM_SMEM);
    cudaFuncSetAttribute(gemm_mma<EpiResidH>,   cudaFuncAttributeMaxDynamicSharedMemorySize, GEMM_SMEM);
    cudaFuncSetAttribute(gemm_mma<EpiMulReluH>, cudaFuncAttributeMaxDynamicSharedMemorySize, GEMM_SMEM);
    cudaFuncSetAttribute(gemm_mma<EpiLSTM>,     cudaFuncAttributeMaxDynamicSharedMemorySize, GEMM_SMEM);
    cudaFuncSetAttribute(attn_kernel,           cudaFuncAttributeMaxDynamicSharedMemorySize, ATTN_SMEM);

    const dim3 blk256(256);

    // 0) all weight converts in one launch
    {
        WJobs js; int off = 0, n = 0;
        auto add = [&](const float* s, __half* d, int K, int N) {
            js.j[n++] = WJob{s, d, K, N, off};
            off += K * N;
        };
        add(red_w, redw, 256, 128);
        for (int i = 0; i < 2; i++) {
            add(qkvw + (size_t)i*128*384, qkvw16 + (size_t)i*384*128, 128, 384);
            add(pw   + (size_t)i*128*128, pww    + (size_t)i*128*128, 128, 128);
            add(f1w  + (size_t)i*128*512, f1ww   + (size_t)i*512*128, 128, 512);
            add(f2w  + (size_t)i*512*128, f2ww   + (size_t)i*128*512, 512, 128);
        }
        add(lf_w, lfw, 128, 128);
        add(gf_w, gfw, 128, 128);
        add(ff_w, ffw, 128, 128);
        js.total = off;
        wcvt_all<<<(off + 255) / 256, blk256>>>(js);
    }

    const dim3 gN1(1, 256), gN3(3, 256), gN4(4, 256);

    // 1) g = concat(xt, hx) @ red_w + red_b ; fused ln1(shift=0) -> C16
    cvtcat_kernel<<<MROWS * 128 / 256, blk256>>>(xt, hx, A16);
    gemm_mma<<<gN1, blk256, GEMM_SMEM>>>(A16, redw, 256, 128,
        EpiBiasLN{pg, red_b, C16, n1g, n1b, 0});

    // 2) two Swin blocks (LNs fused into GEMM epilogues)
    for (int i = 0; i < 2; i++) {
        int shift = (i == 0) ? 0 : 4;
        const float* qkvb_i = qkvb + (size_t)i * 384;
        const float* rp_i   = rp   + (size_t)i * 225 * 4;
        const float* pb_i   = pb   + (size_t)i * 128;
        const float* f1b_i  = f1b  + (size_t)i * 512;
        const float* f2b_i  = f2b  + (size_t)i * 128;

        gemm_mma<<<gN3, blk256, GEMM_SMEM>>>(C16, qkvw16 + (size_t)i*384*128,
                                             128, 384, EpiBiasH{B16, qkvb_i});
        attn_kernel<<<BB * 64, blk256, ATTN_SMEM>>>(B16, rp_i, A16, shift);
        gemm_mma<<<gN1, blk256, GEMM_SMEM>>>(A16, pww + (size_t)i*128*128, 128, 128,
            EpiProjLN{pg, pb_i, shift, C16, n2g + i * CC, n2b + i * CC});
        gemm_mma<<<gN4, blk256, GEMM_SMEM>>>(C16, f1ww + (size_t)i*512*128,
                                             128, 512, EpiGeluH{B16, f1b_i});
        if (i == 0)
            gemm_mma<<<gN1, blk256, GEMM_SMEM>>>(B16, f2ww, 512, 128,
                EpiResidLN{pg, pg, f2b_i, C16, n1g + CC, n1b + CC, 4});
        else
            gemm_mma<<<gN1, blk256, GEMM_SMEM>>>(B16, f2ww + (size_t)1*128*512,
                                                 512, 128, EpiResidH{C16, pg, f2b_i});
    }

    // 3) local branch -> A16
    offmask_kernel<<<MROWS / 8, blk256>>>(xt, off_w, off_b, msk_w, msk_b, poff, pmsk);
    deform_kernel<<<BB * (LL / 32), blk256>>>(xt, poff, pmsk, A16);

    // 4) fusion + LSTM gating
    gemm_mma<<<gN1, blk256, GEMM_SMEM>>>(A16, lfw, 128, 128, EpiBias{pt1, lf_b});
    gemm_mma<<<gN1, blk256, GEMM_SMEM>>>(C16, gfw, 128, 128, EpiMulReluH{A16, pt1, gf_b});
    gemm_mma<<<gN1, blk256, GEMM_SMEM>>>(A16, ffw, 128, 128, EpiLSTM{hy, cx, ff_b});
}

// round 14
// speedup vs baseline: 3.6349x; 1.0337x over previous
#include <cuda_runtime.h>
#include <cuda_fp16.h>
#include <math.h>
#include <stdint.h>

// ---------------------------------------------------------------------------
// Problem constants
// ---------------------------------------------------------------------------
#define BB   8
#define LL   4096
#define CC   128
#define MROWS (BB*LL)      // 32768
#define SCALE_Q 0.17677669529663687f

// ---------------------------------------------------------------------------
// Scratch (device globals — no allocation allowed)
// ---------------------------------------------------------------------------
__device__ float g_buf  [MROWS * CC];        // fp32 running state g
__device__ float g_t1   [MROWS * CC];        // t1 in phase 4
__device__ float g_off  [BB * 3 * LL];
__device__ float g_msk  [BB * 3 * LL];

// fp16 activation buffers
__device__ __align__(256) __half g_A16[MROWS * 256];   // concat input / attn out / deform / fu
__device__ __align__(256) __half g_B16[MROWS * 512];   // qkv (384) / FFN hidden (512)
__device__ __align__(256) __half g_C16[MROWS * 128];   // LN outputs / g fp16 copy

// converted + transposed weights, fp16 [N][K]
__device__ __align__(256) __half w_red[128*256];
__device__ __align__(256) __half w_qkv[2][384*128];
__device__ __align__(256) __half w_pw [2][128*128];
__device__ __align__(256) __half w_f1 [2][512*128];
__device__ __align__(256) __half w_f2 [2][128*512];
__device__ __align__(256) __half w_lf[128*128];
__device__ __align__(256) __half w_gf[128*128];
__device__ __align__(256) __half w_ff[128*128];

// ---------------------------------------------------------------------------
// helpers
// ---------------------------------------------------------------------------
__device__ __forceinline__ uint32_t smem_u32(const void* p) {
    uint32_t a;
    asm("{ .reg .u64 t; cvta.to.shared.u64 t, %1; cvt.u32.u64 %0, t; }"
        : "=r"(a) : "l"(p));
    return a;
}
__device__ __forceinline__ void cp16(uint32_t s, const void* g) {
    asm volatile("cp.async.cg.shared.global [%0], [%1], 16;" :: "r"(s), "l"(g));
}
__device__ __forceinline__ uint32_t pack2h(float a, float b) {
    __half2 p = __floats2half2_rn(a, b);
    return *(uint32_t*)&p;
}

#define LDSM4(r, a) \
    asm volatile("ldmatrix.sync.aligned.m8n8.x4.shared.b16 {%0,%1,%2,%3}, [%4];" \
        : "=r"((r)[0]), "=r"((r)[1]), "=r"((r)[2]), "=r"((r)[3]) : "r"(a))

#define MMA16816(d, a, b0, b1) \
    asm volatile("mma.sync.aligned.m16n8k16.row.col.f32.f16.f16.f32 " \
        "{%0,%1,%2,%3}, {%4,%5,%6,%7}, {%8,%9}, {%0,%1,%2,%3};" \
        : "+f"((d)[0]), "+f"((d)[1]), "+f"((d)[2]), "+f"((d)[3]) \
        : "r"((a)[0]), "r"((a)[1]), "r"((a)[2]), "r"((a)[3]), "r"(b0), "r"(b1))

// warp LN of one 128-col row: lanes hold 4 consecutive values each
__device__ __forceinline__ void warp_ln_stats(float4 v, float& mean, float& rstd) {
    float sum = v.x + v.y + v.z + v.w;
    float sq  = v.x * v.x + v.y * v.y + v.z * v.z + v.w * v.w;
#pragma unroll
    for (int o = 16; o; o >>= 1) {
        sum += __shfl_xor_sync(0xffffffffu, sum, o);
        sq  += __shfl_xor_sync(0xffffffffu, sq, o);
    }
    mean = sum * (1.0f / 128.0f);
    float var = sq * (1.0f / 128.0f) - mean * mean;
    rstd = rsqrtf(var + 1e-5f);
}

// ---------------------------------------------------------------------------
// Epilogues: ep(m, n0, N, float4), n0 % 4 == 0.
// Contract: one warp processes one full output row (32 lanes x float4),
// convergent — warp shuffles are legal inside.
// ---------------------------------------------------------------------------
struct EpiBias {
    float* out; const float* bias;
    __device__ __forceinline__ void operator()(int m, int n0, int N, float4 v) const {
        const float4 b = *(const float4*)&bias[n0];
        v.x += b.x; v.y += b.y; v.z += b.z; v.w += b.w;
        *(float4*)&out[(size_t)m * N + n0] = v;
    }
};
struct EpiBiasH {     // acc + bias -> fp16
    __half* out; const float* bias;
    __device__ __forceinline__ void operator()(int m, int n0, int N, float4 v) const {
        const float4 b = *(const float4*)&bias[n0];
        uint2 o;
        o.x = pack2h(v.x + b.x, v.y + b.y);
        o.y = pack2h(v.z + b.z, v.w + b.w);
        *(uint2*)&out[(size_t)m * N + n0] = o;
    }
};
// acc + bias -> g (fp32) ; LN + roll-partition permute -> a16 (fp16)
struct EpiBiasLN {
    float* g; const float* bias;
    __half* a16; const float* lng; const float* lnb; int shift;
    __device__ __forceinline__ void operator()(int m, int n0, int N, float4 v) const {
        const float4 b = *(const float4*)&bias[n0];
        v.x += b.x; v.y += b.y; v.z += b.z; v.w += b.w;
        *(float4*)&g[(size_t)m * CC + n0] = v;
        float mean, rstd; warp_ln_stats(v, mean, rstd);
        const float4 G  = *(const float4*)&lng[n0];
        const float4 Bt = *(const float4*)&lnb[n0];
        int bb = m >> 12, hw = m & 4095;
        int hp = ((hw >> 6) - shift) & 63;
        int wp = ((hw & 63) - shift) & 63;
        int dst = (bb << 12) + ((((hp >> 3) << 3) + (wp >> 3)) << 6)
                + ((hp & 7) << 3) + (wp & 7);
        uint2 o;
        o.x = pack2h((v.x - mean) * rstd * G.x + Bt.x, (v.y - mean) * rstd * G.y + Bt.y);
        o.y = pack2h((v.z - mean) * rstd * G.z + Bt.z, (v.w - mean) * rstd * G.w + Bt.w);
        *(uint2*)&a16[(size_t)dst * CC + n0] = o;
    }
};
// res + acc + bias -> g ; LN + roll-partition permute -> a16
struct EpiResidLN {
    float* g; const float* res; const float* bias;
    __half* a16; const float* lng; const float* lnb; int shift;
    __device__ __forceinline__ void operator()(int m, int n0, int N, float4 v) const {
        size_t i = (size_t)m * CC + n0;
        const float4 b = *(const float4*)&bias[n0];
        const float4 r = *(const float4*)&res[i];
        v.x += b.x + r.x; v.y += b.y + r.y; v.z += b.z + r.z; v.w += b.w + r.w;
        *(float4*)&g[i] = v;
        float mean, rstd; warp_ln_stats(v, mean, rstd);
        const float4 G  = *(const float4*)&lng[n0];
        const float4 Bt = *(const float4*)&lnb[n0];
        int bb = m >> 12, hw = m & 4095;
        int hp = ((hw >> 6) - shift) & 63;
        int wp = ((hw & 63) - shift) & 63;
        int dst = (bb << 12) + ((((hp >> 3) << 3) + (wp >> 3)) << 6)
                + ((hp & 7) << 3) + (wp & 7);
        uint2 o;
        o.x = pack2h((v.x - mean) * rstd * G.x + Bt.x, (v.y - mean) * rstd * G.y + Bt.y);
        o.y = pack2h((v.z - mean) * rstd * G.z + Bt.z, (v.w - mean) * rstd * G.w + Bt.w);
        *(uint2*)&a16[(size_t)dst * CC + n0] = o;
    }
};
struct EpiResidH {  // (res + acc + bias) -> fp16
    __half* out; const float* res; const float* bias;
    __device__ __forceinline__ void operator()(int m, int n0, int N, float4 v) const {
        size_t i = (size_t)m * N + n0;
        const float4 b = *(const float4*)&bias[n0];
        const float4 r = *(const float4*)&res[i];
        uint2 o;
        o.x = pack2h(v.x + b.x + r.x, v.y + b.y + r.y);
        o.y = pack2h(v.z + b.z + r.z, v.w + b.w + r.w);
        *(uint2*)&out[i] = o;
    }
};
// window-reverse(+shift) residual RMW into g ; LN -> a16 (token layout)
struct EpiProjLN {
    float* g; const float* bias; int shift;
    __half* a16; const float* lng; const float* lnb;
    __device__ __forceinline__ void operator()(int m, int n0, int N, float4 v) const {
        int bb   = m >> 12;
        int rb   = m & 4095;
        int widx = rb >> 6;
        int tok  = rb & 63;
        int hh = ((widx >> 3) << 3) + (tok >> 3);
        int ww = ((widx & 7) << 3) + (tok & 7);
        int h = (hh + shift) & 63;
        int w = (ww + shift) & 63;
        size_t dst = (size_t)(bb << 12) + (h << 6) + w;
        size_t di = dst * CC + n0;
        const float4 bi = *(const float4*)&bias[n0];
        float4 o = *(const float4*)&g[di];
        o.x += v.x + bi.x; o.y += v.y + bi.y; o.z += v.z + bi.z; o.w += v.w + bi.w;
        *(float4*)&g[di] = o;
        float mean, rstd; warp_ln_stats(o, mean, rstd);
        const float4 G  = *(const float4*)&lng[n0];
        const float4 Bt = *(const float4*)&lnb[n0];
        uint2 ov;
        ov.x = pack2h((o.x - mean) * rstd * G.x + Bt.x, (o.y - mean) * rstd * G.y + Bt.y);
        ov.y = pack2h((o.z - mean) * rstd * G.z + Bt.z, (o.w - mean) * rstd * G.w + Bt.w);
        *(uint2*)&a16[di] = ov;
    }
};
struct EpiGeluH {
    __half* out; const float* bias;
    __device__ __forceinline__ void operator()(int m, int n0, int N, float4 v) const {
        const float4 b = *(const float4*)&bias[n0];
        float g[4] = {v.x + b.x, v.y + b.y, v.z + b.z, v.w + b.w};
#pragma unroll
        for (int k = 0; k < 4; k++)
            g[k] = 0.5f * g[k] * (1.0f + erff(g[k] * 0.7071067811865476f));
        uint2 o; o.x = pack2h(g[0], g[1]); o.y = pack2h(g[2], g[3]);
        *(uint2*)&out[(size_t)m * N + n0] = o;
    }
};
struct EpiMulReluH {
    __half* out; const float* t1; const float* bias;
    __device__ __forceinline__ void operator()(int m, int n0, int N, float4 v) const {
        size_t i = (size_t)m * N + n0;
        const float4 b = *(const float4*)&bias[n0];
        const float4 t = *(const float4*)&t1[i];
        float g[4] = {fmaxf(0.0f, t.x * (v.x + b.x)), fmaxf(0.0f, t.y * (v.y + b.y)),
                      fmaxf(0.0f, t.z * (v.z + b.z)), fmaxf(0.0f, t.w * (v.w + b.w))};
        uint2 o; o.x = pack2h(g[0], g[1]); o.y = pack2h(g[2], g[3]);
        *(uint2*)&out[i] = o;
    }
};
struct EpiLSTM {
    float* hy; const float* cx; const float* bias;
    __device__ __forceinline__ void operator()(int m, int n0, int N, float4 v) const {
        size_t i = (size_t)m * N + n0;
        const float4 b = *(const float4*)&bias[n0];
        const float4 c = *(const float4*)&cx[i];
        float f[4] = {v.x + b.x, v.y + b.y, v.z + b.z, v.w + b.w};
        float cc[4] = {c.x, c.y, c.z, c.w};
        float o[4];
#pragma unroll
        for (int k = 0; k < 4; k++) {
            float gate = 1.0f / (1.0f + expf(-f[k]));
            float cell = tanhf(f[k]);
            float cy   = gate * (cc[k] + cell);
            o[k] = gate * tanhf(cy);
        }
        *(float4*)&hy[i] = *(float4*)o;
    }
};

// ---------------------------------------------------------------------------
// fp16 single-pass GEMM on mma.sync (m16n8k16): D = A @ W.
// CTA tile 128x128, 8 warps (4m x 2n), K-chunk 64, 2-stage cp.async pipeline.
// For K=128 both chunks preload in the prologue -> no in-loop prefetch.
// TSTRIDE=144: ldmatrix row banks (36r mod 32) all distinct -> conflict-free.
// 2 CTAs/SM (regs<=127, smem 72KB).
// ---------------------------------------------------------------------------
#define TSTRIDE 144
#define TILE_B  18432     // 128 rows * 144
#define STAGE_B 36864     // A tile + W tile
#define SOUT_STRIDE 132
#define GEMM_SMEM 73728   // max(2*STAGE_B=73728, sout 128*132*4=67584)

__device__ __forceinline__ void mma_mainloop(
    const __half* __restrict__ A, const __half* __restrict__ W,
    int K, int bm, int bn, uint32_t sb, int tid, float acc[2][8][4])
{
    const int wid = tid >> 5, lane = tid & 31;
    const int mw = wid & 3, nw = wid >> 2;
    const int nch = K >> 6;

    auto load_stage = [&](int i) {
        uint32_t st = sb + (uint32_t)(i & 1) * STAGE_B;
        int kt = i << 6;
#pragma unroll
        for (int k = 0; k < 4; k++) {
            int e = tid + k * 256;           // 0..1023
            int r = e >> 3, q = e & 7;       // 128 rows x 8 sixteen-byte quarters
            uint32_t so = (uint32_t)r * TSTRIDE + q * 16;
            cp16(st + so,          A + (size_t)(bm + r) * K + kt + q * 8);
            cp16(st + TILE_B + so, W + (size_t)(bn + r) * K + kt + q * 8);
        }
        asm volatile("cp.async.commit_group;");
    };

    load_stage(0);
    if (nch > 1) load_stage(1);

    for (int i = 0; i < nch; i++) {
        if (i + 1 < nch) asm volatile("cp.async.wait_group 1;");
        else             asm volatile("cp.async.wait_group 0;");
        __syncthreads();

        uint32_t st = sb + (uint32_t)(i & 1) * STAGE_B;
#pragma unroll
        for (int j = 0; j < 4; j++) {
            uint32_t a[2][4], bh[4][4];
#pragma unroll
            for (int mt = 0; mt < 2; mt++) {
                uint32_t addr = st +
                    (uint32_t)((mw << 5) + (mt << 4) + (lane & 15)) * TSTRIDE +
                    (j << 5) + ((lane >> 4) << 4);
                LDSM4(a[mt], addr);
            }
#pragma unroll
            for (int nb = 0; nb < 4; nb++) {
                uint32_t addr = st + TILE_B +
                    (uint32_t)((nw << 6) + (nb << 4) + (lane & 7) + ((lane >> 4) << 3)) * TSTRIDE +
                    (j << 5) + (((lane >> 3) & 1) << 4);
                LDSM4(bh[nb], addr);
            }
#pragma unroll
            for (int mt = 0; mt < 2; mt++)
#pragma unroll
                for (int nt = 0; nt < 8; nt++)
                    MMA16816(acc[mt][nt], a[mt],
                             bh[nt >> 1][(nt & 1) * 2], bh[nt >> 1][(nt & 1) * 2 + 1]);
        }

        if (i + 2 < nch) {        // prefetch must reuse the slot just computed
            __syncthreads();
            load_stage(i + 2);
        }
    }
    __syncthreads();   // last compute done before sout aliases the stages
}

template <class EP>
__global__ __launch_bounds__(256, 2)
void gemm_mma(const __half* __restrict__ A, const __half* __restrict__ W,
              int K, int Nfull, EP ep) {
    extern __shared__ char sm[];
    const int tid  = threadIdx.x;
    const int wid  = tid >> 5;
    const int lane = tid & 31;
    const int mw = wid & 3, nw = wid >> 2;
    const int bm = blockIdx.y * 128;
    const int bn = blockIdx.x * 128;
    const uint32_t sb = smem_u32(sm);

    float acc[2][8][4];
#pragma unroll
    for (int a = 0; a < 2; a++)
#pragma unroll
        for (int b = 0; b < 8; b++)
#pragma unroll
            for (int c = 0; c < 4; c++) acc[a][b][c] = 0.0f;

    mma_mainloop(A, W, K, bm, bn, sb, tid, acc);

    float* sout = (float*)sm;
    const int mb = mw << 5, nb = nw << 6;
#pragma unroll
    for (int mt = 0; mt < 2; mt++)
#pragma unroll
        for (int nt = 0; nt < 8; nt++)
#pragma unroll
            for (int rg = 0; rg < 4; rg++) {
                int ml = mb + (mt << 4) + (lane >> 2) + ((rg >> 1) << 3);
                int nl = nb + (nt << 3) + ((lane & 3) << 1) + (rg & 1);
                sout[ml * SOUT_STRIDE + nl] = acc[mt][nt][rg];
            }
    __syncthreads();
#pragma unroll 4
    for (int e = tid; e < 4096; e += 256) {
        int r = e >> 5, c4 = (e & 31) << 2;
        float4 v = *(float4*)&sout[r * SOUT_STRIDE + c4];
        ep(bm + r, bn + c4, Nfull, v);
    }
}

// ---------------------------------------------------------------------------
// Combined weight transpose + fp16 convert: 12 jobs in one launch
// ---------------------------------------------------------------------------
struct WJob { const float* src; __half* dst; int K, N, start; };
struct WJobs { WJob j[12]; int total; };

__global__ void wcvt_all(WJobs js) {
    int idx = blockIdx.x * 256 + threadIdx.x;
    if (idx >= js.total) return;
    int jj = 0;
#pragma unroll
    for (int t = 1; t < 12; t++) if (idx >= js.j[t].start) jj = t;
    const WJob J = js.j[jj];
    int local = idx - J.start;
    int k = local / J.N, n = local - k * J.N;
    J.dst[(size_t)n * J.K + k] = __float2half(J.src[local]);
}

// concat(xt,hx) -> A16 [M][256]
__global__ void cvtcat_kernel(const float* __restrict__ x, const float* __restrict__ hsrc,
                              __half* __restrict__ o) {
    int i = blockIdx.x * 256 + threadIdx.x;
    int m = i >> 7, k = i & 127;
    o[(size_t)m * 256 + k]       = __float2half(x[i]);
    o[(size_t)m * 256 + 128 + k] = __float2half(hsrc[i]);
}

// ---------------------------------------------------------------------------
// Window attention, qkv in fp16 -> fp16 output.
// Block = one window (256 thr = 4 heads x 64 rows)
// ---------------------------------------------------------------------------
__device__ __forceinline__ int zone_(int h) { return h < 56 ? 0 : (h < 60 ? 1 : 2); }

#define ATTN_SMEM 69136   // kk 32KB + vv 32KB + rps 3600B

__global__ __launch_bounds__(256)
void attn_kernel(const __half* __restrict__ qkv, const float* __restrict__ rp,
                 __half* __restrict__ out, int shift) {
    extern __shared__ float smf[];
    float* kk  = smf;
    float* vv  = smf + 8192;
    float* rps = smf + 16384;

    const int wi   = blockIdx.x;
    const int t    = threadIdx.x;
    const int head = t >> 6;
    const int row  = t & 63;
    const int base = wi * 64;

    for (int i = t; i < 900; i += 256) rps[i] = rp[i];
    for (int i = t; i < 4096; i += 256) {
        int m = i >> 6, c2 = (i & 63) << 1;
        __half2 hk = *(const __half2*)&qkv[(size_t)(base + m) * 384 + 128 + c2];
        __half2 hv = *(const __half2*)&qkv[(size_t)(base + m) * 384 + 256 + c2];
        float2 fk = __half22float2(hk);
        float2 fv = __half22float2(hv);
        int part = c2 >> 5, off = c2 & 31;
        kk[(part * 64 + m) * 32 + off]     = fk.x;
        kk[(part * 64 + m) * 32 + off + 1] = fk.y;
        vv[(part * 64 + m) * 32 + off]     = fv.x;
        vv[(part * 64 + m) * 32 + off + 1] = fv.y;
    }
    __syncthreads();

    float q[32];
#pragma unroll
    for (int d8 = 0; d8 < 4; d8++) {
        uint4 raw = *(const uint4*)&qkv[(size_t)(base + row) * 384 + head * 32 + d8 * 8];
        const __half2* hp = (const __half2*)&raw;
#pragma unroll
        for (int p = 0; p < 4; p++) {
            float2 f = __half22float2(hp[p]);
            q[d8*8 + p*2]     = f.x * SCALE_Q;
            q[d8*8 + p*2 + 1] = f.y * SCALE_Q;
        }
    }

    const int rn = row >> 3, cn = row & 7;
    const int widx = wi & 63;
    const int wh = widx >> 3, wwc = widx & 7;
    int zr_n = 0, zc_n = 0;
    if (shift) { zr_n = zone_(wh * 8 + rn); zc_n = zone_(wwc * 8 + cn); }

    const float* kh = kk + head * 2048;
    const float* vh = vv + head * 2048;

    float o[32];
#pragma unroll
    for (int d = 0; d < 32; d++) o[d] = 0.0f;
    float sum = 0.0f;

#pragma unroll 4
    for (int m = 0; m < 64; m++) {
        float a = 0.0f;
        const float* kr = kh + m * 32;
#pragma unroll
        for (int d4 = 0; d4 < 8; d4++) {
            float4 kv4 = *(const float4*)&kr[d4 * 4];
            a += q[d4*4+0] * kv4.x + q[d4*4+1] * kv4.y +
                 q[d4*4+2] * kv4.z + q[d4*4+3] * kv4.w;
        }
        int rm = m >> 3, cm = m & 7;
        int ridx = (rn - rm + 7) * 15 + (cn - cm + 7);
        a += rps[ridx * 4 + head];
        if (shift) {
            if (zone_(wh * 8 + rm) != zr_n || zone_(wwc * 8 + cm) != zc_n)
                a += -100.0f;
        }
        float p = __expf(a);
        sum += p;
        const float* vr = vh + m * 32;
#pragma unroll
        for (int d4 = 0; d4 < 8; d4++) {
            float4 vv4 = *(const float4*)&vr[d4 * 4];
            o[d4*4+0] += p * vv4.x; o[d4*4+1] += p * vv4.y;
            o[d4*4+2] += p * vv4.z; o[d4*4+3] += p * vv4.w;
        }
    }
    float inv = 1.0f / sum;
#pragma unroll
    for (int d4 = 0; d4 < 8; d4++) {
        uint2 ov;
        ov.x = pack2h(o[d4*4+0] * inv, o[d4*4+1] * inv);
        ov.y = pack2h(o[d4*4+2] * inv, o[d4*4+3] * inv);
        *(uint2*)&out[(size_t)(base + row) * CC + head * 32 + d4 * 4] = ov;
    }
}

// ---------------------------------------------------------------------------
// Conv1d offset + mask head
// ---------------------------------------------------------------------------
__global__ void offmask_kernel(const float* __restrict__ xt,
                               const float* __restrict__ offw, const float* __restrict__ offb,
                               const float* __restrict__ mskw, const float* __restrict__ mskb,
                               float* __restrict__ off, float* __restrict__ msk) {
    __shared__ float swo[1152], swm[1152];
    int tid = threadIdx.x;
    for (int i = tid; i < 1152; i += 256) { swo[i] = offw[i]; swm[i] = mskw[i]; }
    __syncthreads();

    int warp = tid >> 5, lane = tid & 31;
    int pos = blockIdx.x * 8 + warp;
    int b = pos >> 12, l = pos & 4095;

    float ao[3] = {0.f, 0.f, 0.f}, am[3] = {0.f, 0.f, 0.f};
#pragma unroll
    for (int i = 0; i < 4; i++) {
        int c = lane + 32 * i;
        float xv[3];
#pragma unroll
        for (int j = 0; j < 3; j++) {
            int ls = l + j - 1;
            xv[j] = (ls >= 0 && ls < LL)
                  ? xt[((size_t)(b << 12) + ls) * CC + c] : 0.0f;
        }
#pragma unroll
        for (int ko = 0; ko < 3; ko++)
#pragma unroll
            for (int j = 0; j < 3; j++) {
                ao[ko] += xv[j] * swo[ko * 384 + c * 3 + j];
                am[ko] += xv[j] * swm[ko * 384 + c * 3 + j];
            }
    }
#pragma unroll
    for (int o = 16; o; o >>= 1)
#pragma unroll
        for (int ko = 0; ko < 3; ko++) {
            ao[ko] += __shfl_xor_sync(0xffffffffu, ao[ko], o);
            am[ko] += __shfl_xor_sync(0xffffffffu, am[ko], o);
        }
    if (lane == 0) {
#pragma unroll
        for (int ko = 0; ko < 3; ko++) {
            float ov = ao[ko] + offb[ko];
            float mv = am[ko] + mskb[ko];
            off[((size_t)(b * 3 + ko)) * LL + l] = ov;
            msk[((size_t)(b * 3 + ko)) * LL + l] = 1.0f / (1.0f + expf(-mv));
        }
    }
}

// ---------------------------------------------------------------------------
// Deformable sample -> fp16 at flat (B,C,L) layout == (B,L,C) view
// ---------------------------------------------------------------------------
__global__ void deform_kernel(const float* __restrict__ xt,
                              const float* __restrict__ off,
                              const float* __restrict__ msk,
                              __half* __restrict__ out) {
    __shared__ float s[128][33];
    __shared__ int   sfp[3][32], scp[3][32];
    __shared__ float sal[3][32], sm[3][32];

    int blk = blockIdx.x;
    int b = blk >> 7;
    int l0 = (blk & 127) << 5;
    int tid = threadIdx.x;

    if (tid < 96) {
        int k = tid / 32, li = tid % 32;
        int l = l0 + li;
        float o  = off[((size_t)(b * 3 + k)) * LL + l];
        float p  = fminf(fmaxf((float)l + o, 0.0f), 4095.0f);
        int fp   = (int)floorf(p);
        int cp   = min(fp + 1, 4095);
        sfp[k][li] = fp; scp[k][li] = cp;
        sal[k][li] = p - (float)fp;
        sm [k][li] = msk[((size_t)(b * 3 + k)) * LL + l];
    }
    __syncthreads();

    for (int e = tid; e < 4096; e += 256) {
        int li = e >> 7, c = e & 127;
        float acc = 0.0f;
#pragma unroll
        for (int k = 0; k < 3; k++) {
            float a  = sal[k][li];
            float xf = xt[((size_t)(b << 12) + sfp[k][li]) * CC + c];
            float xc = xt[((size_t)(b << 12) + scp[k][li]) * CC + c];
            acc += (xf * (1.0f - a) + xc * a) * sm[k][li];
        }
        s[c][li] = acc;
    }
    __syncthreads();
    for (int e = tid; e < 4096; e += 256) {
        int c = e >> 5, li = e & 31;
        size_t idx = (size_t)b * (CC * LL) + (size_t)c * LL + l0 + li;
        out[idx] = __float2half(s[c][li]);
    }
}

// ---------------------------------------------------------------------------
// Host launch
// ---------------------------------------------------------------------------
extern "C" void kernel_launch(void* const* d_in, const int* in_sizes, int n_in,
                              void* d_out, int out_size) {
    const float* xt    = (const float*)d_in[0];
    const float* hx    = (const float*)d_in[1];
    const float* cx    = (const float*)d_in[2];
    const float* red_w = (const float*)d_in[3];
    const float* red_b = (const float*)d_in[4];
    const float* n1g   = (const float*)d_in[5];
    const float* n1b   = (const float*)d_in[6];
    const float* qkvw  = (const float*)d_in[7];
    const float* qkvb  = (const float*)d_in[8];
    const float* rp    = (const float*)d_in[9];
    const float* pw    = (const float*)d_in[10];
    const float* pb    = (const float*)d_in[11];
    const float* n2g   = (const float*)d_in[12];
    const float* n2b   = (const float*)d_in[13];
    const float* f1w   = (const float*)d_in[14];
    const float* f1b   = (const float*)d_in[15];
    const float* f2w   = (const float*)d_in[16];
    const float* f2b   = (const float*)d_in[17];
    const float* off_w = (const float*)d_in[18];
    const float* off_b = (const float*)d_in[19];
    const float* msk_w = (const float*)d_in[20];
    const float* msk_b = (const float*)d_in[21];
    const float* lf_w  = (const float*)d_in[22];
    const float* lf_b  = (const float*)d_in[23];
    const float* gf_w  = (const float*)d_in[24];
    const float* gf_b  = (const float*)d_in[25];
    const float* ff_w  = (const float*)d_in[26];
    const float* ff_b  = (const float*)d_in[27];
    float* hy = (float*)d_out;

    float *pg, *pt1, *poff, *pmsk;
    cudaGetSymbolAddress((void**)&pg,   g_buf);
    cudaGetSymbolAddress((void**)&pt1,  g_t1);
    cudaGetSymbolAddress((void**)&poff, g_off);
    cudaGetSymbolAddress((void**)&pmsk, g_msk);

    __half *A16, *B16, *C16;
    cudaGetSymbolAddress((void**)&A16, g_A16);
    cudaGetSymbolAddress((void**)&B16, g_B16);
    cudaGetSymbolAddress((void**)&C16, g_C16);

    __half *redw, *qkvw16, *pww, *f1ww, *f2ww, *lfw, *gfw, *ffw;
    cudaGetSymbolAddress((void**)&redw,   w_red);
    cudaGetSymbolAddress((void**)&qkvw16, w_qkv);
    cudaGetSymbolAddress((void**)&pww,    w_pw);
    cudaGetSymbolAddress((void**)&f1ww,   w_f1);
    cudaGetSymbolAddress((void**)&f2ww,   w_f2);
    cudaGetSymbolAddress((void**)&lfw,    w_lf);
    cudaGetSymbolAddress((void**)&gfw,    w_gf);
    cudaGetSymbolAddress((void**)&ffw,    w_ff);

    cudaFuncSetAttribute(gemm_mma<EpiBias>,     cudaFuncAttributeMaxDynamicSharedMemorySize, GEMM_SMEM);
    cudaFuncSetAttribute(gemm_mma<EpiBiasH>,    cudaFuncAttributeMaxDynamicSharedMemorySize, GEMM_SMEM);
    cudaFuncSetAttribute(gemm_mma<EpiBiasLN>,   cudaFuncAttributeMaxDynamicSharedMemorySize, GEMM_SMEM);
    cudaFuncSetAttribute(gemm_mma<EpiGeluH>,    cudaFuncAttributeMaxDynamicSharedMemorySize, GEMM_SMEM);
    cudaFuncSetAttribute(gemm_mma<EpiProjLN>,   cudaFuncAttributeMaxDynamicSharedMemorySize, GEMM_SMEM);
    cudaFuncSetAttribute(gemm_mma<EpiResidLN>,  cudaFuncAttributeMaxDynamicSharedMemorySize, GEMM_SMEM);
    cudaFuncSetAttribute(gemm_mma<EpiResidH>,   cudaFuncAttributeMaxDynamicSharedMemorySize, GEMM_SMEM);
    cudaFuncSetAttribute(gemm_mma<EpiMulReluH>, cudaFuncAttributeMaxDynamicSharedMemorySize, GEMM_SMEM);
    cudaFuncSetAttribute(gemm_mma<EpiLSTM>,     cudaFuncAttributeMaxDynamicSharedMemorySize, GEMM_SMEM);
    cudaFuncSetAttribute(attn_kernel,           cudaFuncAttributeMaxDynamicSharedMemorySize, ATTN_SMEM);

    const dim3 blk256(256);

    // 0) all weight converts in one launch
    {
        WJobs js; int off = 0, n = 0;
        auto add = [&](const float* s, __half* d, int K, int N) {
            js.j[n++] = WJob{s, d, K, N, off};
            off += K * N;
        };
        add(red_w, redw, 256, 128);
        for (int i = 0; i < 2; i++) {
            add(qkvw + (size_t)i*128*384, qkvw16 + (size_t)i*384*128, 128, 384);
            add(pw   + (size_t)i*128*128, pww    + (size_t)i*128*128, 128, 128);
            add(f1w  + (size_t)i*128*512, f1ww   + (size_t)i*512*128, 128, 512);
            add(f2w  + (size_t)i*512*128, f2ww   + (size_t)i*128*512, 512, 128);
        }
        add(lf_w, lfw, 128, 128);
        add(gf_w, gfw, 128, 128);
        add(ff_w, ffw, 128, 128);
        js.total = off;
        wcvt_all<<<(off + 255) / 256, blk256>>>(js);
    }

    const dim3 gN1(1, 256), gN3(3, 256), gN4(4, 256);

    // 1) g = concat(xt, hx) @ red_w + red_b ; fused ln1(shift=0) -> C16
    cvtcat_kernel<<<MROWS * 128 / 256, blk256>>>(xt, hx, A16);
    gemm_mma<<<gN1, blk256, GEMM_SMEM>>>(A16, redw, 256, 128,
        EpiBiasLN{pg, red_b, C16, n1g, n1b, 0});

    // 2) two Swin blocks (LNs fused into GEMM epilogues)
    for (int i = 0; i < 2; i++) {
        int shift = (i == 0) ? 0 : 4;
        const float* qkvb_i = qkvb + (size_t)i * 384;
        const float* rp_i   = rp   + (size_t)i * 225 * 4;
        const float* pb_i   = pb   + (size_t)i * 128;
        const float* f1b_i  = f1b  + (size_t)i * 512;
        const float* f2b_i  = f2b  + (size_t)i * 128;

        gemm_mma<<<gN3, blk256, GEMM_SMEM>>>(C16, qkvw16 + (size_t)i*384*128,
                                             128, 384, EpiBiasH{B16, qkvb_i});
        attn_kernel<<<BB * 64, blk256, ATTN_SMEM>>>(B16, rp_i, A16, shift);
        gemm_mma<<<gN1, blk256, GEMM_SMEM>>>(A16, pww + (size_t)i*128*128, 128, 128,
            EpiProjLN{pg, pb_i, shift, C16, n2g + i * CC, n2b + i * CC});
        gemm_mma<<<gN4, blk256, GEMM_SMEM>>>(C16, f1ww + (size_t)i*512*128,
                                             128, 512, EpiGeluH{B16, f1b_i});
        if (i == 0)
            gemm_mma<<<gN1, blk256, GEMM_SMEM>>>(B16, f2ww, 512, 128,
                EpiResidLN{pg, pg, f2b_i, C16, n1g + CC, n1b + CC, 4});
        else
            gemm_mma<<<gN1, blk256, GEMM_SMEM>>>(B16, f2ww + (size_t)1*128*512,
                                                 512, 128, EpiResidH{C16, pg, f2b_i});
    }

    // 3) local branch -> A16
    offmask_kernel<<<MROWS / 8, blk256>>>(xt, off_w, off_b, msk_w, msk_b, poff, pmsk);
    deform_kernel<<<BB * (LL / 32), blk256>>>(xt, poff, pmsk, A16);

    // 4) fusion + LSTM gating
    gemm_mma<<<gN1, blk256, GEMM_SMEM>>>(A16, lfw, 128, 128, EpiBias{pt1, lf_b});
    gemm_mma<<<gN1, blk256, GEMM_SMEM>>>(C16, gfw, 128, 128, EpiMulReluH{A16, pt1, gf_b});
    gemm_mma<<<gN1, blk256, GEMM_SMEM>>>(A16, ffw, 128, 128, EpiLSTM{hy, cx, ff_b});
}